// round 2
// baseline (speedup 1.0000x reference)
#include <cuda_runtime.h>
#include <math.h>
#include <stdint.h>

// Problem dims (fixed by the dataset)
#define B_  2
#define S_  2048
#define D_  1024
#define L_  1024
#define H_  16
#define DH_ 64
#define BH_ (B_ * H_)          // 32
#define M4_ (B_ * S_)          // 4096 rows for the dense GEMMs

// ---------------------------------------------------------------------------
// Scratch (static __device__ globals — allocation-free per harness rules)
// ---------------------------------------------------------------------------
__device__ float g_q[(size_t)M4_ * L_];
__device__ float g_k[(size_t)M4_ * L_];
__device__ float g_v[(size_t)M4_ * L_];
__device__ float g_scores[(size_t)BH_ * S_ * S_];   // 512 MB: [head][k][q]
__device__ float g_ao[(size_t)M4_ * L_];            // merged attention output
__device__ float g_z1[(size_t)M4_ * D_];
__device__ float g_z2[(size_t)M4_ * D_];

// ---------------------------------------------------------------------------
// Fast exp: FFMA-only (avoids the MUFU EX2 throughput wall: 134M exps needed)
// exp(x) = 2^(x*log2e); |rel err| ~2e-6 on f in [-0.5, 0.5]
// ---------------------------------------------------------------------------
__device__ __forceinline__ float fast_exp(float x) {
    float t = x * 1.4426950408889634f;
    t = fmaxf(fminf(t, 126.0f), -126.0f);
    float fi = rintf(t);
    float f  = t - fi;                        // [-0.5, 0.5]
    float p  = 0.00133335581464284f;          // (ln2)^5/120
    p = fmaf(p, f, 0.00961812910762848f);     // (ln2)^4/24
    p = fmaf(p, f, 0.05550410866482158f);     // (ln2)^3/6
    p = fmaf(p, f, 0.24022650695910072f);     // (ln2)^2/2
    p = fmaf(p, f, 0.69314718055994531f);     // ln2
    p = fmaf(p, f, 1.0f);
    int ei = (int)fi;
    float sc = __int_as_float((ei + 127) << 23);
    return p * sc;
}

// ---------------------------------------------------------------------------
// Generic NN SGEMM: C[M,N] = A[M,K] @ B[K,N]   (row-major, lda=K, ldb=ldc=N)
// 128x128 tile, K-chunk 16, 256 threads, 8x8 per thread, float4 everywhere.
// All dims divisible by tiles in this problem -> no bounds checks.
// ---------------------------------------------------------------------------
__global__ void __launch_bounds__(256) sgemm_nn(const float* __restrict__ A,
                                                const float* __restrict__ Bm,
                                                float* __restrict__ C,
                                                int M, int N, int K) {
    __shared__ float As[16][128];
    __shared__ float Bs[16][128];
    const int bm = blockIdx.y * 128;
    const int bn = blockIdx.x * 128;
    const int tid = threadIdx.x;
    const int tr = (tid >> 4) * 8;   // 0..120
    const int tc = (tid & 15) * 8;   // 0..120
    float acc[8][8] = {};
    for (int k0 = 0; k0 < K; k0 += 16) {
        #pragma unroll
        for (int i = 0; i < 2; i++) {
            int idx = tid + i * 256;            // 512 float4 for A tile
            int m = idx >> 2;
            int kq = (idx & 3) * 4;
            float4 a = *(const float4*)(A + (size_t)(bm + m) * K + k0 + kq);
            As[kq + 0][m] = a.x; As[kq + 1][m] = a.y;
            As[kq + 2][m] = a.z; As[kq + 3][m] = a.w;
        }
        #pragma unroll
        for (int i = 0; i < 2; i++) {
            int idx = tid + i * 256;            // 512 float4 for B tile
            int kk = idx >> 5;
            int nq = (idx & 31) * 4;
            *(float4*)&Bs[kk][nq] = *(const float4*)(Bm + (size_t)(k0 + kk) * N + bn + nq);
        }
        __syncthreads();
        #pragma unroll
        for (int kk = 0; kk < 16; kk++) {
            float ar[8], br[8];
            *(float4*)(ar)     = *(const float4*)&As[kk][tr];
            *(float4*)(ar + 4) = *(const float4*)&As[kk][tr + 4];
            *(float4*)(br)     = *(const float4*)&Bs[kk][tc];
            *(float4*)(br + 4) = *(const float4*)&Bs[kk][tc + 4];
            #pragma unroll
            for (int i = 0; i < 8; i++)
                #pragma unroll
                for (int j = 0; j < 8; j++)
                    acc[i][j] = fmaf(ar[i], br[j], acc[i][j]);
        }
        __syncthreads();
    }
    #pragma unroll
    for (int i = 0; i < 8; i++)
        #pragma unroll
        for (int j = 0; j < 8; j += 4)
            *(float4*)(C + (size_t)(bm + tr + i) * N + bn + tc + j) = *(float4*)&acc[i][j];
}

// ---------------------------------------------------------------------------
// Scores: per head hh, C[kk][qq] = (1/32) * sum_d K[kk,d] * Q[qq,d]
// NT GEMM, M=N=2048, K=64, head slices have row stride 1024.
// ---------------------------------------------------------------------------
__global__ void __launch_bounds__(256) scores_nt(const float* __restrict__ Qm,
                                                 const float* __restrict__ Km,
                                                 float* __restrict__ Sc) {
    const int hh = blockIdx.z;
    const int b = hh >> 4, h = hh & 15;
    const float* A = Km + (size_t)b * S_ * L_ + h * DH_;   // key rows
    const float* Bq = Qm + (size_t)b * S_ * L_ + h * DH_;  // query rows
    float* C = Sc + (size_t)hh * S_ * S_;
    const int bm = blockIdx.y * 128;   // key tile
    const int bn = blockIdx.x * 128;   // query tile
    __shared__ float As[16][128];
    __shared__ float Bs[16][128];
    const int tid = threadIdx.x;
    const int tr = (tid >> 4) * 8;
    const int tc = (tid & 15) * 8;
    float acc[8][8] = {};
    for (int k0 = 0; k0 < DH_; k0 += 16) {
        #pragma unroll
        for (int i = 0; i < 2; i++) {
            int idx = tid + i * 256;
            int m = idx >> 2;
            int kq = (idx & 3) * 4;
            float4 a = *(const float4*)(A + (size_t)(bm + m) * L_ + k0 + kq);
            As[kq + 0][m] = a.x; As[kq + 1][m] = a.y;
            As[kq + 2][m] = a.z; As[kq + 3][m] = a.w;
            float4 bb = *(const float4*)(Bq + (size_t)(bn + m) * L_ + k0 + kq);
            Bs[kq + 0][m] = bb.x; Bs[kq + 1][m] = bb.y;
            Bs[kq + 2][m] = bb.z; Bs[kq + 3][m] = bb.w;
        }
        __syncthreads();
        #pragma unroll
        for (int kk = 0; kk < 16; kk++) {
            float ar[8], br[8];
            *(float4*)(ar)     = *(const float4*)&As[kk][tr];
            *(float4*)(ar + 4) = *(const float4*)&As[kk][tr + 4];
            *(float4*)(br)     = *(const float4*)&Bs[kk][tc];
            *(float4*)(br + 4) = *(const float4*)&Bs[kk][tc + 4];
            #pragma unroll
            for (int i = 0; i < 8; i++)
                #pragma unroll
                for (int j = 0; j < 8; j++)
                    acc[i][j] = fmaf(ar[i], br[j], acc[i][j]);
        }
        __syncthreads();
    }
    #pragma unroll
    for (int i = 0; i < 8; i++)
        #pragma unroll
        for (int j = 0; j < 8; j += 4) {
            float4 o;
            o.x = acc[i][j + 0] * 0.03125f;
            o.y = acc[i][j + 1] * 0.03125f;
            o.z = acc[i][j + 2] * 0.03125f;
            o.w = acc[i][j + 3] * 0.03125f;
            *(float4*)(C + (size_t)(bm + tr + i) * S_ + bn + tc + j) = o;
        }
}

// ---------------------------------------------------------------------------
// Softmax over the query axis: one block per (head,key) row of 2048.
// Row held entirely in registers; writes back p = exp(s-m)/Z in place.
// ---------------------------------------------------------------------------
__global__ void __launch_bounds__(256) softmax_rows(float* __restrict__ Sc) {
    __shared__ float shm[8];
    __shared__ float shs[8];
    const size_t row = blockIdx.x;
    float* p = Sc + row * (size_t)S_;
    const int tid = threadIdx.x;
    const int lane = tid & 31, wid = tid >> 5;

    float4 a = *(const float4*)(p + tid * 4);
    float4 bb = *(const float4*)(p + 1024 + tid * 4);

    float m = fmaxf(fmaxf(fmaxf(a.x, a.y), fmaxf(a.z, a.w)),
                    fmaxf(fmaxf(bb.x, bb.y), fmaxf(bb.z, bb.w)));
    #pragma unroll
    for (int o = 16; o; o >>= 1) m = fmaxf(m, __shfl_xor_sync(0xffffffffu, m, o));
    if (lane == 0) shm[wid] = m;
    __syncthreads();
    m = shm[0];
    #pragma unroll
    for (int i = 1; i < 8; i++) m = fmaxf(m, shm[i]);

    a.x = fast_exp(a.x - m);  a.y = fast_exp(a.y - m);
    a.z = fast_exp(a.z - m);  a.w = fast_exp(a.w - m);
    bb.x = fast_exp(bb.x - m); bb.y = fast_exp(bb.y - m);
    bb.z = fast_exp(bb.z - m); bb.w = fast_exp(bb.w - m);

    float s = (a.x + a.y) + (a.z + a.w) + (bb.x + bb.y) + (bb.z + bb.w);
    #pragma unroll
    for (int o = 16; o; o >>= 1) s += __shfl_xor_sync(0xffffffffu, s, o);
    if (lane == 0) shs[wid] = s;
    __syncthreads();
    s = shs[0];
    #pragma unroll
    for (int i = 1; i < 8; i++) s += shs[i];
    const float inv = 1.0f / s;

    a.x *= inv; a.y *= inv; a.z *= inv; a.w *= inv;
    bb.x *= inv; bb.y *= inv; bb.z *= inv; bb.w *= inv;
    *(float4*)(p + tid * 4) = a;
    *(float4*)(p + 1024 + tid * 4) = bb;
}

// ---------------------------------------------------------------------------
// Weighted V: out[q,d] = sum_k P[k,q] * V[k,d]   (per head; TN GEMM)
// Block = 128 q x 64 d, 256 threads, 8x4 per thread. Writes merged-head layout.
// ---------------------------------------------------------------------------
__global__ void __launch_bounds__(256) av_gemm(const float* __restrict__ P,
                                               const float* __restrict__ Vm,
                                               float* __restrict__ O) {
    const int hh = blockIdx.z;
    const int b = hh >> 4, h = hh & 15;
    const float* p = P + (size_t)hh * S_ * S_;                 // [k][q]
    const float* v = Vm + (size_t)b * S_ * L_ + h * DH_;       // [k][d] stride L_
    float* o = O + (size_t)b * S_ * L_ + h * DH_;              // [q][d] stride L_
    const int bq = blockIdx.x * 128;
    __shared__ float Ps[16][128];
    __shared__ float Vs[16][64];
    const int tid = threadIdx.x;
    const int tq = (tid >> 4) * 8;
    const int td = (tid & 15) * 4;
    float acc[8][4] = {};
    for (int k0 = 0; k0 < S_; k0 += 16) {
        #pragma unroll
        for (int i = 0; i < 2; i++) {
            int idx = tid + i * 256;
            int kk = idx >> 5;
            int qq = (idx & 31) * 4;
            *(float4*)&Ps[kk][qq] = *(const float4*)(p + (size_t)(k0 + kk) * S_ + bq + qq);
        }
        {
            int kk = tid >> 4;
            int dd = (tid & 15) * 4;
            *(float4*)&Vs[kk][dd] = *(const float4*)(v + (size_t)(k0 + kk) * L_ + dd);
        }
        __syncthreads();
        #pragma unroll
        for (int kk = 0; kk < 16; kk++) {
            float pr[8], vr[4];
            *(float4*)(pr)     = *(const float4*)&Ps[kk][tq];
            *(float4*)(pr + 4) = *(const float4*)&Ps[kk][tq + 4];
            *(float4*)(vr)     = *(const float4*)&Vs[kk][td];
            #pragma unroll
            for (int i = 0; i < 8; i++)
                #pragma unroll
                for (int j = 0; j < 4; j++)
                    acc[i][j] = fmaf(pr[i], vr[j], acc[i][j]);
        }
        __syncthreads();
    }
    #pragma unroll
    for (int i = 0; i < 8; i++)
        *(float4*)(o + (size_t)(bq + tq + i) * L_ + td) = *(float4*)&acc[i][0];
}

// ---------------------------------------------------------------------------
// Row L2 normalize (in place) — matches torch F.normalize (eps=1e-12)
// ---------------------------------------------------------------------------
__global__ void __launch_bounds__(256) l2norm_rows(float* __restrict__ Z) {
    __shared__ float shs[8];
    const size_t row = blockIdx.x;
    float* p = Z + row * (size_t)D_;
    const int tid = threadIdx.x;
    const int lane = tid & 31, wid = tid >> 5;
    float4 v = *(const float4*)(p + tid * 4);
    float ss = v.x * v.x + v.y * v.y + v.z * v.z + v.w * v.w;
    #pragma unroll
    for (int o = 16; o; o >>= 1) ss += __shfl_xor_sync(0xffffffffu, ss, o);
    if (lane == 0) shs[wid] = ss;
    __syncthreads();
    ss = shs[0];
    #pragma unroll
    for (int i = 1; i < 8; i++) ss += shs[i];
    const float sc = 1.0f / fmaxf(sqrtf(ss), 1e-12f);
    v.x *= sc; v.y *= sc; v.z *= sc; v.w *= sc;
    *(float4*)(p + tid * 4) = v;
}

// ---------------------------------------------------------------------------
// Row L2 normalize + exact GELU (erf), writes to output
// ---------------------------------------------------------------------------
__global__ void __launch_bounds__(256) l2norm_gelu(const float* __restrict__ Z,
                                                   float* __restrict__ O) {
    __shared__ float shs[8];
    const size_t row = blockIdx.x;
    const float* p = Z + row * (size_t)D_;
    float* q = O + row * (size_t)D_;
    const int tid = threadIdx.x;
    const int lane = tid & 31, wid = tid >> 5;
    float4 v = *(const float4*)(p + tid * 4);
    float ss = v.x * v.x + v.y * v.y + v.z * v.z + v.w * v.w;
    #pragma unroll
    for (int o = 16; o; o >>= 1) ss += __shfl_xor_sync(0xffffffffu, ss, o);
    if (lane == 0) shs[wid] = ss;
    __syncthreads();
    ss = shs[0];
    #pragma unroll
    for (int i = 1; i < 8; i++) ss += shs[i];
    const float sc = 1.0f / fmaxf(sqrtf(ss), 1e-12f);
    float y0 = v.x * sc, y1 = v.y * sc, y2 = v.z * sc, y3 = v.w * sc;
    const float inv_sqrt2 = 0.70710678118654752f;
    float4 g;
    g.x = 0.5f * y0 * (1.0f + erff(y0 * inv_sqrt2));
    g.y = 0.5f * y1 * (1.0f + erff(y1 * inv_sqrt2));
    g.z = 0.5f * y2 * (1.0f + erff(y2 * inv_sqrt2));
    g.w = 0.5f * y3 * (1.0f + erff(y3 * inv_sqrt2));
    *(float4*)(q + tid * 4) = g;
}

// ---------------------------------------------------------------------------
// Launch
// ---------------------------------------------------------------------------
extern "C" void kernel_launch(void* const* d_in, const int* in_sizes, int n_in,
                              void* d_out, int out_size) {
    (void)in_sizes; (void)n_in; (void)out_size;
    const float* x   = (const float*)d_in[0];
    const float* Wq  = (const float*)d_in[1];
    const float* Wk  = (const float*)d_in[2];
    const float* Wv  = (const float*)d_in[3];
    const float* Wo  = (const float*)d_in[4];
    const float* Wff = (const float*)d_in[5];

    float *q, *k, *v, *sc, *ao, *z1, *z2;
    cudaGetSymbolAddress((void**)&q,  g_q);
    cudaGetSymbolAddress((void**)&k,  g_k);
    cudaGetSymbolAddress((void**)&v,  g_v);
    cudaGetSymbolAddress((void**)&sc, g_scores);
    cudaGetSymbolAddress((void**)&ao, g_ao);
    cudaGetSymbolAddress((void**)&z1, g_z1);
    cudaGetSymbolAddress((void**)&z2, g_z2);

    const dim3 blk(256);
    const dim3 gDense(L_ / 128, M4_ / 128);          // (8, 32)

    sgemm_nn<<<gDense, blk>>>(x, Wq, q, M4_, L_, D_);
    sgemm_nn<<<gDense, blk>>>(x, Wk, k, M4_, L_, D_);
    sgemm_nn<<<gDense, blk>>>(x, Wv, v, M4_, L_, D_);

    scores_nt<<<dim3(S_ / 128, S_ / 128, BH_), blk>>>(q, k, sc);   // (16,16,32)
    softmax_rows<<<BH_ * S_, blk>>>(sc);                           // 65536 rows
    av_gemm<<<dim3(S_ / 128, 1, BH_), blk>>>(sc, v, ao);           // (16,1,32)

    sgemm_nn<<<gDense, blk>>>(ao, Wo, z1, M4_, L_, D_);
    l2norm_rows<<<M4_, blk>>>(z1);
    sgemm_nn<<<gDense, blk>>>(z1, Wff, z2, M4_, D_, D_);
    l2norm_gelu<<<M4_, blk>>>(z2, (float*)d_out);
}

// round 8
// speedup vs baseline: 1.4561x; 1.4561x over previous
#include <cuda_runtime.h>
#include <cuda_bf16.h>
#include <math.h>
#include <stdint.h>

// Problem dims (fixed by the dataset)
#define B_  2
#define S_  2048
#define D_  1024
#define L_  1024
#define H_  16
#define DH_ 64
#define BH_ (B_ * H_)          // 32
#define M4_ (B_ * S_)          // 4096 rows for the dense GEMMs

// ---------------------------------------------------------------------------
// Scratch (static __device__ globals — allocation-free per harness rules)
// ---------------------------------------------------------------------------
__device__ float g_q[(size_t)M4_ * L_];
__device__ float g_k[(size_t)M4_ * L_];
__device__ float g_v[(size_t)M4_ * L_];
__device__ float g_scores[(size_t)BH_ * S_ * S_];   // 512 MB: [head][k][q]
__device__ float g_ao[(size_t)M4_ * L_];
__device__ float g_z1[(size_t)M4_ * D_];
__device__ float g_z2[(size_t)M4_ * D_];

// bf16 hi/lo split operands (ushort storage)
__device__ unsigned short g_xhi[(size_t)M4_ * D_];
__device__ unsigned short g_xlo[(size_t)M4_ * D_];
__device__ unsigned short g_qhi[(size_t)M4_ * L_];
__device__ unsigned short g_qlo[(size_t)M4_ * L_];
__device__ unsigned short g_khi[(size_t)M4_ * L_];
__device__ unsigned short g_klo[(size_t)M4_ * L_];
__device__ unsigned short g_aohi[(size_t)M4_ * L_];
__device__ unsigned short g_aolo[(size_t)M4_ * L_];
__device__ unsigned short g_z1hi[(size_t)M4_ * D_];
__device__ unsigned short g_z1lo[(size_t)M4_ * D_];
// transposed weights [N,K] hi/lo, 5 weights
__device__ unsigned short g_wt_hi[5][(size_t)D_ * L_];
__device__ unsigned short g_wt_lo[5][(size_t)D_ * L_];

// ---------------------------------------------------------------------------
// helpers
// ---------------------------------------------------------------------------
__device__ __forceinline__ uint32_t sptr(const void* p) {
    return (uint32_t)__cvta_generic_to_shared(p);
}

__device__ __forceinline__ void ldsm4(uint32_t a, uint32_t& r0, uint32_t& r1,
                                      uint32_t& r2, uint32_t& r3) {
    asm volatile("ldmatrix.sync.aligned.m8n8.x4.shared.b16 {%0,%1,%2,%3}, [%4];"
                 : "=r"(r0), "=r"(r1), "=r"(r2), "=r"(r3) : "r"(a));
}

__device__ __forceinline__ void mma16816(float* d, const uint32_t* a, const uint32_t* b) {
    asm volatile(
        "mma.sync.aligned.m16n8k16.row.col.f32.bf16.bf16.f32 "
        "{%0,%1,%2,%3}, {%4,%5,%6,%7}, {%8,%9}, {%0,%1,%2,%3};"
        : "+f"(d[0]), "+f"(d[1]), "+f"(d[2]), "+f"(d[3])
        : "r"(a[0]), "r"(a[1]), "r"(a[2]), "r"(a[3]), "r"(b[0]), "r"(b[1]));
}

__device__ __forceinline__ void split1(float a, __nv_bfloat16& h, __nv_bfloat16& l) {
    h = __float2bfloat16(a);
    l = __float2bfloat16(a - __bfloat162float(h));
}

// ---------------------------------------------------------------------------
// Warp-MMA NT GEMM, bf16x3: C[M,N] = scale * A[M,K] @ Bt[N,K]^T, fp32 out.
// A as Ahi/Alo row-major (lda), Bt as Bhi/Blo row-major (ldb).
// CTA 128x128, K-chunk 32, 256 threads = 8 warps (4M x 2N), warp tile 32x64.
// headMode: blockIdx.z selects attention head slices (stride-L_ views).
// ---------------------------------------------------------------------------
#define PAD_ 40

__global__ void __launch_bounds__(256) hgemm_nt(
    const __nv_bfloat16* __restrict__ Ahi, const __nv_bfloat16* __restrict__ Alo,
    const __nv_bfloat16* __restrict__ Bhi, const __nv_bfloat16* __restrict__ Blo,
    float* __restrict__ C, int M, int N, int K,
    int lda, int ldb, int ldc, float scale, int headMode) {
    __shared__ __align__(16) __nv_bfloat16 sAh[128][PAD_];
    __shared__ __align__(16) __nv_bfloat16 sAl[128][PAD_];
    __shared__ __align__(16) __nv_bfloat16 sBh[128][PAD_];
    __shared__ __align__(16) __nv_bfloat16 sBl[128][PAD_];

    if (headMode) {
        const int z = blockIdx.z;
        const int b = z >> 4, h = z & 15;
        const size_t off = (size_t)b * S_ * L_ + (size_t)h * DH_;
        Ahi += off; Alo += off; Bhi += off; Blo += off;
        C += (size_t)z * S_ * S_;
    }

    const int tid = threadIdx.x;
    const int wid = tid >> 5, lane = tid & 31;
    const int wm = wid >> 1, wn = wid & 1;
    const int bm = blockIdx.y * 128, bn = blockIdx.x * 128;

    float acc[2][8][4];
    #pragma unroll
    for (int i = 0; i < 2; i++)
        #pragma unroll
        for (int j = 0; j < 8; j++)
            #pragma unroll
            for (int r = 0; r < 4; r++) acc[i][j][r] = 0.0f;

    // ldmatrix source addresses (fixed per thread; col varies by kstep)
    const int a_row = (lane & 15);
    const int a_col8 = (lane >> 4) * 8;            // 0 or 8
    const int b_rowoff = (lane & 7) + ((lane >> 4) << 3);
    const int b_col8 = ((lane >> 3) & 1) * 8;

    for (int k0 = 0; k0 < K; k0 += 32) {
        // cooperative loads: 4 tiles of [128][32] bf16
        #pragma unroll
        for (int i = 0; i < 2; i++) {
            const int idx = tid + i * 256;
            const int row = idx >> 2;
            const int seg = (idx & 3) * 8;
            *(uint4*)&sAh[row][seg] = *(const uint4*)(Ahi + (size_t)(bm + row) * lda + k0 + seg);
            *(uint4*)&sAl[row][seg] = *(const uint4*)(Alo + (size_t)(bm + row) * lda + k0 + seg);
            *(uint4*)&sBh[row][seg] = *(const uint4*)(Bhi + (size_t)(bn + row) * ldb + k0 + seg);
            *(uint4*)&sBl[row][seg] = *(const uint4*)(Blo + (size_t)(bn + row) * ldb + k0 + seg);
        }
        __syncthreads();

        #pragma unroll
        for (int ks = 0; ks < 2; ks++) {
            const int kc = ks * 16;
            uint32_t ah[2][4], al[2][4];
            #pragma unroll
            for (int mf = 0; mf < 2; mf++) {
                ldsm4(sptr(&sAh[wm * 32 + mf * 16 + a_row][kc + a_col8]),
                      ah[mf][0], ah[mf][1], ah[mf][2], ah[mf][3]);
                ldsm4(sptr(&sAl[wm * 32 + mf * 16 + a_row][kc + a_col8]),
                      al[mf][0], al[mf][1], al[mf][2], al[mf][3]);
            }
            #pragma unroll
            for (int nf2 = 0; nf2 < 4; nf2++) {
                const int brow = wn * 64 + nf2 * 16 + b_rowoff;
                uint32_t bh[4], bl[4];
                ldsm4(sptr(&sBh[brow][kc + b_col8]), bh[0], bh[1], bh[2], bh[3]);
                ldsm4(sptr(&sBl[brow][kc + b_col8]), bl[0], bl[1], bl[2], bl[3]);
                #pragma unroll
                for (int mf = 0; mf < 2; mf++) {
                    #pragma unroll
                    for (int f = 0; f < 2; f++) {
                        float* d = acc[mf][nf2 * 2 + f];
                        mma16816(d, ah[mf], bh + 2 * f);   // hi*hi
                        mma16816(d, ah[mf], bl + 2 * f);   // hi*lo
                        mma16816(d, al[mf], bh + 2 * f);   // lo*hi
                    }
                }
            }
        }
        __syncthreads();
    }

    // epilogue
    const int g = lane >> 2, t2 = (lane & 3) * 2;
    #pragma unroll
    for (int mf = 0; mf < 2; mf++) {
        #pragma unroll
        for (int nf = 0; nf < 8; nf++) {
            const int row = bm + wm * 32 + mf * 16 + g;
            const int col = bn + wn * 64 + nf * 8 + t2;
            float* d = acc[mf][nf];
            float2 lo = make_float2(d[0] * scale, d[1] * scale);
            float2 hi = make_float2(d[2] * scale, d[3] * scale);
            *(float2*)(C + (size_t)row * ldc + col) = lo;
            *(float2*)(C + (size_t)(row + 8) * ldc + col) = hi;
        }
    }
}

// ---------------------------------------------------------------------------
// fp32 -> bf16 hi/lo split (element-wise)
// ---------------------------------------------------------------------------
__global__ void __launch_bounds__(256) split_kernel(const float* __restrict__ A,
                                                    __nv_bfloat16* __restrict__ Hi,
                                                    __nv_bfloat16* __restrict__ Lo) {
    size_t i = ((size_t)blockIdx.x * 256 + threadIdx.x) * 4;
    float4 a = *(const float4*)(A + i);
    __nv_bfloat16 h0, l0, h1, l1, h2, l2, h3, l3;
    split1(a.x, h0, l0); split1(a.y, h1, l1);
    split1(a.z, h2, l2); split1(a.w, h3, l3);
    __nv_bfloat162* hp = (__nv_bfloat162*)(Hi + i);
    __nv_bfloat162* lp = (__nv_bfloat162*)(Lo + i);
    hp[0] = __nv_bfloat162(h0, h1); hp[1] = __nv_bfloat162(h2, h3);
    lp[0] = __nv_bfloat162(l0, l1); lp[1] = __nv_bfloat162(l2, l3);
}

// W[K,N] -> Wt_hi/lo [N,K] (transpose + split), 32x32 tiles
__global__ void __launch_bounds__(256) transpose_split(const float* __restrict__ W,
                                                       __nv_bfloat16* __restrict__ Th,
                                                       __nv_bfloat16* __restrict__ Tl,
                                                       int K, int N) {
    __shared__ float t[32][33];
    const int k0 = blockIdx.y * 32, n0 = blockIdx.x * 32;
    const int tx = threadIdx.x & 31, ty = threadIdx.x >> 5;   // 32 x 8
    #pragma unroll
    for (int j = 0; j < 4; j++) {
        int row = ty + j * 8;
        t[row][tx] = W[(size_t)(k0 + row) * N + n0 + tx];
    }
    __syncthreads();
    #pragma unroll
    for (int j = 0; j < 4; j++) {
        int row = ty + j * 8;
        float v = t[tx][row];
        __nv_bfloat16 h, l; split1(v, h, l);
        size_t o = (size_t)(n0 + row) * K + k0 + tx;
        Th[o] = h; Tl[o] = l;
    }
}

// ---------------------------------------------------------------------------
// Fast exp (FFMA-only)
// ---------------------------------------------------------------------------
__device__ __forceinline__ float fast_exp(float x) {
    float t = x * 1.4426950408889634f;
    t = fmaxf(fminf(t, 126.0f), -126.0f);
    float fi = rintf(t);
    float f  = t - fi;
    float p  = 0.00133335581464284f;
    p = fmaf(p, f, 0.00961812910762848f);
    p = fmaf(p, f, 0.05550410866482158f);
    p = fmaf(p, f, 0.24022650695910072f);
    p = fmaf(p, f, 0.69314718055994531f);
    p = fmaf(p, f, 1.0f);
    int ei = (int)fi;
    float sc = __int_as_float((ei + 127) << 23);
    return p * sc;
}

// ---------------------------------------------------------------------------
// Softmax over the query axis (per key row of 2048)
// ---------------------------------------------------------------------------
__global__ void __launch_bounds__(256) softmax_rows(float* __restrict__ Sc) {
    __shared__ float shm[8];
    __shared__ float shs[8];
    const size_t row = blockIdx.x;
    float* p = Sc + row * (size_t)S_;
    const int tid = threadIdx.x;
    const int lane = tid & 31, wid = tid >> 5;

    float4 a = *(const float4*)(p + tid * 4);
    float4 bb = *(const float4*)(p + 1024 + tid * 4);

    float m = fmaxf(fmaxf(fmaxf(a.x, a.y), fmaxf(a.z, a.w)),
                    fmaxf(fmaxf(bb.x, bb.y), fmaxf(bb.z, bb.w)));
    #pragma unroll
    for (int o = 16; o; o >>= 1) m = fmaxf(m, __shfl_xor_sync(0xffffffffu, m, o));
    if (lane == 0) shm[wid] = m;
    __syncthreads();
    m = shm[0];
    #pragma unroll
    for (int i = 1; i < 8; i++) m = fmaxf(m, shm[i]);

    a.x = fast_exp(a.x - m);  a.y = fast_exp(a.y - m);
    a.z = fast_exp(a.z - m);  a.w = fast_exp(a.w - m);
    bb.x = fast_exp(bb.x - m); bb.y = fast_exp(bb.y - m);
    bb.z = fast_exp(bb.z - m); bb.w = fast_exp(bb.w - m);

    float s = (a.x + a.y) + (a.z + a.w) + (bb.x + bb.y) + (bb.z + bb.w);
    #pragma unroll
    for (int o = 16; o; o >>= 1) s += __shfl_xor_sync(0xffffffffu, s, o);
    if (lane == 0) shs[wid] = s;
    __syncthreads();
    s = shs[0];
    #pragma unroll
    for (int i = 1; i < 8; i++) s += shs[i];
    const float inv = 1.0f / s;

    a.x *= inv; a.y *= inv; a.z *= inv; a.w *= inv;
    bb.x *= inv; bb.y *= inv; bb.z *= inv; bb.w *= inv;
    *(float4*)(p + tid * 4) = a;
    *(float4*)(p + 1024 + tid * 4) = bb;
}

// ---------------------------------------------------------------------------
// Weighted V: out[q,d] = sum_k P[k,q] * V[k,d]  (SIMT)
// ---------------------------------------------------------------------------
__global__ void __launch_bounds__(256) av_gemm(const float* __restrict__ P,
                                               const float* __restrict__ Vm,
                                               float* __restrict__ O) {
    const int hh = blockIdx.z;
    const int b = hh >> 4, h = hh & 15;
    const float* p = P + (size_t)hh * S_ * S_;
    const float* v = Vm + (size_t)b * S_ * L_ + h * DH_;
    float* o = O + (size_t)b * S_ * L_ + h * DH_;
    const int bq = blockIdx.x * 128;
    __shared__ float Ps[16][128];
    __shared__ float Vs[16][64];
    const int tid = threadIdx.x;
    const int tq = (tid >> 4) * 8;
    const int td = (tid & 15) * 4;
    float acc[8][4] = {};
    for (int k0 = 0; k0 < S_; k0 += 16) {
        #pragma unroll
        for (int i = 0; i < 2; i++) {
            int idx = tid + i * 256;
            int kk = idx >> 5;
            int qq = (idx & 31) * 4;
            *(float4*)&Ps[kk][qq] = *(const float4*)(p + (size_t)(k0 + kk) * S_ + bq + qq);
        }
        {
            int kk = tid >> 4;
            int dd = (tid & 15) * 4;
            *(float4*)&Vs[kk][dd] = *(const float4*)(v + (size_t)(k0 + kk) * L_ + dd);
        }
        __syncthreads();
        #pragma unroll
        for (int kk = 0; kk < 16; kk++) {
            float pr[8], vr[4];
            *(float4*)(pr)     = *(const float4*)&Ps[kk][tq];
            *(float4*)(pr + 4) = *(const float4*)&Ps[kk][tq + 4];
            *(float4*)(vr)     = *(const float4*)&Vs[kk][td];
            #pragma unroll
            for (int i = 0; i < 8; i++)
                #pragma unroll
                for (int j = 0; j < 4; j++)
                    acc[i][j] = fmaf(pr[i], vr[j], acc[i][j]);
        }
        __syncthreads();
    }
    #pragma unroll
    for (int i = 0; i < 8; i++)
        *(float4*)(o + (size_t)(bq + tq + i) * L_ + td) = *(float4*)&acc[i][0];
}

// ---------------------------------------------------------------------------
// Row L2 normalize -> bf16 hi/lo split (feeds next HMMA GEMM)
// ---------------------------------------------------------------------------
__global__ void __launch_bounds__(256) l2norm_split(const float* __restrict__ Z,
                                                    __nv_bfloat16* __restrict__ Hi,
                                                    __nv_bfloat16* __restrict__ Lo) {
    __shared__ float shs[8];
    const size_t row = blockIdx.x;
    const float* p = Z + row * (size_t)D_;
    const int tid = threadIdx.x;
    const int lane = tid & 31, wid = tid >> 5;
    float4 v = *(const float4*)(p + tid * 4);
    float ss = v.x * v.x + v.y * v.y + v.z * v.z + v.w * v.w;
    #pragma unroll
    for (int o = 16; o; o >>= 1) ss += __shfl_xor_sync(0xffffffffu, ss, o);
    if (lane == 0) shs[wid] = ss;
    __syncthreads();
    ss = shs[0];
    #pragma unroll
    for (int i = 1; i < 8; i++) ss += shs[i];
    const float sc = 1.0f / fmaxf(sqrtf(ss), 1e-12f);
    float y0 = v.x * sc, y1 = v.y * sc, y2 = v.z * sc, y3 = v.w * sc;
    __nv_bfloat16 h0, l0, h1, l1, h2, l2, h3, l3;
    split1(y0, h0, l0); split1(y1, h1, l1);
    split1(y2, h2, l2); split1(y3, h3, l3);
    size_t o = row * (size_t)D_ + tid * 4;
    __nv_bfloat162* hp = (__nv_bfloat162*)(Hi + o);
    __nv_bfloat162* lp = (__nv_bfloat162*)(Lo + o);
    hp[0] = __nv_bfloat162(h0, h1); hp[1] = __nv_bfloat162(h2, h3);
    lp[0] = __nv_bfloat162(l0, l1); lp[1] = __nv_bfloat162(l2, l3);
}

// ---------------------------------------------------------------------------
// Row L2 normalize + exact GELU (erf), writes to output
// ---------------------------------------------------------------------------
__global__ void __launch_bounds__(256) l2norm_gelu(const float* __restrict__ Z,
                                                   float* __restrict__ O) {
    __shared__ float shs[8];
    const size_t row = blockIdx.x;
    const float* p = Z + row * (size_t)D_;
    float* q = O + row * (size_t)D_;
    const int tid = threadIdx.x;
    const int lane = tid & 31, wid = tid >> 5;
    float4 v = *(const float4*)(p + tid * 4);
    float ss = v.x * v.x + v.y * v.y + v.z * v.z + v.w * v.w;
    #pragma unroll
    for (int o = 16; o; o >>= 1) ss += __shfl_xor_sync(0xffffffffu, ss, o);
    if (lane == 0) shs[wid] = ss;
    __syncthreads();
    ss = shs[0];
    #pragma unroll
    for (int i = 1; i < 8; i++) ss += shs[i];
    const float sc = 1.0f / fmaxf(sqrtf(ss), 1e-12f);
    float y0 = v.x * sc, y1 = v.y * sc, y2 = v.z * sc, y3 = v.w * sc;
    const float inv_sqrt2 = 0.70710678118654752f;
    float4 g;
    g.x = 0.5f * y0 * (1.0f + erff(y0 * inv_sqrt2));
    g.y = 0.5f * y1 * (1.0f + erff(y1 * inv_sqrt2));
    g.z = 0.5f * y2 * (1.0f + erff(y2 * inv_sqrt2));
    g.w = 0.5f * y3 * (1.0f + erff(y3 * inv_sqrt2));
    *(float4*)(q + tid * 4) = g;
}

// ---------------------------------------------------------------------------
// Launch
// ---------------------------------------------------------------------------
extern "C" void kernel_launch(void* const* d_in, const int* in_sizes, int n_in,
                              void* d_out, int out_size) {
    (void)in_sizes; (void)n_in; (void)out_size;
    const float* x   = (const float*)d_in[0];
    const float* Wq  = (const float*)d_in[1];
    const float* Wk  = (const float*)d_in[2];
    const float* Wv  = (const float*)d_in[3];
    const float* Wo  = (const float*)d_in[4];
    const float* Wff = (const float*)d_in[5];

    float *q, *k, *v, *sc, *ao, *z1, *z2;
    cudaGetSymbolAddress((void**)&q,  g_q);
    cudaGetSymbolAddress((void**)&k,  g_k);
    cudaGetSymbolAddress((void**)&v,  g_v);
    cudaGetSymbolAddress((void**)&sc, g_scores);
    cudaGetSymbolAddress((void**)&ao, g_ao);
    cudaGetSymbolAddress((void**)&z1, g_z1);
    cudaGetSymbolAddress((void**)&z2, g_z2);

    __nv_bfloat16 *xhi, *xlo, *qhi, *qlo, *khi, *klo, *aohi, *aolo, *z1hi, *z1lo, *wth, *wtl;
    cudaGetSymbolAddress((void**)&xhi,  g_xhi);
    cudaGetSymbolAddress((void**)&xlo,  g_xlo);
    cudaGetSymbolAddress((void**)&qhi,  g_qhi);
    cudaGetSymbolAddress((void**)&qlo,  g_qlo);
    cudaGetSymbolAddress((void**)&khi,  g_khi);
    cudaGetSymbolAddress((void**)&klo,  g_klo);
    cudaGetSymbolAddress((void**)&aohi, g_aohi);
    cudaGetSymbolAddress((void**)&aolo, g_aolo);
    cudaGetSymbolAddress((void**)&z1hi, g_z1hi);
    cudaGetSymbolAddress((void**)&z1lo, g_z1lo);
    cudaGetSymbolAddress((void**)&wth,  g_wt_hi);
    cudaGetSymbolAddress((void**)&wtl,  g_wt_lo);
    const size_t WSTR = (size_t)D_ * L_;

    const dim3 blk(256);
    const dim3 gT(L_ / 32, D_ / 32);

    // operand preparation
    split_kernel<<<(M4_ * D_) / 1024, blk>>>(x, xhi, xlo);
    transpose_split<<<gT, blk>>>(Wq,  wth + 0 * WSTR, wtl + 0 * WSTR, D_, L_);
    transpose_split<<<gT, blk>>>(Wk,  wth + 1 * WSTR, wtl + 1 * WSTR, D_, L_);
    transpose_split<<<gT, blk>>>(Wv,  wth + 2 * WSTR, wtl + 2 * WSTR, D_, L_);
    transpose_split<<<gT, blk>>>(Wo,  wth + 3 * WSTR, wtl + 3 * WSTR, L_, D_);
    transpose_split<<<gT, blk>>>(Wff, wth + 4 * WSTR, wtl + 4 * WSTR, D_, D_);

    const dim3 gG(L_ / 128, M4_ / 128, 1);           // (8, 32)

    // QKV projections (HMMA bf16x3)
    hgemm_nt<<<gG, blk>>>(xhi, xlo, wth + 0 * WSTR, wtl + 0 * WSTR, q, M4_, L_, D_, D_, D_, L_, 1.0f, 0);
    hgemm_nt<<<gG, blk>>>(xhi, xlo, wth + 1 * WSTR, wtl + 1 * WSTR, k, M4_, L_, D_, D_, D_, L_, 1.0f, 0);
    hgemm_nt<<<gG, blk>>>(xhi, xlo, wth + 2 * WSTR, wtl + 2 * WSTR, v, M4_, L_, D_, D_, D_, L_, 1.0f, 0);

    // scores via HMMA: per head, C[k][q] = (1/32) * K · Q^T
    split_kernel<<<(M4_ * L_) / 1024, blk>>>(q, qhi, qlo);
    split_kernel<<<(M4_ * L_) / 1024, blk>>>(k, khi, klo);
    hgemm_nt<<<dim3(S_ / 128, S_ / 128, BH_), blk>>>(khi, klo, qhi, qlo, sc,
                                                     S_, S_, DH_, L_, L_, S_, 0.03125f, 1);

    softmax_rows<<<BH_ * S_, blk>>>(sc);
    av_gemm<<<dim3(S_ / 128, 1, BH_), blk>>>(sc, v, ao);

    // output projection (HMMA)
    split_kernel<<<(M4_ * L_) / 1024, blk>>>(ao, aohi, aolo);
    hgemm_nt<<<gG, blk>>>(aohi, aolo, wth + 3 * WSTR, wtl + 3 * WSTR, z1, M4_, D_, L_, L_, L_, D_, 1.0f, 0);

    // FFN (HMMA)
    l2norm_split<<<M4_, blk>>>(z1, z1hi, z1lo);
    hgemm_nt<<<gG, blk>>>(z1hi, z1lo, wth + 4 * WSTR, wtl + 4 * WSTR, z2, M4_, D_, D_, D_, D_, D_, 1.0f, 0);
    l2norm_gelu<<<M4_, blk>>>(z2, (float*)d_out);
}

// round 10
// speedup vs baseline: 1.6529x; 1.1351x over previous
#include <cuda_runtime.h>
#include <cuda_bf16.h>
#include <math.h>
#include <stdint.h>

// Problem dims (fixed by the dataset)
#define B_  2
#define S_  2048
#define D_  1024
#define L_  1024
#define H_  16
#define DH_ 64
#define BH_ (B_ * H_)          // 32
#define M4_ (B_ * S_)          // 4096 rows for the dense GEMMs

// ---------------------------------------------------------------------------
// Scratch (static __device__ globals — allocation-free per harness rules)
// ---------------------------------------------------------------------------
__device__ float g_q[(size_t)M4_ * L_];
__device__ float g_k[(size_t)M4_ * L_];
__device__ float g_v[(size_t)M4_ * L_];
__device__ float g_scores[(size_t)BH_ * S_ * S_];   // 512 MB: [head][k][q]
__device__ float g_ao[(size_t)M4_ * L_];
__device__ float g_z1[(size_t)M4_ * D_];
__device__ float g_z2[(size_t)M4_ * D_];

// softmax probabilities, bf16 hi/lo split: [head][k][q]
__device__ unsigned short g_phi[(size_t)BH_ * S_ * S_];
__device__ unsigned short g_plo[(size_t)BH_ * S_ * S_];

// bf16 hi/lo split operands (ushort storage)
__device__ unsigned short g_xhi[(size_t)M4_ * D_];
__device__ unsigned short g_xlo[(size_t)M4_ * D_];
__device__ unsigned short g_qhi[(size_t)M4_ * L_];
__device__ unsigned short g_qlo[(size_t)M4_ * L_];
__device__ unsigned short g_khi[(size_t)M4_ * L_];
__device__ unsigned short g_klo[(size_t)M4_ * L_];
__device__ unsigned short g_aohi[(size_t)M4_ * L_];
__device__ unsigned short g_aolo[(size_t)M4_ * L_];
__device__ unsigned short g_z1hi[(size_t)M4_ * D_];
__device__ unsigned short g_z1lo[(size_t)M4_ * D_];
// transposed weights [N,K] hi/lo, 5 weights
__device__ unsigned short g_wt_hi[5][(size_t)D_ * L_];
__device__ unsigned short g_wt_lo[5][(size_t)D_ * L_];

// ---------------------------------------------------------------------------
// helpers
// ---------------------------------------------------------------------------
__device__ __forceinline__ uint32_t sptr(const void* p) {
    return (uint32_t)__cvta_generic_to_shared(p);
}

__device__ __forceinline__ void ldsm4(uint32_t a, uint32_t& r0, uint32_t& r1,
                                      uint32_t& r2, uint32_t& r3) {
    asm volatile("ldmatrix.sync.aligned.m8n8.x4.shared.b16 {%0,%1,%2,%3}, [%4];"
                 : "=r"(r0), "=r"(r1), "=r"(r2), "=r"(r3) : "r"(a));
}

__device__ __forceinline__ void ldsm4t(uint32_t a, uint32_t& r0, uint32_t& r1,
                                       uint32_t& r2, uint32_t& r3) {
    asm volatile("ldmatrix.sync.aligned.m8n8.x4.trans.shared.b16 {%0,%1,%2,%3}, [%4];"
                 : "=r"(r0), "=r"(r1), "=r"(r2), "=r"(r3) : "r"(a));
}

__device__ __forceinline__ void mma16816(float* d, const uint32_t* a, const uint32_t* b) {
    asm volatile(
        "mma.sync.aligned.m16n8k16.row.col.f32.bf16.bf16.f32 "
        "{%0,%1,%2,%3}, {%4,%5,%6,%7}, {%8,%9}, {%0,%1,%2,%3};"
        : "+f"(d[0]), "+f"(d[1]), "+f"(d[2]), "+f"(d[3])
        : "r"(a[0]), "r"(a[1]), "r"(a[2]), "r"(a[3]), "r"(b[0]), "r"(b[1]));
}

__device__ __forceinline__ void split1(float a, __nv_bfloat16& h, __nv_bfloat16& l) {
    h = __float2bfloat16(a);
    l = __float2bfloat16(a - __bfloat162float(h));
}

// ---------------------------------------------------------------------------
// Warp-MMA NT GEMM, bf16x3: C[M,N] = scale * A[M,K] @ Bt[N,K]^T, fp32 out.
// CTA 128x128, K-chunk 32, 256 threads = 8 warps (4M x 2N), warp tile 32x64.
// headMode: blockIdx.z selects attention head slices (stride-L_ views).
// ---------------------------------------------------------------------------
#define PAD_ 40

__global__ void __launch_bounds__(256) hgemm_nt(
    const __nv_bfloat16* __restrict__ Ahi, const __nv_bfloat16* __restrict__ Alo,
    const __nv_bfloat16* __restrict__ Bhi, const __nv_bfloat16* __restrict__ Blo,
    float* __restrict__ C, int M, int N, int K,
    int lda, int ldb, int ldc, float scale, int headMode) {
    __shared__ __align__(16) __nv_bfloat16 sAh[128][PAD_];
    __shared__ __align__(16) __nv_bfloat16 sAl[128][PAD_];
    __shared__ __align__(16) __nv_bfloat16 sBh[128][PAD_];
    __shared__ __align__(16) __nv_bfloat16 sBl[128][PAD_];

    if (headMode) {
        const int z = blockIdx.z;
        const int b = z >> 4, h = z & 15;
        const size_t off = (size_t)b * S_ * L_ + (size_t)h * DH_;
        Ahi += off; Alo += off; Bhi += off; Blo += off;
        C += (size_t)z * S_ * S_;
    }

    const int tid = threadIdx.x;
    const int wid = tid >> 5, lane = tid & 31;
    const int wm = wid >> 1, wn = wid & 1;
    const int bm = blockIdx.y * 128, bn = blockIdx.x * 128;

    float acc[2][8][4];
    #pragma unroll
    for (int i = 0; i < 2; i++)
        #pragma unroll
        for (int j = 0; j < 8; j++)
            #pragma unroll
            for (int r = 0; r < 4; r++) acc[i][j][r] = 0.0f;

    const int a_row = (lane & 15);
    const int a_col8 = (lane >> 4) * 8;
    const int b_rowoff = (lane & 7) + ((lane >> 4) << 3);
    const int b_col8 = ((lane >> 3) & 1) * 8;

    for (int k0 = 0; k0 < K; k0 += 32) {
        #pragma unroll
        for (int i = 0; i < 2; i++) {
            const int idx = tid + i * 256;
            const int row = idx >> 2;
            const int seg = (idx & 3) * 8;
            *(uint4*)&sAh[row][seg] = *(const uint4*)(Ahi + (size_t)(bm + row) * lda + k0 + seg);
            *(uint4*)&sAl[row][seg] = *(const uint4*)(Alo + (size_t)(bm + row) * lda + k0 + seg);
            *(uint4*)&sBh[row][seg] = *(const uint4*)(Bhi + (size_t)(bn + row) * ldb + k0 + seg);
            *(uint4*)&sBl[row][seg] = *(const uint4*)(Blo + (size_t)(bn + row) * ldb + k0 + seg);
        }
        __syncthreads();

        #pragma unroll
        for (int ks = 0; ks < 2; ks++) {
            const int kc = ks * 16;
            uint32_t ah[2][4], al[2][4];
            #pragma unroll
            for (int mf = 0; mf < 2; mf++) {
                ldsm4(sptr(&sAh[wm * 32 + mf * 16 + a_row][kc + a_col8]),
                      ah[mf][0], ah[mf][1], ah[mf][2], ah[mf][3]);
                ldsm4(sptr(&sAl[wm * 32 + mf * 16 + a_row][kc + a_col8]),
                      al[mf][0], al[mf][1], al[mf][2], al[mf][3]);
            }
            #pragma unroll
            for (int nf2 = 0; nf2 < 4; nf2++) {
                const int brow = wn * 64 + nf2 * 16 + b_rowoff;
                uint32_t bh[4], bl[4];
                ldsm4(sptr(&sBh[brow][kc + b_col8]), bh[0], bh[1], bh[2], bh[3]);
                ldsm4(sptr(&sBl[brow][kc + b_col8]), bl[0], bl[1], bl[2], bl[3]);
                #pragma unroll
                for (int mf = 0; mf < 2; mf++) {
                    #pragma unroll
                    for (int f = 0; f < 2; f++) {
                        float* d = acc[mf][nf2 * 2 + f];
                        mma16816(d, ah[mf], bh + 2 * f);
                        mma16816(d, ah[mf], bl + 2 * f);
                        mma16816(d, al[mf], bh + 2 * f);
                    }
                }
            }
        }
        __syncthreads();
    }

    const int g = lane >> 2, t2 = (lane & 3) * 2;
    #pragma unroll
    for (int mf = 0; mf < 2; mf++) {
        #pragma unroll
        for (int nf = 0; nf < 8; nf++) {
            const int row = bm + wm * 32 + mf * 16 + g;
            const int col = bn + wn * 64 + nf * 8 + t2;
            float* d = acc[mf][nf];
            float2 lo = make_float2(d[0] * scale, d[1] * scale);
            float2 hi = make_float2(d[2] * scale, d[3] * scale);
            *(float2*)(C + (size_t)row * ldc + col) = lo;
            *(float2*)(C + (size_t)(row + 8) * ldc + col) = hi;
        }
    }
}

// ---------------------------------------------------------------------------
// Attention-weighted V via HMMA: out[q,d] = sum_k P[k,q] * V[k,d]  (per head)
// P given bf16 hi/lo K-major [k][q]; V fp32 [k][d] split in-kernel.
// CTA: 128 q x 64 d, K-chunk 32, 8 warps each 16 q x 64 d.
// Trans-ldmatrix loads both operands (K-major storage).
// ---------------------------------------------------------------------------
#define AVP_ 136   // P tile pitch (bf16): 272B rows -> conflict-free trans ldsm
#define AVV_ 72    // V tile pitch (bf16): 144B rows

__global__ void __launch_bounds__(256) av_hmma(
    const __nv_bfloat16* __restrict__ Phi, const __nv_bfloat16* __restrict__ Plo,
    const float* __restrict__ Vm, float* __restrict__ O) {
    __shared__ __align__(16) __nv_bfloat16 sPh[32][AVP_];
    __shared__ __align__(16) __nv_bfloat16 sPl[32][AVP_];
    __shared__ __align__(16) __nv_bfloat16 sVh[32][AVV_];
    __shared__ __align__(16) __nv_bfloat16 sVl[32][AVV_];

    const int hh = blockIdx.z;
    const int b = hh >> 4, h = hh & 15;
    const __nv_bfloat16* ph = Phi + (size_t)hh * S_ * S_;
    const __nv_bfloat16* pl = Plo + (size_t)hh * S_ * S_;
    const float* v = Vm + (size_t)b * S_ * L_ + h * DH_;
    float* o = O + (size_t)b * S_ * L_ + h * DH_;
    const int bq = blockIdx.x * 128;
    const int tid = threadIdx.x;
    const int wid = tid >> 5, lane = tid & 31;
    const int wq = wid * 16;

    float acc[8][4];
    #pragma unroll
    for (int j = 0; j < 8; j++)
        #pragma unroll
        for (int r = 0; r < 4; r++) acc[j][r] = 0.0f;

    // trans-ldmatrix lane address components
    const int a_k = (lane & 7) + ((lane >> 4) << 3);      // A: k row in tile
    const int a_q = ((lane >> 3) & 1) * 8;                // A: q group
    const int b_k = (lane & 7) + (((lane >> 3) & 1) << 3);// B: k row
    const int b_d = (lane >> 4) * 8;                      // B: d group

    for (int k0 = 0; k0 < S_; k0 += 32) {
        // P tile: 32 k x 128 q bf16 hi/lo (512 uint4 each)
        #pragma unroll
        for (int i = 0; i < 2; i++) {
            int idx = tid + i * 256;
            int kk = idx >> 4;
            int qq = (idx & 15) * 8;
            *(uint4*)&sPh[kk][qq] = *(const uint4*)(ph + (size_t)(k0 + kk) * S_ + bq + qq);
            *(uint4*)&sPl[kk][qq] = *(const uint4*)(pl + (size_t)(k0 + kk) * S_ + bq + qq);
        }
        // V tile: 32 k x 64 d fp32 -> bf16 hi/lo (512 float4)
        #pragma unroll
        for (int i = 0; i < 2; i++) {
            int idx = tid + i * 256;
            int kk = idx >> 4;
            int dd = (idx & 15) * 4;
            float4 a = *(const float4*)(v + (size_t)(k0 + kk) * L_ + dd);
            __nv_bfloat16 h0, l0, h1, l1, h2, l2, h3, l3;
            split1(a.x, h0, l0); split1(a.y, h1, l1);
            split1(a.z, h2, l2); split1(a.w, h3, l3);
            *(__nv_bfloat162*)&sVh[kk][dd]     = __nv_bfloat162(h0, h1);
            *(__nv_bfloat162*)&sVh[kk][dd + 2] = __nv_bfloat162(h2, h3);
            *(__nv_bfloat162*)&sVl[kk][dd]     = __nv_bfloat162(l0, l1);
            *(__nv_bfloat162*)&sVl[kk][dd + 2] = __nv_bfloat162(l2, l3);
        }
        __syncthreads();

        #pragma unroll
        for (int ks = 0; ks < 2; ks++) {
            const int kc = ks * 16;
            uint32_t aph[4], apl[4];
            ldsm4t(sptr(&sPh[kc + a_k][wq + a_q]), aph[0], aph[1], aph[2], aph[3]);
            ldsm4t(sptr(&sPl[kc + a_k][wq + a_q]), apl[0], apl[1], apl[2], apl[3]);
            #pragma unroll
            for (int nb = 0; nb < 4; nb++) {          // d blocks of 16
                uint32_t bvh[4], bvl[4];
                ldsm4t(sptr(&sVh[kc + b_k][nb * 16 + b_d]), bvh[0], bvh[1], bvh[2], bvh[3]);
                ldsm4t(sptr(&sVl[kc + b_k][nb * 16 + b_d]), bvl[0], bvl[1], bvl[2], bvl[3]);
                #pragma unroll
                for (int f = 0; f < 2; f++) {
                    float* d = acc[nb * 2 + f];
                    mma16816(d, aph, bvh + 2 * f);    // hi*hi
                    mma16816(d, aph, bvl + 2 * f);    // hi*lo
                    mma16816(d, apl, bvh + 2 * f);    // lo*hi
                }
            }
        }
        __syncthreads();
    }

    // epilogue
    const int g = lane >> 2, t2 = (lane & 3) * 2;
    #pragma unroll
    for (int nf = 0; nf < 8; nf++) {
        const int row = bq + wq + g;
        const int col = nf * 8 + t2;
        float* d = acc[nf];
        *(float2*)(o + (size_t)row * L_ + col) = make_float2(d[0], d[1]);
        *(float2*)(o + (size_t)(row + 8) * L_ + col) = make_float2(d[2], d[3]);
    }
}

// ---------------------------------------------------------------------------
// fp32 -> bf16 hi/lo split (element-wise)
// ---------------------------------------------------------------------------
__global__ void __launch_bounds__(256) split_kernel(const float* __restrict__ A,
                                                    __nv_bfloat16* __restrict__ Hi,
                                                    __nv_bfloat16* __restrict__ Lo) {
    size_t i = ((size_t)blockIdx.x * 256 + threadIdx.x) * 4;
    float4 a = *(const float4*)(A + i);
    __nv_bfloat16 h0, l0, h1, l1, h2, l2, h3, l3;
    split1(a.x, h0, l0); split1(a.y, h1, l1);
    split1(a.z, h2, l2); split1(a.w, h3, l3);
    __nv_bfloat162* hp = (__nv_bfloat162*)(Hi + i);
    __nv_bfloat162* lp = (__nv_bfloat162*)(Lo + i);
    hp[0] = __nv_bfloat162(h0, h1); hp[1] = __nv_bfloat162(h2, h3);
    lp[0] = __nv_bfloat162(l0, l1); lp[1] = __nv_bfloat162(l2, l3);
}

// W[K,N] -> Wt_hi/lo [N,K] (transpose + split), 32x32 tiles
__global__ void __launch_bounds__(256) transpose_split(const float* __restrict__ W,
                                                       __nv_bfloat16* __restrict__ Th,
                                                       __nv_bfloat16* __restrict__ Tl,
                                                       int K, int N) {
    __shared__ float t[32][33];
    const int k0 = blockIdx.y * 32, n0 = blockIdx.x * 32;
    const int tx = threadIdx.x & 31, ty = threadIdx.x >> 5;
    #pragma unroll
    for (int j = 0; j < 4; j++) {
        int row = ty + j * 8;
        t[row][tx] = W[(size_t)(k0 + row) * N + n0 + tx];
    }
    __syncthreads();
    #pragma unroll
    for (int j = 0; j < 4; j++) {
        int row = ty + j * 8;
        float v = t[tx][row];
        __nv_bfloat16 h, l; split1(v, h, l);
        size_t o = (size_t)(n0 + row) * K + k0 + tx;
        Th[o] = h; Tl[o] = l;
    }
}

// ---------------------------------------------------------------------------
// Fast exp (FFMA-only)
// ---------------------------------------------------------------------------
__device__ __forceinline__ float fast_exp(float x) {
    float t = x * 1.4426950408889634f;
    t = fmaxf(fminf(t, 126.0f), -126.0f);
    float fi = rintf(t);
    float f  = t - fi;
    float p  = 0.00133335581464284f;
    p = fmaf(p, f, 0.00961812910762848f);
    p = fmaf(p, f, 0.05550410866482158f);
    p = fmaf(p, f, 0.24022650695910072f);
    p = fmaf(p, f, 0.69314718055994531f);
    p = fmaf(p, f, 1.0f);
    int ei = (int)fi;
    float sc = __int_as_float((ei + 127) << 23);
    return p * sc;
}

// ---------------------------------------------------------------------------
// Softmax over the query axis (per key row of 2048), emits bf16 hi/lo P.
// ---------------------------------------------------------------------------
__global__ void __launch_bounds__(256) softmax_rows(const float* __restrict__ Sc,
                                                    __nv_bfloat16* __restrict__ Phi,
                                                    __nv_bfloat16* __restrict__ Plo) {
    __shared__ float shm[8];
    __shared__ float shs[8];
    const size_t row = blockIdx.x;
    const float* p = Sc + row * (size_t)S_;
    const int tid = threadIdx.x;
    const int lane = tid & 31, wid = tid >> 5;

    float4 a = *(const float4*)(p + tid * 4);
    float4 bb = *(const float4*)(p + 1024 + tid * 4);

    float m = fmaxf(fmaxf(fmaxf(a.x, a.y), fmaxf(a.z, a.w)),
                    fmaxf(fmaxf(bb.x, bb.y), fmaxf(bb.z, bb.w)));
    #pragma unroll
    for (int o = 16; o; o >>= 1) m = fmaxf(m, __shfl_xor_sync(0xffffffffu, m, o));
    if (lane == 0) shm[wid] = m;
    __syncthreads();
    m = shm[0];
    #pragma unroll
    for (int i = 1; i < 8; i++) m = fmaxf(m, shm[i]);

    a.x = fast_exp(a.x - m);  a.y = fast_exp(a.y - m);
    a.z = fast_exp(a.z - m);  a.w = fast_exp(a.w - m);
    bb.x = fast_exp(bb.x - m); bb.y = fast_exp(bb.y - m);
    bb.z = fast_exp(bb.z - m); bb.w = fast_exp(bb.w - m);

    float s = (a.x + a.y) + (a.z + a.w) + (bb.x + bb.y) + (bb.z + bb.w);
    #pragma unroll
    for (int o = 16; o; o >>= 1) s += __shfl_xor_sync(0xffffffffu, s, o);
    if (lane == 0) shs[wid] = s;
    __syncthreads();
    s = shs[0];
    #pragma unroll
    for (int i = 1; i < 8; i++) s += shs[i];
    const float inv = 1.0f / s;

    a.x *= inv; a.y *= inv; a.z *= inv; a.w *= inv;
    bb.x *= inv; bb.y *= inv; bb.z *= inv; bb.w *= inv;

    __nv_bfloat16 h0, l0, h1, l1, h2, l2, h3, l3;
    size_t o1 = row * (size_t)S_ + tid * 4;
    size_t o2 = o1 + 1024;
    split1(a.x, h0, l0); split1(a.y, h1, l1);
    split1(a.z, h2, l2); split1(a.w, h3, l3);
    ((__nv_bfloat162*)(Phi + o1))[0] = __nv_bfloat162(h0, h1);
    ((__nv_bfloat162*)(Phi + o1))[1] = __nv_bfloat162(h2, h3);
    ((__nv_bfloat162*)(Plo + o1))[0] = __nv_bfloat162(l0, l1);
    ((__nv_bfloat162*)(Plo + o1))[1] = __nv_bfloat162(l2, l3);
    split1(bb.x, h0, l0); split1(bb.y, h1, l1);
    split1(bb.z, h2, l2); split1(bb.w, h3, l3);
    ((__nv_bfloat162*)(Phi + o2))[0] = __nv_bfloat162(h0, h1);
    ((__nv_bfloat162*)(Phi + o2))[1] = __nv_bfloat162(h2, h3);
    ((__nv_bfloat162*)(Plo + o2))[0] = __nv_bfloat162(l0, l1);
    ((__nv_bfloat162*)(Plo + o2))[1] = __nv_bfloat162(l2, l3);
}

// ---------------------------------------------------------------------------
// Row L2 normalize -> bf16 hi/lo split (feeds next HMMA GEMM)
// ---------------------------------------------------------------------------
__global__ void __launch_bounds__(256) l2norm_split(const float* __restrict__ Z,
                                                    __nv_bfloat16* __restrict__ Hi,
                                                    __nv_bfloat16* __restrict__ Lo) {
    __shared__ float shs[8];
    const size_t row = blockIdx.x;
    const float* p = Z + row * (size_t)D_;
    const int tid = threadIdx.x;
    const int lane = tid & 31, wid = tid >> 5;
    float4 v = *(const float4*)(p + tid * 4);
    float ss = v.x * v.x + v.y * v.y + v.z * v.z + v.w * v.w;
    #pragma unroll
    for (int o = 16; o; o >>= 1) ss += __shfl_xor_sync(0xffffffffu, ss, o);
    if (lane == 0) shs[wid] = ss;
    __syncthreads();
    ss = shs[0];
    #pragma unroll
    for (int i = 1; i < 8; i++) ss += shs[i];
    const float sc = 1.0f / fmaxf(sqrtf(ss), 1e-12f);
    float y0 = v.x * sc, y1 = v.y * sc, y2 = v.z * sc, y3 = v.w * sc;
    __nv_bfloat16 h0, l0, h1, l1, h2, l2, h3, l3;
    split1(y0, h0, l0); split1(y1, h1, l1);
    split1(y2, h2, l2); split1(y3, h3, l3);
    size_t o = row * (size_t)D_ + tid * 4;
    __nv_bfloat162* hp = (__nv_bfloat162*)(Hi + o);
    __nv_bfloat162* lp = (__nv_bfloat162*)(Lo + o);
    hp[0] = __nv_bfloat162(h0, h1); hp[1] = __nv_bfloat162(h2, h3);
    lp[0] = __nv_bfloat162(l0, l1); lp[1] = __nv_bfloat162(l2, l3);
}

// ---------------------------------------------------------------------------
// Row L2 normalize + exact GELU (erf), writes to output
// ---------------------------------------------------------------------------
__global__ void __launch_bounds__(256) l2norm_gelu(const float* __restrict__ Z,
                                                   float* __restrict__ O) {
    __shared__ float shs[8];
    const size_t row = blockIdx.x;
    const float* p = Z + row * (size_t)D_;
    float* q = O + row * (size_t)D_;
    const int tid = threadIdx.x;
    const int lane = tid & 31, wid = tid >> 5;
    float4 v = *(const float4*)(p + tid * 4);
    float ss = v.x * v.x + v.y * v.y + v.z * v.z + v.w * v.w;
    #pragma unroll
    for (int o = 16; o; o >>= 1) ss += __shfl_xor_sync(0xffffffffu, ss, o);
    if (lane == 0) shs[wid] = ss;
    __syncthreads();
    ss = shs[0];
    #pragma unroll
    for (int i = 1; i < 8; i++) ss += shs[i];
    const float sc = 1.0f / fmaxf(sqrtf(ss), 1e-12f);
    float y0 = v.x * sc, y1 = v.y * sc, y2 = v.z * sc, y3 = v.w * sc;
    const float inv_sqrt2 = 0.70710678118654752f;
    float4 g;
    g.x = 0.5f * y0 * (1.0f + erff(y0 * inv_sqrt2));
    g.y = 0.5f * y1 * (1.0f + erff(y1 * inv_sqrt2));
    g.z = 0.5f * y2 * (1.0f + erff(y2 * inv_sqrt2));
    g.w = 0.5f * y3 * (1.0f + erff(y3 * inv_sqrt2));
    *(float4*)(q + tid * 4) = g;
}

// ---------------------------------------------------------------------------
// Launch
// ---------------------------------------------------------------------------
extern "C" void kernel_launch(void* const* d_in, const int* in_sizes, int n_in,
                              void* d_out, int out_size) {
    (void)in_sizes; (void)n_in; (void)out_size;
    const float* x   = (const float*)d_in[0];
    const float* Wq  = (const float*)d_in[1];
    const float* Wk  = (const float*)d_in[2];
    const float* Wv  = (const float*)d_in[3];
    const float* Wo  = (const float*)d_in[4];
    const float* Wff = (const float*)d_in[5];

    float *q, *k, *v, *sc, *ao, *z1, *z2;
    cudaGetSymbolAddress((void**)&q,  g_q);
    cudaGetSymbolAddress((void**)&k,  g_k);
    cudaGetSymbolAddress((void**)&v,  g_v);
    cudaGetSymbolAddress((void**)&sc, g_scores);
    cudaGetSymbolAddress((void**)&ao, g_ao);
    cudaGetSymbolAddress((void**)&z1, g_z1);
    cudaGetSymbolAddress((void**)&z2, g_z2);

    __nv_bfloat16 *phi, *plo;
    cudaGetSymbolAddress((void**)&phi, g_phi);
    cudaGetSymbolAddress((void**)&plo, g_plo);

    __nv_bfloat16 *xhi, *xlo, *qhi, *qlo, *khi, *klo, *aohi, *aolo, *z1hi, *z1lo, *wth, *wtl;
    cudaGetSymbolAddress((void**)&xhi,  g_xhi);
    cudaGetSymbolAddress((void**)&xlo,  g_xlo);
    cudaGetSymbolAddress((void**)&qhi,  g_qhi);
    cudaGetSymbolAddress((void**)&qlo,  g_qlo);
    cudaGetSymbolAddress((void**)&khi,  g_khi);
    cudaGetSymbolAddress((void**)&klo,  g_klo);
    cudaGetSymbolAddress((void**)&aohi, g_aohi);
    cudaGetSymbolAddress((void**)&aolo, g_aolo);
    cudaGetSymbolAddress((void**)&z1hi, g_z1hi);
    cudaGetSymbolAddress((void**)&z1lo, g_z1lo);
    cudaGetSymbolAddress((void**)&wth,  g_wt_hi);
    cudaGetSymbolAddress((void**)&wtl,  g_wt_lo);
    const size_t WSTR = (size_t)D_ * L_;

    const dim3 blk(256);
    const dim3 gT(L_ / 32, D_ / 32);

    // operand preparation
    split_kernel<<<(M4_ * D_) / 1024, blk>>>(x, xhi, xlo);
    transpose_split<<<gT, blk>>>(Wq,  wth + 0 * WSTR, wtl + 0 * WSTR, D_, L_);
    transpose_split<<<gT, blk>>>(Wk,  wth + 1 * WSTR, wtl + 1 * WSTR, D_, L_);
    transpose_split<<<gT, blk>>>(Wv,  wth + 2 * WSTR, wtl + 2 * WSTR, D_, L_);
    transpose_split<<<gT, blk>>>(Wo,  wth + 3 * WSTR, wtl + 3 * WSTR, L_, D_);
    transpose_split<<<gT, blk>>>(Wff, wth + 4 * WSTR, wtl + 4 * WSTR, D_, D_);

    const dim3 gG(L_ / 128, M4_ / 128, 1);           // (8, 32)

    // QKV projections (HMMA bf16x3)
    hgemm_nt<<<gG, blk>>>(xhi, xlo, wth + 0 * WSTR, wtl + 0 * WSTR, q, M4_, L_, D_, D_, D_, L_, 1.0f, 0);
    hgemm_nt<<<gG, blk>>>(xhi, xlo, wth + 1 * WSTR, wtl + 1 * WSTR, k, M4_, L_, D_, D_, D_, L_, 1.0f, 0);
    hgemm_nt<<<gG, blk>>>(xhi, xlo, wth + 2 * WSTR, wtl + 2 * WSTR, v, M4_, L_, D_, D_, D_, L_, 1.0f, 0);

    // scores via HMMA: per head, C[k][q] = (1/32) * K · Q^T
    split_kernel<<<(M4_ * L_) / 1024, blk>>>(q, qhi, qlo);
    split_kernel<<<(M4_ * L_) / 1024, blk>>>(k, khi, klo);
    hgemm_nt<<<dim3(S_ / 128, S_ / 128, BH_), blk>>>(khi, klo, qhi, qlo, sc,
                                                     S_, S_, DH_, L_, L_, S_, 0.03125f, 1);

    // softmax over q axis, emitting bf16 hi/lo P
    softmax_rows<<<BH_ * S_, blk>>>(sc, phi, plo);

    // attention-weighted V (HMMA bf16x3, trans ldmatrix)
    av_hmma<<<dim3(S_ / 128, 1, BH_), blk>>>(phi, plo, v, ao);

    // output projection (HMMA)
    split_kernel<<<(M4_ * L_) / 1024, blk>>>(ao, aohi, aolo);
    hgemm_nt<<<gG, blk>>>(aohi, aolo, wth + 3 * WSTR, wtl + 3 * WSTR, z1, M4_, D_, L_, L_, L_, D_, 1.0f, 0);

    // FFN (HMMA)
    l2norm_split<<<M4_, blk>>>(z1, z1hi, z1lo);
    hgemm_nt<<<gG, blk>>>(z1hi, z1lo, wth + 4 * WSTR, wtl + 4 * WSTR, z2, M4_, D_, D_, D_, D_, D_, 1.0f, 0);
    l2norm_gelu<<<M4_, blk>>>(z2, (float*)d_out);
}

// round 12
// speedup vs baseline: 1.8737x; 1.1336x over previous
#include <cuda_runtime.h>
#include <cuda_bf16.h>
#include <math.h>
#include <stdint.h>

// Problem dims (fixed by the dataset)
#define B_  2
#define S_  2048
#define D_  1024
#define L_  1024
#define H_  16
#define DH_ 64
#define BH_ (B_ * H_)          // 32
#define M4_ (B_ * S_)          // 4096

// ---------------------------------------------------------------------------
// Scratch
// ---------------------------------------------------------------------------
__device__ float g_z1[(size_t)M4_ * D_];
__device__ float g_z2[(size_t)M4_ * D_];
__device__ float g_rz[(size_t)BH_ * S_];            // 1/Z per (head, k)

__device__ unsigned short g_xhi[(size_t)M4_ * D_];
__device__ unsigned short g_xlo[(size_t)M4_ * D_];
__device__ unsigned short g_qhi[(size_t)M4_ * L_];
__device__ unsigned short g_qlo[(size_t)M4_ * L_];
__device__ unsigned short g_khi[(size_t)M4_ * L_];
__device__ unsigned short g_klo[(size_t)M4_ * L_];
__device__ unsigned short g_vhi[(size_t)M4_ * L_];
__device__ unsigned short g_vlo[(size_t)M4_ * L_];
__device__ unsigned short g_aohi[(size_t)M4_ * L_];
__device__ unsigned short g_aolo[(size_t)M4_ * L_];
__device__ unsigned short g_z1hi[(size_t)M4_ * D_];
__device__ unsigned short g_z1lo[(size_t)M4_ * D_];
__device__ unsigned short g_wt_hi[5][(size_t)D_ * L_];
__device__ unsigned short g_wt_lo[5][(size_t)D_ * L_];

// ---------------------------------------------------------------------------
// helpers
// ---------------------------------------------------------------------------
__device__ __forceinline__ uint32_t sptr(const void* p) {
    return (uint32_t)__cvta_generic_to_shared(p);
}
__device__ __forceinline__ void ldsm4(uint32_t a, uint32_t& r0, uint32_t& r1,
                                      uint32_t& r2, uint32_t& r3) {
    asm volatile("ldmatrix.sync.aligned.m8n8.x4.shared.b16 {%0,%1,%2,%3}, [%4];"
                 : "=r"(r0), "=r"(r1), "=r"(r2), "=r"(r3) : "r"(a));
}
__device__ __forceinline__ void ldsm4t(uint32_t a, uint32_t& r0, uint32_t& r1,
                                       uint32_t& r2, uint32_t& r3) {
    asm volatile("ldmatrix.sync.aligned.m8n8.x4.trans.shared.b16 {%0,%1,%2,%3}, [%4];"
                 : "=r"(r0), "=r"(r1), "=r"(r2), "=r"(r3) : "r"(a));
}
__device__ __forceinline__ void mma16816(float* d, const uint32_t* a, const uint32_t* b) {
    asm volatile(
        "mma.sync.aligned.m16n8k16.row.col.f32.bf16.bf16.f32 "
        "{%0,%1,%2,%3}, {%4,%5,%6,%7}, {%8,%9}, {%0,%1,%2,%3};"
        : "+f"(d[0]), "+f"(d[1]), "+f"(d[2]), "+f"(d[3])
        : "r"(a[0]), "r"(a[1]), "r"(a[2]), "r"(a[3]), "r"(b[0]), "r"(b[1]));
}
__device__ __forceinline__ void split1(float a, __nv_bfloat16& h, __nv_bfloat16& l) {
    h = __float2bfloat16(a);
    l = __float2bfloat16(a - __bfloat162float(h));
}
// split two floats -> packed bf16x2 hi pair + lo pair (x low halfword, y high)
__device__ __forceinline__ void split_pack(float x, float y, uint32_t& hi, uint32_t& lo) {
    __nv_bfloat16 hx, lx, hy, ly;
    split1(x, hx, lx); split1(y, hy, ly);
    __nv_bfloat162 Hp(hx, hy), Lp(lx, ly);
    hi = *(uint32_t*)&Hp; lo = *(uint32_t*)&Lp;
}
__device__ __forceinline__ float fast_exp(float x) {
    float t = x * 1.4426950408889634f;
    t = fmaxf(fminf(t, 126.0f), -126.0f);
    float fi = rintf(t);
    float f  = t - fi;
    float p  = 0.00133335581464284f;
    p = fmaf(p, f, 0.00961812910762848f);
    p = fmaf(p, f, 0.05550410866482158f);
    p = fmaf(p, f, 0.24022650695910072f);
    p = fmaf(p, f, 0.69314718055994531f);
    p = fmaf(p, f, 1.0f);
    int ei = (int)fi;
    float sc = __int_as_float((ei + 127) << 23);
    return p * sc;
}

// ---------------------------------------------------------------------------
// Warp-MMA NT GEMM, bf16x3: C = scale * A[M,K] @ Bt[N,K]^T.
// splitOut=0 -> fp32 C; splitOut=1 -> bf16 hi/lo (Chi, Clo).
// CTA 128x128, K-chunk 32, 256 threads = 8 warps (4M x 2N).
// ---------------------------------------------------------------------------
#define PAD_ 40

__global__ void __launch_bounds__(256) hgemm_nt(
    const __nv_bfloat16* __restrict__ Ahi, const __nv_bfloat16* __restrict__ Alo,
    const __nv_bfloat16* __restrict__ Bhi, const __nv_bfloat16* __restrict__ Blo,
    float* __restrict__ C, __nv_bfloat16* __restrict__ Chi, __nv_bfloat16* __restrict__ Clo,
    int M, int N, int K, int lda, int ldb, int ldc, float scale, int splitOut) {
    __shared__ __align__(16) __nv_bfloat16 sAh[128][PAD_];
    __shared__ __align__(16) __nv_bfloat16 sAl[128][PAD_];
    __shared__ __align__(16) __nv_bfloat16 sBh[128][PAD_];
    __shared__ __align__(16) __nv_bfloat16 sBl[128][PAD_];

    const int tid = threadIdx.x;
    const int wid = tid >> 5, lane = tid & 31;
    const int wm = wid >> 1, wn = wid & 1;
    const int bm = blockIdx.y * 128, bn = blockIdx.x * 128;

    float acc[2][8][4];
    #pragma unroll
    for (int i = 0; i < 2; i++)
        #pragma unroll
        for (int j = 0; j < 8; j++)
            #pragma unroll
            for (int r = 0; r < 4; r++) acc[i][j][r] = 0.0f;

    const int a_row = (lane & 15);
    const int a_col8 = (lane >> 4) * 8;
    const int b_rowoff = (lane & 7) + ((lane >> 4) << 3);
    const int b_col8 = ((lane >> 3) & 1) * 8;

    for (int k0 = 0; k0 < K; k0 += 32) {
        #pragma unroll
        for (int i = 0; i < 2; i++) {
            const int idx = tid + i * 256;
            const int row = idx >> 2;
            const int seg = (idx & 3) * 8;
            *(uint4*)&sAh[row][seg] = *(const uint4*)(Ahi + (size_t)(bm + row) * lda + k0 + seg);
            *(uint4*)&sAl[row][seg] = *(const uint4*)(Alo + (size_t)(bm + row) * lda + k0 + seg);
            *(uint4*)&sBh[row][seg] = *(const uint4*)(Bhi + (size_t)(bn + row) * ldb + k0 + seg);
            *(uint4*)&sBl[row][seg] = *(const uint4*)(Blo + (size_t)(bn + row) * ldb + k0 + seg);
        }
        __syncthreads();

        #pragma unroll
        for (int ks = 0; ks < 2; ks++) {
            const int kc = ks * 16;
            uint32_t ah[2][4], al[2][4];
            #pragma unroll
            for (int mf = 0; mf < 2; mf++) {
                ldsm4(sptr(&sAh[wm * 32 + mf * 16 + a_row][kc + a_col8]),
                      ah[mf][0], ah[mf][1], ah[mf][2], ah[mf][3]);
                ldsm4(sptr(&sAl[wm * 32 + mf * 16 + a_row][kc + a_col8]),
                      al[mf][0], al[mf][1], al[mf][2], al[mf][3]);
            }
            #pragma unroll
            for (int nf2 = 0; nf2 < 4; nf2++) {
                const int brow = wn * 64 + nf2 * 16 + b_rowoff;
                uint32_t bh[4], bl[4];
                ldsm4(sptr(&sBh[brow][kc + b_col8]), bh[0], bh[1], bh[2], bh[3]);
                ldsm4(sptr(&sBl[brow][kc + b_col8]), bl[0], bl[1], bl[2], bl[3]);
                #pragma unroll
                for (int mf = 0; mf < 2; mf++) {
                    #pragma unroll
                    for (int f = 0; f < 2; f++) {
                        float* d = acc[mf][nf2 * 2 + f];
                        mma16816(d, ah[mf], bh + 2 * f);
                        mma16816(d, ah[mf], bl + 2 * f);
                        mma16816(d, al[mf], bh + 2 * f);
                    }
                }
            }
        }
        __syncthreads();
    }

    const int g = lane >> 2, t2 = (lane & 3) * 2;
    #pragma unroll
    for (int mf = 0; mf < 2; mf++) {
        #pragma unroll
        for (int nf = 0; nf < 8; nf++) {
            const int row = bm + wm * 32 + mf * 16 + g;
            const int col = bn + wn * 64 + nf * 8 + t2;
            float* d = acc[mf][nf];
            if (!splitOut) {
                *(float2*)(C + (size_t)row * ldc + col) = make_float2(d[0] * scale, d[1] * scale);
                *(float2*)(C + (size_t)(row + 8) * ldc + col) = make_float2(d[2] * scale, d[3] * scale);
            } else {
                uint32_t hp, lp;
                split_pack(d[0] * scale, d[1] * scale, hp, lp);
                *(uint32_t*)(Chi + (size_t)row * ldc + col) = hp;
                *(uint32_t*)(Clo + (size_t)row * ldc + col) = lp;
                split_pack(d[2] * scale, d[3] * scale, hp, lp);
                *(uint32_t*)(Chi + (size_t)(row + 8) * ldc + col) = hp;
                *(uint32_t*)(Clo + (size_t)(row + 8) * ldc + col) = lp;
            }
        }
    }
}

// ---------------------------------------------------------------------------
// Attention pass 1: Z[k] = sum_q exp(<k,q>/32).  Writes rZ = 1/Z.
// Grid (16 k-tiles, 32 heads). Block 256 = 8 warps (4M x 2N) over S[128k][128q].
// K tile persistent in smem; loop 16 q-tiles.
// ---------------------------------------------------------------------------
#define TP_ 72          // tile pitch in bf16 (144B rows, conflict-free)
#define TB_ (128 * TP_ * 2)   // bytes per bf16 tile

__global__ void __launch_bounds__(256) attn_stats(
    const __nv_bfloat16* __restrict__ Khi, const __nv_bfloat16* __restrict__ Klo,
    const __nv_bfloat16* __restrict__ Qhi, const __nv_bfloat16* __restrict__ Qlo,
    float* __restrict__ rZ) {
    extern __shared__ char smem[];
    __nv_bfloat16* sKh = (__nv_bfloat16*)(smem);
    __nv_bfloat16* sKl = (__nv_bfloat16*)(smem + TB_);
    __nv_bfloat16* sQh = (__nv_bfloat16*)(smem + 2 * TB_);
    __nv_bfloat16* sQl = (__nv_bfloat16*)(smem + 3 * TB_);
    float* sZ = (float*)(smem + 4 * TB_);

    const int hh = blockIdx.y;
    const int b = hh >> 4, h = hh & 15;
    const size_t off = (size_t)b * S_ * L_ + (size_t)h * DH_;
    const int kt = blockIdx.x * 128;

    const int tid = threadIdx.x;
    const int wid = tid >> 5, lane = tid & 31;
    const int wm = wid >> 1, wn = wid & 1;
    const int a_row = (lane & 15);
    const int a_col8 = (lane >> 4) * 8;
    const int b_rowoff = (lane & 7) + ((lane >> 4) << 3);
    const int b_col8 = ((lane >> 3) & 1) * 8;
    const int g = lane >> 2;

    // load K tile (128 x 64 hi/lo)
    #pragma unroll
    for (int i = 0; i < 4; i++) {
        int idx = tid + i * 256;
        int row = idx >> 3;
        int seg = (idx & 7) * 8;
        *(uint4*)&sKh[row * TP_ + seg] = *(const uint4*)(Khi + off + (size_t)(kt + row) * L_ + seg);
        *(uint4*)&sKl[row * TP_ + seg] = *(const uint4*)(Klo + off + (size_t)(kt + row) * L_ + seg);
    }

    float zp[2][2] = {};
    for (int qt = 0; qt < S_; qt += 128) {
        __syncthreads();
        #pragma unroll
        for (int i = 0; i < 4; i++) {
            int idx = tid + i * 256;
            int row = idx >> 3;
            int seg = (idx & 7) * 8;
            *(uint4*)&sQh[row * TP_ + seg] = *(const uint4*)(Qhi + off + (size_t)(qt + row) * L_ + seg);
            *(uint4*)&sQl[row * TP_ + seg] = *(const uint4*)(Qlo + off + (size_t)(qt + row) * L_ + seg);
        }
        __syncthreads();

        float acc[2][8][4];
        #pragma unroll
        for (int i = 0; i < 2; i++)
            #pragma unroll
            for (int j = 0; j < 8; j++)
                #pragma unroll
                for (int r = 0; r < 4; r++) acc[i][j][r] = 0.0f;

        #pragma unroll
        for (int ks = 0; ks < 4; ks++) {
            const int kc = ks * 16;
            uint32_t ah[2][4], al[2][4];
            #pragma unroll
            for (int mf = 0; mf < 2; mf++) {
                ldsm4(sptr(&sKh[(wm * 32 + mf * 16 + a_row) * TP_ + kc + a_col8]),
                      ah[mf][0], ah[mf][1], ah[mf][2], ah[mf][3]);
                ldsm4(sptr(&sKl[(wm * 32 + mf * 16 + a_row) * TP_ + kc + a_col8]),
                      al[mf][0], al[mf][1], al[mf][2], al[mf][3]);
            }
            #pragma unroll
            for (int nf2 = 0; nf2 < 4; nf2++) {
                const int brow = wn * 64 + nf2 * 16 + b_rowoff;
                uint32_t bh[4], bl[4];
                ldsm4(sptr(&sQh[brow * TP_ + kc + b_col8]), bh[0], bh[1], bh[2], bh[3]);
                ldsm4(sptr(&sQl[brow * TP_ + kc + b_col8]), bl[0], bl[1], bl[2], bl[3]);
                #pragma unroll
                for (int mf = 0; mf < 2; mf++) {
                    #pragma unroll
                    for (int f = 0; f < 2; f++) {
                        float* d = acc[mf][nf2 * 2 + f];
                        mma16816(d, ah[mf], bh + 2 * f);
                        mma16816(d, ah[mf], bl + 2 * f);
                        mma16816(d, al[mf], bh + 2 * f);
                    }
                }
            }
        }

        // accumulate exp sums per k-row
        #pragma unroll
        for (int mf = 0; mf < 2; mf++)
            #pragma unroll
            for (int nf = 0; nf < 8; nf++) {
                float* d = acc[mf][nf];
                zp[mf][0] += fast_exp(d[0] * 0.03125f) + fast_exp(d[1] * 0.03125f);
                zp[mf][1] += fast_exp(d[2] * 0.03125f) + fast_exp(d[3] * 0.03125f);
            }
    }

    // reduce across the 4 column lanes of each row group
    #pragma unroll
    for (int mf = 0; mf < 2; mf++)
        #pragma unroll
        for (int r = 0; r < 2; r++) {
            zp[mf][r] += __shfl_xor_sync(0xffffffffu, zp[mf][r], 1);
            zp[mf][r] += __shfl_xor_sync(0xffffffffu, zp[mf][r], 2);
        }

    if (tid < 128) sZ[tid] = 0.0f;
    __syncthreads();
    if ((lane & 3) == 0) {
        #pragma unroll
        for (int mf = 0; mf < 2; mf++) {
            int r0 = wm * 32 + mf * 16 + g;
            atomicAdd(&sZ[r0], zp[mf][0]);
            atomicAdd(&sZ[r0 + 8], zp[mf][1]);
        }
    }
    __syncthreads();
    if (tid < 128)
        rZ[(size_t)hh * S_ + kt + tid] = 1.0f / sZ[tid];
}

// ---------------------------------------------------------------------------
// Attention pass 2: out[q,d] = sum_k (exp(<k,q>/32) * rZ[k]) * V[k,d].
// Grid (16 q-tiles, 32 heads). Block 256 = 8 warps, each 16 q x 64 d.
// S' = Q·K^T recomputed in registers; P built in-register (flash acc->A trick).
// Writes ao split bf16 hi/lo.
// ---------------------------------------------------------------------------
__global__ void __launch_bounds__(256) attn_av(
    const __nv_bfloat16* __restrict__ Qhi, const __nv_bfloat16* __restrict__ Qlo,
    const __nv_bfloat16* __restrict__ Khi, const __nv_bfloat16* __restrict__ Klo,
    const __nv_bfloat16* __restrict__ Vhi, const __nv_bfloat16* __restrict__ Vlo,
    const float* __restrict__ rZ,
    __nv_bfloat16* __restrict__ Ohi, __nv_bfloat16* __restrict__ Olo) {
    extern __shared__ char smem[];
    __nv_bfloat16* sQh = (__nv_bfloat16*)(smem);
    __nv_bfloat16* sQl = (__nv_bfloat16*)(smem + TB_);
    __nv_bfloat16* sKh = (__nv_bfloat16*)(smem + 2 * TB_);
    __nv_bfloat16* sKl = (__nv_bfloat16*)(smem + 3 * TB_);
    __nv_bfloat16* sVh = (__nv_bfloat16*)(smem + 4 * TB_);
    __nv_bfloat16* sVl = (__nv_bfloat16*)(smem + 5 * TB_);
    float* srz = (float*)(smem + 6 * TB_);

    const int hh = blockIdx.y;
    const int b = hh >> 4, h = hh & 15;
    const size_t off = (size_t)b * S_ * L_ + (size_t)h * DH_;
    const int qt = blockIdx.x * 128;

    const int tid = threadIdx.x;
    const int wid = tid >> 5, lane = tid & 31;
    const int g = lane >> 2, t2 = (lane & 3) * 2;
    const int a_row = (lane & 15);
    const int a_col8 = (lane >> 4) * 8;
    const int b_rowoff = (lane & 7) + ((lane >> 4) << 3);
    const int b_col8 = ((lane >> 3) & 1) * 8;
    const int v_k = (lane & 7) + (((lane >> 3) & 1) << 3);   // trans ldsm row
    const int v_d = (lane >> 4) * 8;

    // load Q tile once
    #pragma unroll
    for (int i = 0; i < 4; i++) {
        int idx = tid + i * 256;
        int row = idx >> 3;
        int seg = (idx & 7) * 8;
        *(uint4*)&sQh[row * TP_ + seg] = *(const uint4*)(Qhi + off + (size_t)(qt + row) * L_ + seg);
        *(uint4*)&sQl[row * TP_ + seg] = *(const uint4*)(Qlo + off + (size_t)(qt + row) * L_ + seg);
    }

    float avacc[8][4];
    #pragma unroll
    for (int j = 0; j < 8; j++)
        #pragma unroll
        for (int r = 0; r < 4; r++) avacc[j][r] = 0.0f;

    const int wq = wid * 16;

    for (int kt = 0; kt < S_; kt += 128) {
        __syncthreads();
        #pragma unroll
        for (int i = 0; i < 4; i++) {
            int idx = tid + i * 256;
            int row = idx >> 3;
            int seg = (idx & 7) * 8;
            *(uint4*)&sKh[row * TP_ + seg] = *(const uint4*)(Khi + off + (size_t)(kt + row) * L_ + seg);
            *(uint4*)&sKl[row * TP_ + seg] = *(const uint4*)(Klo + off + (size_t)(kt + row) * L_ + seg);
            *(uint4*)&sVh[row * TP_ + seg] = *(const uint4*)(Vhi + off + (size_t)(kt + row) * L_ + seg);
            *(uint4*)&sVl[row * TP_ + seg] = *(const uint4*)(Vlo + off + (size_t)(kt + row) * L_ + seg);
        }
        if (tid < 128) srz[tid] = rZ[(size_t)hh * S_ + kt + tid];
        __syncthreads();

        #pragma unroll
        for (int khalf = 0; khalf < 2; khalf++) {
            // S' tile: 16 q rows x 64 k cols for this warp
            float sacc[8][4];
            #pragma unroll
            for (int j = 0; j < 8; j++)
                #pragma unroll
                for (int r = 0; r < 4; r++) sacc[j][r] = 0.0f;

            #pragma unroll
            for (int ks = 0; ks < 4; ks++) {
                const int kc = ks * 16;
                uint32_t ah[4], al[4];
                ldsm4(sptr(&sQh[(wq + a_row) * TP_ + kc + a_col8]), ah[0], ah[1], ah[2], ah[3]);
                ldsm4(sptr(&sQl[(wq + a_row) * TP_ + kc + a_col8]), al[0], al[1], al[2], al[3]);
                #pragma unroll
                for (int nf2 = 0; nf2 < 4; nf2++) {
                    const int brow = khalf * 64 + nf2 * 16 + b_rowoff;
                    uint32_t bh[4], bl[4];
                    ldsm4(sptr(&sKh[brow * TP_ + kc + b_col8]), bh[0], bh[1], bh[2], bh[3]);
                    ldsm4(sptr(&sKl[brow * TP_ + kc + b_col8]), bl[0], bl[1], bl[2], bl[3]);
                    #pragma unroll
                    for (int f = 0; f < 2; f++) {
                        float* d = sacc[nf2 * 2 + f];
                        mma16816(d, ah, bh + 2 * f);
                        mma16816(d, ah, bl + 2 * f);
                        mma16816(d, al, bh + 2 * f);
                    }
                }
            }

            // p = exp(s/32) * rZ[k]; build A-fragments (hi/lo) per k16 chunk
            uint32_t pah[4][4], pal[4][4];
            #pragma unroll
            for (int j = 0; j < 4; j++) {          // k16 chunk = nf 2j, 2j+1
                #pragma unroll
                for (int e = 0; e < 2; e++) {      // e=0 -> nf 2j (k +0..7), e=1 -> nf 2j+1 (k +8..15)
                    float* d = sacc[2 * j + e];
                    const int col = khalf * 64 + j * 16 + e * 8 + t2;
                    float r0 = srz[col], r1 = srz[col + 1];
                    float p0 = fast_exp(d[0] * 0.03125f) * r0;
                    float p1 = fast_exp(d[1] * 0.03125f) * r1;
                    float p2 = fast_exp(d[2] * 0.03125f) * r0;
                    float p3 = fast_exp(d[3] * 0.03125f) * r1;
                    split_pack(p0, p1, pah[j][2 * e + 0], pal[j][2 * e + 0]);   // row g
                    split_pack(p2, p3, pah[j][2 * e + 1], pal[j][2 * e + 1]);   // row g+8
                }
            }

            // AV: accumulate over the 4 k16 chunks of this half
            #pragma unroll
            for (int j = 0; j < 4; j++) {
                const int kbase = khalf * 64 + j * 16;
                #pragma unroll
                for (int nb = 0; nb < 4; nb++) {   // d groups of 16
                    uint32_t bvh[4], bvl[4];
                    ldsm4t(sptr(&sVh[(kbase + v_k) * TP_ + nb * 16 + v_d]),
                           bvh[0], bvh[1], bvh[2], bvh[3]);
                    ldsm4t(sptr(&sVl[(kbase + v_k) * TP_ + nb * 16 + v_d]),
                           bvl[0], bvl[1], bvl[2], bvl[3]);
                    #pragma unroll
                    for (int f = 0; f < 2; f++) {
                        float* d = avacc[nb * 2 + f];
                        mma16816(d, pah[j], bvh + 2 * f);
                        mma16816(d, pah[j], bvl + 2 * f);
                        mma16816(d, pal[j], bvh + 2 * f);
                    }
                }
            }
        }
    }

    // epilogue: write ao split bf16
    #pragma unroll
    for (int nf = 0; nf < 8; nf++) {
        const int row = qt + wq + g;
        const int col = nf * 8 + t2;
        float* d = avacc[nf];
        uint32_t hp, lp;
        split_pack(d[0], d[1], hp, lp);
        *(uint32_t*)(Ohi + off + (size_t)row * L_ + col) = hp;
        *(uint32_t*)(Olo + off + (size_t)row * L_ + col) = lp;
        split_pack(d[2], d[3], hp, lp);
        *(uint32_t*)(Ohi + off + (size_t)(row + 8) * L_ + col) = hp;
        *(uint32_t*)(Olo + off + (size_t)(row + 8) * L_ + col) = lp;
    }
}

// ---------------------------------------------------------------------------
// fp32 -> bf16 hi/lo split (element-wise)
// ---------------------------------------------------------------------------
__global__ void __launch_bounds__(256) split_kernel(const float* __restrict__ A,
                                                    __nv_bfloat16* __restrict__ Hi,
                                                    __nv_bfloat16* __restrict__ Lo) {
    size_t i = ((size_t)blockIdx.x * 256 + threadIdx.x) * 4;
    float4 a = *(const float4*)(A + i);
    __nv_bfloat16 h0, l0, h1, l1, h2, l2, h3, l3;
    split1(a.x, h0, l0); split1(a.y, h1, l1);
    split1(a.z, h2, l2); split1(a.w, h3, l3);
    __nv_bfloat162* hp = (__nv_bfloat162*)(Hi + i);
    __nv_bfloat162* lp = (__nv_bfloat162*)(Lo + i);
    hp[0] = __nv_bfloat162(h0, h1); hp[1] = __nv_bfloat162(h2, h3);
    lp[0] = __nv_bfloat162(l0, l1); lp[1] = __nv_bfloat162(l2, l3);
}

// W[K,N] -> Wt hi/lo [N,K]
__global__ void __launch_bounds__(256) transpose_split(const float* __restrict__ W,
                                                       __nv_bfloat16* __restrict__ Th,
                                                       __nv_bfloat16* __restrict__ Tl,
                                                       int K, int N) {
    __shared__ float t[32][33];
    const int k0 = blockIdx.y * 32, n0 = blockIdx.x * 32;
    const int tx = threadIdx.x & 31, ty = threadIdx.x >> 5;
    #pragma unroll
    for (int j = 0; j < 4; j++) {
        int row = ty + j * 8;
        t[row][tx] = W[(size_t)(k0 + row) * N + n0 + tx];
    }
    __syncthreads();
    #pragma unroll
    for (int j = 0; j < 4; j++) {
        int row = ty + j * 8;
        float v = t[tx][row];
        __nv_bfloat16 h, l; split1(v, h, l);
        size_t o = (size_t)(n0 + row) * K + k0 + tx;
        Th[o] = h; Tl[o] = l;
    }
}

// ---------------------------------------------------------------------------
// Row L2 normalize -> bf16 hi/lo split
// ---------------------------------------------------------------------------
__global__ void __launch_bounds__(256) l2norm_split(const float* __restrict__ Z,
                                                    __nv_bfloat16* __restrict__ Hi,
                                                    __nv_bfloat16* __restrict__ Lo) {
    __shared__ float shs[8];
    const size_t row = blockIdx.x;
    const float* p = Z + row * (size_t)D_;
    const int tid = threadIdx.x;
    const int lane = tid & 31, wid = tid >> 5;
    float4 v = *(const float4*)(p + tid * 4);
    float ss = v.x * v.x + v.y * v.y + v.z * v.z + v.w * v.w;
    #pragma unroll
    for (int o = 16; o; o >>= 1) ss += __shfl_xor_sync(0xffffffffu, ss, o);
    if (lane == 0) shs[wid] = ss;
    __syncthreads();
    ss = shs[0];
    #pragma unroll
    for (int i = 1; i < 8; i++) ss += shs[i];
    const float sc = 1.0f / fmaxf(sqrtf(ss), 1e-12f);
    float y0 = v.x * sc, y1 = v.y * sc, y2 = v.z * sc, y3 = v.w * sc;
    __nv_bfloat16 h0, l0, h1, l1, h2, l2, h3, l3;
    split1(y0, h0, l0); split1(y1, h1, l1);
    split1(y2, h2, l2); split1(y3, h3, l3);
    size_t o = row * (size_t)D_ + tid * 4;
    __nv_bfloat162* hp = (__nv_bfloat162*)(Hi + o);
    __nv_bfloat162* lp = (__nv_bfloat162*)(Lo + o);
    hp[0] = __nv_bfloat162(h0, h1); hp[1] = __nv_bfloat162(h2, h3);
    lp[0] = __nv_bfloat162(l0, l1); lp[1] = __nv_bfloat162(l2, l3);
}

// ---------------------------------------------------------------------------
// Row L2 normalize + exact GELU, writes to output
// ---------------------------------------------------------------------------
__global__ void __launch_bounds__(256) l2norm_gelu(const float* __restrict__ Z,
                                                   float* __restrict__ O) {
    __shared__ float shs[8];
    const size_t row = blockIdx.x;
    const float* p = Z + row * (size_t)D_;
    float* q = O + row * (size_t)D_;
    const int tid = threadIdx.x;
    const int lane = tid & 31, wid = tid >> 5;
    float4 v = *(const float4*)(p + tid * 4);
    float ss = v.x * v.x + v.y * v.y + v.z * v.z + v.w * v.w;
    #pragma unroll
    for (int o = 16; o; o >>= 1) ss += __shfl_xor_sync(0xffffffffu, ss, o);
    if (lane == 0) shs[wid] = ss;
    __syncthreads();
    ss = shs[0];
    #pragma unroll
    for (int i = 1; i < 8; i++) ss += shs[i];
    const float sc = 1.0f / fmaxf(sqrtf(ss), 1e-12f);
    float y0 = v.x * sc, y1 = v.y * sc, y2 = v.z * sc, y3 = v.w * sc;
    const float inv_sqrt2 = 0.70710678118654752f;
    float4 g;
    g.x = 0.5f * y0 * (1.0f + erff(y0 * inv_sqrt2));
    g.y = 0.5f * y1 * (1.0f + erff(y1 * inv_sqrt2));
    g.z = 0.5f * y2 * (1.0f + erff(y2 * inv_sqrt2));
    g.w = 0.5f * y3 * (1.0f + erff(y3 * inv_sqrt2));
    *(float4*)(q + tid * 4) = g;
}

// ---------------------------------------------------------------------------
// Launch
// ---------------------------------------------------------------------------
extern "C" void kernel_launch(void* const* d_in, const int* in_sizes, int n_in,
                              void* d_out, int out_size) {
    (void)in_sizes; (void)n_in; (void)out_size;
    const float* x   = (const float*)d_in[0];
    const float* Wq  = (const float*)d_in[1];
    const float* Wk  = (const float*)d_in[2];
    const float* Wv  = (const float*)d_in[3];
    const float* Wo  = (const float*)d_in[4];
    const float* Wff = (const float*)d_in[5];

    float *z1, *z2, *rz;
    cudaGetSymbolAddress((void**)&z1, g_z1);
    cudaGetSymbolAddress((void**)&z2, g_z2);
    cudaGetSymbolAddress((void**)&rz, g_rz);

    __nv_bfloat16 *xhi, *xlo, *qhi, *qlo, *khi, *klo, *vhi, *vlo,
                  *aohi, *aolo, *z1hi, *z1lo, *wth, *wtl;
    cudaGetSymbolAddress((void**)&xhi,  g_xhi);
    cudaGetSymbolAddress((void**)&xlo,  g_xlo);
    cudaGetSymbolAddress((void**)&qhi,  g_qhi);
    cudaGetSymbolAddress((void**)&qlo,  g_qlo);
    cudaGetSymbolAddress((void**)&khi,  g_khi);
    cudaGetSymbolAddress((void**)&klo,  g_klo);
    cudaGetSymbolAddress((void**)&vhi,  g_vhi);
    cudaGetSymbolAddress((void**)&vlo,  g_vlo);
    cudaGetSymbolAddress((void**)&aohi, g_aohi);
    cudaGetSymbolAddress((void**)&aolo, g_aolo);
    cudaGetSymbolAddress((void**)&z1hi, g_z1hi);
    cudaGetSymbolAddress((void**)&z1lo, g_z1lo);
    cudaGetSymbolAddress((void**)&wth,  g_wt_hi);
    cudaGetSymbolAddress((void**)&wtl,  g_wt_lo);
    const size_t WSTR = (size_t)D_ * L_;

    const int SMEM1 = 4 * TB_ + 512;
    const int SMEM2 = 6 * TB_ + 512;
    cudaFuncSetAttribute(attn_stats, cudaFuncAttributeMaxDynamicSharedMemorySize, SMEM1);
    cudaFuncSetAttribute(attn_av,    cudaFuncAttributeMaxDynamicSharedMemorySize, SMEM2);

    const dim3 blk(256);
    const dim3 gT(L_ / 32, D_ / 32);

    split_kernel<<<(M4_ * D_) / 1024, blk>>>(x, xhi, xlo);
    transpose_split<<<gT, blk>>>(Wq,  wth + 0 * WSTR, wtl + 0 * WSTR, D_, L_);
    transpose_split<<<gT, blk>>>(Wk,  wth + 1 * WSTR, wtl + 1 * WSTR, D_, L_);
    transpose_split<<<gT, blk>>>(Wv,  wth + 2 * WSTR, wtl + 2 * WSTR, D_, L_);
    transpose_split<<<gT, blk>>>(Wo,  wth + 3 * WSTR, wtl + 3 * WSTR, L_, D_);
    transpose_split<<<gT, blk>>>(Wff, wth + 4 * WSTR, wtl + 4 * WSTR, D_, D_);

    const dim3 gG(L_ / 128, M4_ / 128, 1);

    // QKV projections, emitting bf16 hi/lo directly
    hgemm_nt<<<gG, blk>>>(xhi, xlo, wth + 0 * WSTR, wtl + 0 * WSTR, z1, qhi, qlo,
                          M4_, L_, D_, D_, D_, L_, 1.0f, 1);
    hgemm_nt<<<gG, blk>>>(xhi, xlo, wth + 1 * WSTR, wtl + 1 * WSTR, z1, khi, klo,
                          M4_, L_, D_, D_, D_, L_, 1.0f, 1);
    hgemm_nt<<<gG, blk>>>(xhi, xlo, wth + 2 * WSTR, wtl + 2 * WSTR, z1, vhi, vlo,
                          M4_, L_, D_, D_, D_, L_, 1.0f, 1);

    // fused attention (two-pass, no materialized scores)
    attn_stats<<<dim3(16, 32), blk, SMEM1>>>(khi, klo, qhi, qlo, rz);
    attn_av<<<dim3(16, 32), blk, SMEM2>>>(qhi, qlo, khi, klo, vhi, vlo, rz, aohi, aolo);

    // output projection
    hgemm_nt<<<gG, blk>>>(aohi, aolo, wth + 3 * WSTR, wtl + 3 * WSTR, z1,
                          (__nv_bfloat16*)0, (__nv_bfloat16*)0,
                          M4_, D_, L_, L_, L_, D_, 1.0f, 0);

    // FFN
    l2norm_split<<<M4_, blk>>>(z1, z1hi, z1lo);
    hgemm_nt<<<gG, blk>>>(z1hi, z1lo, wth + 4 * WSTR, wtl + 4 * WSTR, z2,
                          (__nv_bfloat16*)0, (__nv_bfloat16*)0,
                          M4_, D_, D_, D_, D_, D_, 1.0f, 0);
    l2norm_gelu<<<M4_, blk>>>(z2, (float*)d_out);
}

// round 13
// speedup vs baseline: 2.3695x; 1.2646x over previous
#include <cuda_runtime.h>
#include <cuda_bf16.h>
#include <math.h>
#include <stdint.h>

// Problem dims (fixed by the dataset)
#define B_  2
#define S_  2048
#define D_  1024
#define L_  1024
#define H_  16
#define DH_ 64
#define BH_ (B_ * H_)          // 32
#define M4_ (B_ * S_)          // 4096

// ---------------------------------------------------------------------------
// Scratch
// ---------------------------------------------------------------------------
__device__ float g_z1[(size_t)M4_ * D_];
__device__ float g_z2[(size_t)M4_ * D_];
__device__ float g_rz[(size_t)BH_ * S_];            // 1/Z per (head, k)

__device__ unsigned short g_xhi[(size_t)M4_ * D_];
__device__ unsigned short g_xlo[(size_t)M4_ * D_];
__device__ unsigned short g_qhi[(size_t)M4_ * L_];
__device__ unsigned short g_qlo[(size_t)M4_ * L_];
__device__ unsigned short g_khi[(size_t)M4_ * L_];
__device__ unsigned short g_klo[(size_t)M4_ * L_];
__device__ unsigned short g_vhi[(size_t)M4_ * L_];
__device__ unsigned short g_vlo[(size_t)M4_ * L_];
__device__ unsigned short g_aohi[(size_t)M4_ * L_];
__device__ unsigned short g_aolo[(size_t)M4_ * L_];
__device__ unsigned short g_z1hi[(size_t)M4_ * D_];
__device__ unsigned short g_z1lo[(size_t)M4_ * D_];
__device__ unsigned short g_wt_hi[5][(size_t)D_ * L_];
__device__ unsigned short g_wt_lo[5][(size_t)D_ * L_];

// ---------------------------------------------------------------------------
// helpers
// ---------------------------------------------------------------------------
__device__ __forceinline__ uint32_t sptr(const void* p) {
    return (uint32_t)__cvta_generic_to_shared(p);
}
__device__ __forceinline__ void cpa16(uint32_t saddr, const void* g) {
    asm volatile("cp.async.cg.shared.global [%0], [%1], 16;" :: "r"(saddr), "l"(g));
}
__device__ __forceinline__ void cpa_commit() {
    asm volatile("cp.async.commit_group;" ::: "memory");
}
__device__ __forceinline__ void cpa_wait1() {
    asm volatile("cp.async.wait_group 1;" ::: "memory");
}
__device__ __forceinline__ void ldsm4(uint32_t a, uint32_t& r0, uint32_t& r1,
                                      uint32_t& r2, uint32_t& r3) {
    asm volatile("ldmatrix.sync.aligned.m8n8.x4.shared.b16 {%0,%1,%2,%3}, [%4];"
                 : "=r"(r0), "=r"(r1), "=r"(r2), "=r"(r3) : "r"(a));
}
__device__ __forceinline__ void ldsm4t(uint32_t a, uint32_t& r0, uint32_t& r1,
                                       uint32_t& r2, uint32_t& r3) {
    asm volatile("ldmatrix.sync.aligned.m8n8.x4.trans.shared.b16 {%0,%1,%2,%3}, [%4];"
                 : "=r"(r0), "=r"(r1), "=r"(r2), "=r"(r3) : "r"(a));
}
__device__ __forceinline__ void mma16816(float* d, const uint32_t* a, const uint32_t* b) {
    asm volatile(
        "mma.sync.aligned.m16n8k16.row.col.f32.bf16.bf16.f32 "
        "{%0,%1,%2,%3}, {%4,%5,%6,%7}, {%8,%9}, {%0,%1,%2,%3};"
        : "+f"(d[0]), "+f"(d[1]), "+f"(d[2]), "+f"(d[3])
        : "r"(a[0]), "r"(a[1]), "r"(a[2]), "r"(a[3]), "r"(b[0]), "r"(b[1]));
}
__device__ __forceinline__ void split1(float a, __nv_bfloat16& h, __nv_bfloat16& l) {
    h = __float2bfloat16(a);
    l = __float2bfloat16(a - __bfloat162float(h));
}
__device__ __forceinline__ void split_pack(float x, float y, uint32_t& hi, uint32_t& lo) {
    __nv_bfloat16 hx, lx, hy, ly;
    split1(x, hx, lx); split1(y, hy, ly);
    __nv_bfloat162 Hp(hx, hy), Lp(lx, ly);
    hi = *(uint32_t*)&Hp; lo = *(uint32_t*)&Lp;
}
// exp(s/32) via MUFU: 1 mul + 1 ex2 issue-slot (vs ~11 for poly exp)
#define EXPC_ (1.4426950408889634f / 32.0f)
__device__ __forceinline__ float fexp32(float s) {
    float y;
    asm("ex2.approx.f32 %0, %1;" : "=f"(y) : "f"(s * EXPC_));
    return y;
}

// ---------------------------------------------------------------------------
// Warp-MMA NT GEMM, bf16x3, 2-stage cp.async double buffer.
// C = scale * A[M,K] @ Bt[N,K]^T; splitOut=1 -> bf16 hi/lo output.
// CTA 128x128, K-chunk 32, 256 threads = 8 warps (4M x 2N).
// ---------------------------------------------------------------------------
#define PAD_ 40
#define TBG_ (128 * PAD_ * 2)      // bytes per smem tile
#define GSMEM_ (8 * TBG_)          // 2 stages x 4 tiles = 80 KB

__global__ void __launch_bounds__(256) hgemm_nt(
    const __nv_bfloat16* __restrict__ Ahi, const __nv_bfloat16* __restrict__ Alo,
    const __nv_bfloat16* __restrict__ Bhi, const __nv_bfloat16* __restrict__ Blo,
    float* __restrict__ C, __nv_bfloat16* __restrict__ Chi, __nv_bfloat16* __restrict__ Clo,
    int M, int N, int K, int lda, int ldb, int ldc, float scale, int splitOut) {
    extern __shared__ char dsm[];

    const int tid = threadIdx.x;
    const int wid = tid >> 5, lane = tid & 31;
    const int wm = wid >> 1, wn = wid & 1;
    const int bm = blockIdx.y * 128, bn = blockIdx.x * 128;

    // per-thread load coordinates (2 uint4 per tile per thread)
    const int r0_ = tid >> 1, s0_ = (tid & 1) * 8;            // idx = tid
    const int r1_ = (tid + 256) >> 1, s1_ = s0_;              // idx = tid + 256
    // (idx>>2 with i*256: row=idx>>2, seg=(idx&3)*8; 512 uint4 per tile)
    // use original mapping:
    const int la_row0 = tid >> 2, la_seg0 = (tid & 3) * 8;
    const int la_row1 = (tid + 256) >> 2, la_seg1 = ((tid + 256) & 3) * 8;
    (void)r0_; (void)s0_; (void)r1_; (void)s1_;

    float acc[2][8][4];
    #pragma unroll
    for (int i = 0; i < 2; i++)
        #pragma unroll
        for (int j = 0; j < 8; j++)
            #pragma unroll
            for (int r = 0; r < 4; r++) acc[i][j][r] = 0.0f;

    const int a_row = (lane & 15);
    const int a_col8 = (lane >> 4) * 8;
    const int b_rowoff = (lane & 7) + ((lane >> 4) << 3);
    const int b_col8 = ((lane >> 3) & 1) * 8;

    const int nch = K >> 5;

    // tile base pointers: stage s, tile t (0=Ah,1=Al,2=Bh,3=Bl)
    auto tileb = [&](int s, int t) -> __nv_bfloat16* {
        return (__nv_bfloat16*)(dsm + (size_t)(s * 4 + t) * TBG_);
    };
    auto ldchunk = [&](int c, int s) {
        const int k0 = c << 5;
        __nv_bfloat16* ah = tileb(s, 0);
        __nv_bfloat16* al = tileb(s, 1);
        __nv_bfloat16* bh = tileb(s, 2);
        __nv_bfloat16* bl = tileb(s, 3);
        cpa16(sptr(ah + la_row0 * PAD_ + la_seg0), Ahi + (size_t)(bm + la_row0) * lda + k0 + la_seg0);
        cpa16(sptr(ah + la_row1 * PAD_ + la_seg1), Ahi + (size_t)(bm + la_row1) * lda + k0 + la_seg1);
        cpa16(sptr(al + la_row0 * PAD_ + la_seg0), Alo + (size_t)(bm + la_row0) * lda + k0 + la_seg0);
        cpa16(sptr(al + la_row1 * PAD_ + la_seg1), Alo + (size_t)(bm + la_row1) * lda + k0 + la_seg1);
        cpa16(sptr(bh + la_row0 * PAD_ + la_seg0), Bhi + (size_t)(bn + la_row0) * ldb + k0 + la_seg0);
        cpa16(sptr(bh + la_row1 * PAD_ + la_seg1), Bhi + (size_t)(bn + la_row1) * ldb + k0 + la_seg1);
        cpa16(sptr(bl + la_row0 * PAD_ + la_seg0), Blo + (size_t)(bn + la_row0) * ldb + k0 + la_seg0);
        cpa16(sptr(bl + la_row1 * PAD_ + la_seg1), Blo + (size_t)(bn + la_row1) * ldb + k0 + la_seg1);
    };

    ldchunk(0, 0);
    cpa_commit();

    for (int c = 0; c < nch; c++) {
        const int s = c & 1;
        if (c + 1 < nch) ldchunk(c + 1, (c + 1) & 1);
        cpa_commit();
        cpa_wait1();
        __syncthreads();

        __nv_bfloat16* sAh = tileb(s, 0);
        __nv_bfloat16* sAl = tileb(s, 1);
        __nv_bfloat16* sBh = tileb(s, 2);
        __nv_bfloat16* sBl = tileb(s, 3);

        #pragma unroll
        for (int ks = 0; ks < 2; ks++) {
            const int kc = ks * 16;
            uint32_t ah[2][4], al[2][4];
            #pragma unroll
            for (int mf = 0; mf < 2; mf++) {
                ldsm4(sptr(sAh + (wm * 32 + mf * 16 + a_row) * PAD_ + kc + a_col8),
                      ah[mf][0], ah[mf][1], ah[mf][2], ah[mf][3]);
                ldsm4(sptr(sAl + (wm * 32 + mf * 16 + a_row) * PAD_ + kc + a_col8),
                      al[mf][0], al[mf][1], al[mf][2], al[mf][3]);
            }
            #pragma unroll
            for (int nf2 = 0; nf2 < 4; nf2++) {
                const int brow = wn * 64 + nf2 * 16 + b_rowoff;
                uint32_t bh[4], bl[4];
                ldsm4(sptr(sBh + brow * PAD_ + kc + b_col8), bh[0], bh[1], bh[2], bh[3]);
                ldsm4(sptr(sBl + brow * PAD_ + kc + b_col8), bl[0], bl[1], bl[2], bl[3]);
                #pragma unroll
                for (int mf = 0; mf < 2; mf++) {
                    #pragma unroll
                    for (int f = 0; f < 2; f++) {
                        float* d = acc[mf][nf2 * 2 + f];
                        mma16816(d, ah[mf], bh + 2 * f);
                        mma16816(d, ah[mf], bl + 2 * f);
                        mma16816(d, al[mf], bh + 2 * f);
                    }
                }
            }
        }
        __syncthreads();
    }

    const int g = lane >> 2, t2 = (lane & 3) * 2;
    #pragma unroll
    for (int mf = 0; mf < 2; mf++) {
        #pragma unroll
        for (int nf = 0; nf < 8; nf++) {
            const int row = bm + wm * 32 + mf * 16 + g;
            const int col = bn + wn * 64 + nf * 8 + t2;
            float* d = acc[mf][nf];
            if (!splitOut) {
                *(float2*)(C + (size_t)row * ldc + col) = make_float2(d[0] * scale, d[1] * scale);
                *(float2*)(C + (size_t)(row + 8) * ldc + col) = make_float2(d[2] * scale, d[3] * scale);
            } else {
                uint32_t hp, lp;
                split_pack(d[0] * scale, d[1] * scale, hp, lp);
                *(uint32_t*)(Chi + (size_t)row * ldc + col) = hp;
                *(uint32_t*)(Clo + (size_t)row * ldc + col) = lp;
                split_pack(d[2] * scale, d[3] * scale, hp, lp);
                *(uint32_t*)(Chi + (size_t)(row + 8) * ldc + col) = hp;
                *(uint32_t*)(Clo + (size_t)(row + 8) * ldc + col) = lp;
            }
        }
    }
}

// ---------------------------------------------------------------------------
// Attention pass 1: Z[k] = sum_q exp(<k,q>/32).  Writes rZ = 1/Z.
// ---------------------------------------------------------------------------
#define TP_ 72
#define TB_ (128 * TP_ * 2)

__global__ void __launch_bounds__(256) attn_stats(
    const __nv_bfloat16* __restrict__ Khi, const __nv_bfloat16* __restrict__ Klo,
    const __nv_bfloat16* __restrict__ Qhi, const __nv_bfloat16* __restrict__ Qlo,
    float* __restrict__ rZ) {
    extern __shared__ char smem[];
    __nv_bfloat16* sKh = (__nv_bfloat16*)(smem);
    __nv_bfloat16* sKl = (__nv_bfloat16*)(smem + TB_);
    __nv_bfloat16* sQh = (__nv_bfloat16*)(smem + 2 * TB_);
    __nv_bfloat16* sQl = (__nv_bfloat16*)(smem + 3 * TB_);
    float* sZ = (float*)(smem + 4 * TB_);

    const int hh = blockIdx.y;
    const int b = hh >> 4, h = hh & 15;
    const size_t off = (size_t)b * S_ * L_ + (size_t)h * DH_;
    const int kt = blockIdx.x * 128;

    const int tid = threadIdx.x;
    const int wid = tid >> 5, lane = tid & 31;
    const int wm = wid >> 1, wn = wid & 1;
    const int a_row = (lane & 15);
    const int a_col8 = (lane >> 4) * 8;
    const int b_rowoff = (lane & 7) + ((lane >> 4) << 3);
    const int b_col8 = ((lane >> 3) & 1) * 8;
    const int g = lane >> 2;

    #pragma unroll
    for (int i = 0; i < 4; i++) {
        int idx = tid + i * 256;
        int row = idx >> 3;
        int seg = (idx & 7) * 8;
        *(uint4*)&sKh[row * TP_ + seg] = *(const uint4*)(Khi + off + (size_t)(kt + row) * L_ + seg);
        *(uint4*)&sKl[row * TP_ + seg] = *(const uint4*)(Klo + off + (size_t)(kt + row) * L_ + seg);
    }

    float zp[2][2] = {};
    for (int qt = 0; qt < S_; qt += 128) {
        __syncthreads();
        #pragma unroll
        for (int i = 0; i < 4; i++) {
            int idx = tid + i * 256;
            int row = idx >> 3;
            int seg = (idx & 7) * 8;
            *(uint4*)&sQh[row * TP_ + seg] = *(const uint4*)(Qhi + off + (size_t)(qt + row) * L_ + seg);
            *(uint4*)&sQl[row * TP_ + seg] = *(const uint4*)(Qlo + off + (size_t)(qt + row) * L_ + seg);
        }
        __syncthreads();

        float acc[2][8][4];
        #pragma unroll
        for (int i = 0; i < 2; i++)
            #pragma unroll
            for (int j = 0; j < 8; j++)
                #pragma unroll
                for (int r = 0; r < 4; r++) acc[i][j][r] = 0.0f;

        #pragma unroll
        for (int ks = 0; ks < 4; ks++) {
            const int kc = ks * 16;
            uint32_t ah[2][4], al[2][4];
            #pragma unroll
            for (int mf = 0; mf < 2; mf++) {
                ldsm4(sptr(&sKh[(wm * 32 + mf * 16 + a_row) * TP_ + kc + a_col8]),
                      ah[mf][0], ah[mf][1], ah[mf][2], ah[mf][3]);
                ldsm4(sptr(&sKl[(wm * 32 + mf * 16 + a_row) * TP_ + kc + a_col8]),
                      al[mf][0], al[mf][1], al[mf][2], al[mf][3]);
            }
            #pragma unroll
            for (int nf2 = 0; nf2 < 4; nf2++) {
                const int brow = wn * 64 + nf2 * 16 + b_rowoff;
                uint32_t bh[4], bl[4];
                ldsm4(sptr(&sQh[brow * TP_ + kc + b_col8]), bh[0], bh[1], bh[2], bh[3]);
                ldsm4(sptr(&sQl[brow * TP_ + kc + b_col8]), bl[0], bl[1], bl[2], bl[3]);
                #pragma unroll
                for (int mf = 0; mf < 2; mf++) {
                    #pragma unroll
                    for (int f = 0; f < 2; f++) {
                        float* d = acc[mf][nf2 * 2 + f];
                        mma16816(d, ah[mf], bh + 2 * f);
                        mma16816(d, ah[mf], bl + 2 * f);
                        mma16816(d, al[mf], bh + 2 * f);
                    }
                }
            }
        }

        #pragma unroll
        for (int mf = 0; mf < 2; mf++)
            #pragma unroll
            for (int nf = 0; nf < 8; nf++) {
                float* d = acc[mf][nf];
                zp[mf][0] += fexp32(d[0]) + fexp32(d[1]);
                zp[mf][1] += fexp32(d[2]) + fexp32(d[3]);
            }
    }

    #pragma unroll
    for (int mf = 0; mf < 2; mf++)
        #pragma unroll
        for (int r = 0; r < 2; r++) {
            zp[mf][r] += __shfl_xor_sync(0xffffffffu, zp[mf][r], 1);
            zp[mf][r] += __shfl_xor_sync(0xffffffffu, zp[mf][r], 2);
        }

    if (tid < 128) sZ[tid] = 0.0f;
    __syncthreads();
    if ((lane & 3) == 0) {
        #pragma unroll
        for (int mf = 0; mf < 2; mf++) {
            int r0 = wm * 32 + mf * 16 + g;
            atomicAdd(&sZ[r0], zp[mf][0]);
            atomicAdd(&sZ[r0 + 8], zp[mf][1]);
        }
    }
    __syncthreads();
    if (tid < 128)
        rZ[(size_t)hh * S_ + kt + tid] = 1.0f / sZ[tid];
}

// ---------------------------------------------------------------------------
// Attention pass 2: out[q,d] = sum_k (exp(<k,q>/32) * rZ[k]) * V[k,d].
// ---------------------------------------------------------------------------
__global__ void __launch_bounds__(256) attn_av(
    const __nv_bfloat16* __restrict__ Qhi, const __nv_bfloat16* __restrict__ Qlo,
    const __nv_bfloat16* __restrict__ Khi, const __nv_bfloat16* __restrict__ Klo,
    const __nv_bfloat16* __restrict__ Vhi, const __nv_bfloat16* __restrict__ Vlo,
    const float* __restrict__ rZ,
    __nv_bfloat16* __restrict__ Ohi, __nv_bfloat16* __restrict__ Olo) {
    extern __shared__ char smem[];
    __nv_bfloat16* sQh = (__nv_bfloat16*)(smem);
    __nv_bfloat16* sQl = (__nv_bfloat16*)(smem + TB_);
    __nv_bfloat16* sKh = (__nv_bfloat16*)(smem + 2 * TB_);
    __nv_bfloat16* sKl = (__nv_bfloat16*)(smem + 3 * TB_);
    __nv_bfloat16* sVh = (__nv_bfloat16*)(smem + 4 * TB_);
    __nv_bfloat16* sVl = (__nv_bfloat16*)(smem + 5 * TB_);
    float* srz = (float*)(smem + 6 * TB_);

    const int hh = blockIdx.y;
    const int b = hh >> 4, h = hh & 15;
    const size_t off = (size_t)b * S_ * L_ + (size_t)h * DH_;
    const int qt = blockIdx.x * 128;

    const int tid = threadIdx.x;
    const int wid = tid >> 5, lane = tid & 31;
    const int g = lane >> 2, t2 = (lane & 3) * 2;
    const int a_row = (lane & 15);
    const int a_col8 = (lane >> 4) * 8;
    const int b_rowoff = (lane & 7) + ((lane >> 4) << 3);
    const int b_col8 = ((lane >> 3) & 1) * 8;
    const int v_k = (lane & 7) + (((lane >> 3) & 1) << 3);
    const int v_d = (lane >> 4) * 8;

    #pragma unroll
    for (int i = 0; i < 4; i++) {
        int idx = tid + i * 256;
        int row = idx >> 3;
        int seg = (idx & 7) * 8;
        *(uint4*)&sQh[row * TP_ + seg] = *(const uint4*)(Qhi + off + (size_t)(qt + row) * L_ + seg);
        *(uint4*)&sQl[row * TP_ + seg] = *(const uint4*)(Qlo + off + (size_t)(qt + row) * L_ + seg);
    }

    float avacc[8][4];
    #pragma unroll
    for (int j = 0; j < 8; j++)
        #pragma unroll
        for (int r = 0; r < 4; r++) avacc[j][r] = 0.0f;

    const int wq = wid * 16;

    for (int kt = 0; kt < S_; kt += 128) {
        __syncthreads();
        #pragma unroll
        for (int i = 0; i < 4; i++) {
            int idx = tid + i * 256;
            int row = idx >> 3;
            int seg = (idx & 7) * 8;
            *(uint4*)&sKh[row * TP_ + seg] = *(const uint4*)(Khi + off + (size_t)(kt + row) * L_ + seg);
            *(uint4*)&sKl[row * TP_ + seg] = *(const uint4*)(Klo + off + (size_t)(kt + row) * L_ + seg);
            *(uint4*)&sVh[row * TP_ + seg] = *(const uint4*)(Vhi + off + (size_t)(kt + row) * L_ + seg);
            *(uint4*)&sVl[row * TP_ + seg] = *(const uint4*)(Vlo + off + (size_t)(kt + row) * L_ + seg);
        }
        if (tid < 128) srz[tid] = rZ[(size_t)hh * S_ + kt + tid];
        __syncthreads();

        #pragma unroll
        for (int khalf = 0; khalf < 2; khalf++) {
            float sacc[8][4];
            #pragma unroll
            for (int j = 0; j < 8; j++)
                #pragma unroll
                for (int r = 0; r < 4; r++) sacc[j][r] = 0.0f;

            #pragma unroll
            for (int ks = 0; ks < 4; ks++) {
                const int kc = ks * 16;
                uint32_t ah[4], al[4];
                ldsm4(sptr(&sQh[(wq + a_row) * TP_ + kc + a_col8]), ah[0], ah[1], ah[2], ah[3]);
                ldsm4(sptr(&sQl[(wq + a_row) * TP_ + kc + a_col8]), al[0], al[1], al[2], al[3]);
                #pragma unroll
                for (int nf2 = 0; nf2 < 4; nf2++) {
                    const int brow = khalf * 64 + nf2 * 16 + b_rowoff;
                    uint32_t bh[4], bl[4];
                    ldsm4(sptr(&sKh[brow * TP_ + kc + b_col8]), bh[0], bh[1], bh[2], bh[3]);
                    ldsm4(sptr(&sKl[brow * TP_ + kc + b_col8]), bl[0], bl[1], bl[2], bl[3]);
                    #pragma unroll
                    for (int f = 0; f < 2; f++) {
                        float* d = sacc[nf2 * 2 + f];
                        mma16816(d, ah, bh + 2 * f);
                        mma16816(d, ah, bl + 2 * f);
                        mma16816(d, al, bh + 2 * f);
                    }
                }
            }

            uint32_t pah[4][4], pal[4][4];
            #pragma unroll
            for (int j = 0; j < 4; j++) {
                #pragma unroll
                for (int e = 0; e < 2; e++) {
                    float* d = sacc[2 * j + e];
                    const int col = khalf * 64 + j * 16 + e * 8 + t2;
                    float r0 = srz[col], r1 = srz[col + 1];
                    float p0 = fexp32(d[0]) * r0;
                    float p1 = fexp32(d[1]) * r1;
                    float p2 = fexp32(d[2]) * r0;
                    float p3 = fexp32(d[3]) * r1;
                    split_pack(p0, p1, pah[j][2 * e + 0], pal[j][2 * e + 0]);
                    split_pack(p2, p3, pah[j][2 * e + 1], pal[j][2 * e + 1]);
                }
            }

            #pragma unroll
            for (int j = 0; j < 4; j++) {
                const int kbase = khalf * 64 + j * 16;
                #pragma unroll
                for (int nb = 0; nb < 4; nb++) {
                    uint32_t bvh[4], bvl[4];
                    ldsm4t(sptr(&sVh[(kbase + v_k) * TP_ + nb * 16 + v_d]),
                           bvh[0], bvh[1], bvh[2], bvh[3]);
                    ldsm4t(sptr(&sVl[(kbase + v_k) * TP_ + nb * 16 + v_d]),
                           bvl[0], bvl[1], bvl[2], bvl[3]);
                    #pragma unroll
                    for (int f = 0; f < 2; f++) {
                        float* d = avacc[nb * 2 + f];
                        mma16816(d, pah[j], bvh + 2 * f);
                        mma16816(d, pah[j], bvl + 2 * f);
                        mma16816(d, pal[j], bvh + 2 * f);
                    }
                }
            }
        }
    }

    #pragma unroll
    for (int nf = 0; nf < 8; nf++) {
        const int row = qt + wq + g;
        const int col = nf * 8 + t2;
        float* d = avacc[nf];
        uint32_t hp, lp;
        split_pack(d[0], d[1], hp, lp);
        *(uint32_t*)(Ohi + off + (size_t)row * L_ + col) = hp;
        *(uint32_t*)(Olo + off + (size_t)row * L_ + col) = lp;
        split_pack(d[2], d[3], hp, lp);
        *(uint32_t*)(Ohi + off + (size_t)(row + 8) * L_ + col) = hp;
        *(uint32_t*)(Olo + off + (size_t)(row + 8) * L_ + col) = lp;
    }
}

// ---------------------------------------------------------------------------
// fp32 -> bf16 hi/lo split (element-wise)
// ---------------------------------------------------------------------------
__global__ void __launch_bounds__(256) split_kernel(const float* __restrict__ A,
                                                    __nv_bfloat16* __restrict__ Hi,
                                                    __nv_bfloat16* __restrict__ Lo) {
    size_t i = ((size_t)blockIdx.x * 256 + threadIdx.x) * 4;
    float4 a = *(const float4*)(A + i);
    __nv_bfloat16 h0, l0, h1, l1, h2, l2, h3, l3;
    split1(a.x, h0, l0); split1(a.y, h1, l1);
    split1(a.z, h2, l2); split1(a.w, h3, l3);
    __nv_bfloat162* hp = (__nv_bfloat162*)(Hi + i);
    __nv_bfloat162* lp = (__nv_bfloat162*)(Lo + i);
    hp[0] = __nv_bfloat162(h0, h1); hp[1] = __nv_bfloat162(h2, h3);
    lp[0] = __nv_bfloat162(l0, l1); lp[1] = __nv_bfloat162(l2, l3);
}

// W[K,N] -> Wt hi/lo [N,K]
__global__ void __launch_bounds__(256) transpose_split(const float* __restrict__ W,
                                                       __nv_bfloat16* __restrict__ Th,
                                                       __nv_bfloat16* __restrict__ Tl,
                                                       int K, int N) {
    __shared__ float t[32][33];
    const int k0 = blockIdx.y * 32, n0 = blockIdx.x * 32;
    const int tx = threadIdx.x & 31, ty = threadIdx.x >> 5;
    #pragma unroll
    for (int j = 0; j < 4; j++) {
        int row = ty + j * 8;
        t[row][tx] = W[(size_t)(k0 + row) * N + n0 + tx];
    }
    __syncthreads();
    #pragma unroll
    for (int j = 0; j < 4; j++) {
        int row = ty + j * 8;
        float v = t[tx][row];
        __nv_bfloat16 h, l; split1(v, h, l);
        size_t o = (size_t)(n0 + row) * K + k0 + tx;
        Th[o] = h; Tl[o] = l;
    }
}

// ---------------------------------------------------------------------------
// Row L2 normalize -> bf16 hi/lo split
// ---------------------------------------------------------------------------
__global__ void __launch_bounds__(256) l2norm_split(const float* __restrict__ Z,
                                                    __nv_bfloat16* __restrict__ Hi,
                                                    __nv_bfloat16* __restrict__ Lo) {
    __shared__ float shs[8];
    const size_t row = blockIdx.x;
    const float* p = Z + row * (size_t)D_;
    const int tid = threadIdx.x;
    const int lane = tid & 31, wid = tid >> 5;
    float4 v = *(const float4*)(p + tid * 4);
    float ss = v.x * v.x + v.y * v.y + v.z * v.z + v.w * v.w;
    #pragma unroll
    for (int o = 16; o; o >>= 1) ss += __shfl_xor_sync(0xffffffffu, ss, o);
    if (lane == 0) shs[wid] = ss;
    __syncthreads();
    ss = shs[0];
    #pragma unroll
    for (int i = 1; i < 8; i++) ss += shs[i];
    const float sc = 1.0f / fmaxf(sqrtf(ss), 1e-12f);
    float y0 = v.x * sc, y1 = v.y * sc, y2 = v.z * sc, y3 = v.w * sc;
    __nv_bfloat16 h0, l0, h1, l1, h2, l2, h3, l3;
    split1(y0, h0, l0); split1(y1, h1, l1);
    split1(y2, h2, l2); split1(y3, h3, l3);
    size_t o = row * (size_t)D_ + tid * 4;
    __nv_bfloat162* hp = (__nv_bfloat162*)(Hi + o);
    __nv_bfloat162* lp = (__nv_bfloat162*)(Lo + o);
    hp[0] = __nv_bfloat162(h0, h1); hp[1] = __nv_bfloat162(h2, h3);
    lp[0] = __nv_bfloat162(l0, l1); lp[1] = __nv_bfloat162(l2, l3);
}

// ---------------------------------------------------------------------------
// Row L2 normalize + exact GELU, writes to output
// ---------------------------------------------------------------------------
__global__ void __launch_bounds__(256) l2norm_gelu(const float* __restrict__ Z,
                                                   float* __restrict__ O) {
    __shared__ float shs[8];
    const size_t row = blockIdx.x;
    const float* p = Z + row * (size_t)D_;
    float* q = O + row * (size_t)D_;
    const int tid = threadIdx.x;
    const int lane = tid & 31, wid = tid >> 5;
    float4 v = *(const float4*)(p + tid * 4);
    float ss = v.x * v.x + v.y * v.y + v.z * v.z + v.w * v.w;
    #pragma unroll
    for (int o = 16; o; o >>= 1) ss += __shfl_xor_sync(0xffffffffu, ss, o);
    if (lane == 0) shs[wid] = ss;
    __syncthreads();
    ss = shs[0];
    #pragma unroll
    for (int i = 1; i < 8; i++) ss += shs[i];
    const float sc = 1.0f / fmaxf(sqrtf(ss), 1e-12f);
    float y0 = v.x * sc, y1 = v.y * sc, y2 = v.z * sc, y3 = v.w * sc;
    const float inv_sqrt2 = 0.70710678118654752f;
    float4 g;
    g.x = 0.5f * y0 * (1.0f + erff(y0 * inv_sqrt2));
    g.y = 0.5f * y1 * (1.0f + erff(y1 * inv_sqrt2));
    g.z = 0.5f * y2 * (1.0f + erff(y2 * inv_sqrt2));
    g.w = 0.5f * y3 * (1.0f + erff(y3 * inv_sqrt2));
    *(float4*)(q + tid * 4) = g;
}

// ---------------------------------------------------------------------------
// Launch
// ---------------------------------------------------------------------------
extern "C" void kernel_launch(void* const* d_in, const int* in_sizes, int n_in,
                              void* d_out, int out_size) {
    (void)in_sizes; (void)n_in; (void)out_size;
    const float* x   = (const float*)d_in[0];
    const float* Wq  = (const float*)d_in[1];
    const float* Wk  = (const float*)d_in[2];
    const float* Wv  = (const float*)d_in[3];
    const float* Wo  = (const float*)d_in[4];
    const float* Wff = (const float*)d_in[5];

    float *z1, *z2, *rz;
    cudaGetSymbolAddress((void**)&z1, g_z1);
    cudaGetSymbolAddress((void**)&z2, g_z2);
    cudaGetSymbolAddress((void**)&rz, g_rz);

    __nv_bfloat16 *xhi, *xlo, *qhi, *qlo, *khi, *klo, *vhi, *vlo,
                  *aohi, *aolo, *z1hi, *z1lo, *wth, *wtl;
    cudaGetSymbolAddress((void**)&xhi,  g_xhi);
    cudaGetSymbolAddress((void**)&xlo,  g_xlo);
    cudaGetSymbolAddress((void**)&qhi,  g_qhi);
    cudaGetSymbolAddress((void**)&qlo,  g_qlo);
    cudaGetSymbolAddress((void**)&khi,  g_khi);
    cudaGetSymbolAddress((void**)&klo,  g_klo);
    cudaGetSymbolAddress((void**)&vhi,  g_vhi);
    cudaGetSymbolAddress((void**)&vlo,  g_vlo);
    cudaGetSymbolAddress((void**)&aohi, g_aohi);
    cudaGetSymbolAddress((void**)&aolo, g_aolo);
    cudaGetSymbolAddress((void**)&z1hi, g_z1hi);
    cudaGetSymbolAddress((void**)&z1lo, g_z1lo);
    cudaGetSymbolAddress((void**)&wth,  g_wt_hi);
    cudaGetSymbolAddress((void**)&wtl,  g_wt_lo);
    const size_t WSTR = (size_t)D_ * L_;

    const int SMEM1 = 4 * TB_ + 512;
    const int SMEM2 = 6 * TB_ + 512;
    cudaFuncSetAttribute(hgemm_nt,   cudaFuncAttributeMaxDynamicSharedMemorySize, GSMEM_);
    cudaFuncSetAttribute(attn_stats, cudaFuncAttributeMaxDynamicSharedMemorySize, SMEM1);
    cudaFuncSetAttribute(attn_av,    cudaFuncAttributeMaxDynamicSharedMemorySize, SMEM2);

    const dim3 blk(256);
    const dim3 gT(L_ / 32, D_ / 32);

    split_kernel<<<(M4_ * D_) / 1024, blk>>>(x, xhi, xlo);
    transpose_split<<<gT, blk>>>(Wq,  wth + 0 * WSTR, wtl + 0 * WSTR, D_, L_);
    transpose_split<<<gT, blk>>>(Wk,  wth + 1 * WSTR, wtl + 1 * WSTR, D_, L_);
    transpose_split<<<gT, blk>>>(Wv,  wth + 2 * WSTR, wtl + 2 * WSTR, D_, L_);
    transpose_split<<<gT, blk>>>(Wo,  wth + 3 * WSTR, wtl + 3 * WSTR, L_, D_);
    transpose_split<<<gT, blk>>>(Wff, wth + 4 * WSTR, wtl + 4 * WSTR, D_, D_);

    const dim3 gG(L_ / 128, M4_ / 128, 1);

    // QKV projections, emitting bf16 hi/lo directly
    hgemm_nt<<<gG, blk, GSMEM_>>>(xhi, xlo, wth + 0 * WSTR, wtl + 0 * WSTR, z1, qhi, qlo,
                                  M4_, L_, D_, D_, D_, L_, 1.0f, 1);
    hgemm_nt<<<gG, blk, GSMEM_>>>(xhi, xlo, wth + 1 * WSTR, wtl + 1 * WSTR, z1, khi, klo,
                                  M4_, L_, D_, D_, D_, L_, 1.0f, 1);
    hgemm_nt<<<gG, blk, GSMEM_>>>(xhi, xlo, wth + 2 * WSTR, wtl + 2 * WSTR, z1, vhi, vlo,
                                  M4_, L_, D_, D_, D_, L_, 1.0f, 1);

    // fused attention (two-pass, no materialized scores)
    attn_stats<<<dim3(16, 32), blk, SMEM1>>>(khi, klo, qhi, qlo, rz);
    attn_av<<<dim3(16, 32), blk, SMEM2>>>(qhi, qlo, khi, klo, vhi, vlo, rz, aohi, aolo);

    // output projection
    hgemm_nt<<<gG, blk, GSMEM_>>>(aohi, aolo, wth + 3 * WSTR, wtl + 3 * WSTR, z1,
                                  (__nv_bfloat16*)0, (__nv_bfloat16*)0,
                                  M4_, D_, L_, L_, L_, D_, 1.0f, 0);

    // FFN
    l2norm_split<<<M4_, blk>>>(z1, z1hi, z1lo);
    hgemm_nt<<<gG, blk, GSMEM_>>>(z1hi, z1lo, wth + 4 * WSTR, wtl + 4 * WSTR, z2,
                                  (__nv_bfloat16*)0, (__nv_bfloat16*)0,
                                  M4_, D_, D_, D_, D_, D_, 1.0f, 0);
    l2norm_gelu<<<M4_, blk>>>(z2, (float*)d_out);
}

// round 14
// speedup vs baseline: 2.3998x; 1.0128x over previous
#include <cuda_runtime.h>
#include <cuda_bf16.h>
#include <math.h>
#include <stdint.h>

// Problem dims (fixed by the dataset)
#define B_  2
#define S_  2048
#define D_  1024
#define L_  1024
#define H_  16
#define DH_ 64
#define BH_ (B_ * H_)          // 32
#define M4_ (B_ * S_)          // 4096

// ---------------------------------------------------------------------------
// Scratch
// ---------------------------------------------------------------------------
__device__ float g_z1[(size_t)M4_ * D_];
__device__ float g_z2[(size_t)M4_ * D_];
__device__ float g_rz[(size_t)BH_ * S_];            // 1/Z per (head, k)

__device__ unsigned short g_xhi[(size_t)M4_ * D_];
__device__ unsigned short g_xlo[(size_t)M4_ * D_];
__device__ unsigned short g_qhi[(size_t)M4_ * L_];
__device__ unsigned short g_qlo[(size_t)M4_ * L_];
__device__ unsigned short g_khi[(size_t)M4_ * L_];
__device__ unsigned short g_klo[(size_t)M4_ * L_];
__device__ unsigned short g_vhi[(size_t)M4_ * L_];
__device__ unsigned short g_vlo[(size_t)M4_ * L_];
__device__ unsigned short g_aohi[(size_t)M4_ * L_];
__device__ unsigned short g_aolo[(size_t)M4_ * L_];
__device__ unsigned short g_z1hi[(size_t)M4_ * D_];
__device__ unsigned short g_z1lo[(size_t)M4_ * D_];
__device__ unsigned short g_wt_hi[5][(size_t)D_ * L_];
__device__ unsigned short g_wt_lo[5][(size_t)D_ * L_];

// ---------------------------------------------------------------------------
// helpers
// ---------------------------------------------------------------------------
__device__ __forceinline__ uint32_t sptr(const void* p) {
    return (uint32_t)__cvta_generic_to_shared(p);
}
__device__ __forceinline__ void cpa16(uint32_t saddr, const void* g) {
    asm volatile("cp.async.cg.shared.global [%0], [%1], 16;" :: "r"(saddr), "l"(g));
}
__device__ __forceinline__ void cpa_commit() {
    asm volatile("cp.async.commit_group;" ::: "memory");
}
__device__ __forceinline__ void cpa_wait1() {
    asm volatile("cp.async.wait_group 1;" ::: "memory");
}
__device__ __forceinline__ void ldsm4(uint32_t a, uint32_t& r0, uint32_t& r1,
                                      uint32_t& r2, uint32_t& r3) {
    asm volatile("ldmatrix.sync.aligned.m8n8.x4.shared.b16 {%0,%1,%2,%3}, [%4];"
                 : "=r"(r0), "=r"(r1), "=r"(r2), "=r"(r3) : "r"(a));
}
__device__ __forceinline__ void ldsm4t(uint32_t a, uint32_t& r0, uint32_t& r1,
                                       uint32_t& r2, uint32_t& r3) {
    asm volatile("ldmatrix.sync.aligned.m8n8.x4.trans.shared.b16 {%0,%1,%2,%3}, [%4];"
                 : "=r"(r0), "=r"(r1), "=r"(r2), "=r"(r3) : "r"(a));
}
__device__ __forceinline__ void mma16816(float* d, const uint32_t* a, const uint32_t* b) {
    asm volatile(
        "mma.sync.aligned.m16n8k16.row.col.f32.bf16.bf16.f32 "
        "{%0,%1,%2,%3}, {%4,%5,%6,%7}, {%8,%9}, {%0,%1,%2,%3};"
        : "+f"(d[0]), "+f"(d[1]), "+f"(d[2]), "+f"(d[3])
        : "r"(a[0]), "r"(a[1]), "r"(a[2]), "r"(a[3]), "r"(b[0]), "r"(b[1]));
}
__device__ __forceinline__ void split1(float a, __nv_bfloat16& h, __nv_bfloat16& l) {
    h = __float2bfloat16(a);
    l = __float2bfloat16(a - __bfloat162float(h));
}
__device__ __forceinline__ void split_pack(float x, float y, uint32_t& hi, uint32_t& lo) {
    __nv_bfloat16 hx, lx, hy, ly;
    split1(x, hx, lx); split1(y, hy, ly);
    __nv_bfloat162 Hp(hx, hy), Lp(lx, ly);
    hi = *(uint32_t*)&Hp; lo = *(uint32_t*)&Lp;
}
// exp(s/32) via MUFU: 1 mul + 1 ex2 issue-slot
#define EXPC_ (1.4426950408889634f / 32.0f)
__device__ __forceinline__ float fexp32(float s) {
    float y;
    asm("ex2.approx.f32 %0, %1;" : "=f"(y) : "f"(s * EXPC_));
    return y;
}

// ---------------------------------------------------------------------------
// Warp-MMA NT GEMM, bf16x3, 2-stage cp.async double buffer.
// C = scale * A[M,K] @ Bt[N,K]^T; splitOut=1 -> bf16 hi/lo output.
// CTA 128x128, K-chunk 32, 256 threads = 8 warps (4M x 2N).
// ---------------------------------------------------------------------------
#define PAD_ 40
#define TBG_ (128 * PAD_ * 2)      // bytes per smem tile
#define GSMEM_ (8 * TBG_)          // 2 stages x 4 tiles = 80 KB

__global__ void __launch_bounds__(256) hgemm_nt(
    const __nv_bfloat16* __restrict__ Ahi, const __nv_bfloat16* __restrict__ Alo,
    const __nv_bfloat16* __restrict__ Bhi, const __nv_bfloat16* __restrict__ Blo,
    float* __restrict__ C, __nv_bfloat16* __restrict__ Chi, __nv_bfloat16* __restrict__ Clo,
    int M, int N, int K, int lda, int ldb, int ldc, float scale, int splitOut) {
    extern __shared__ char dsm[];

    const int tid = threadIdx.x;
    const int wid = tid >> 5, lane = tid & 31;
    const int wm = wid >> 1, wn = wid & 1;
    const int bm = blockIdx.y * 128, bn = blockIdx.x * 128;

    const int la_row0 = tid >> 2, la_seg0 = (tid & 3) * 8;
    const int la_row1 = (tid + 256) >> 2, la_seg1 = ((tid + 256) & 3) * 8;

    float acc[2][8][4];
    #pragma unroll
    for (int i = 0; i < 2; i++)
        #pragma unroll
        for (int j = 0; j < 8; j++)
            #pragma unroll
            for (int r = 0; r < 4; r++) acc[i][j][r] = 0.0f;

    const int a_row = (lane & 15);
    const int a_col8 = (lane >> 4) * 8;
    const int b_rowoff = (lane & 7) + ((lane >> 4) << 3);
    const int b_col8 = ((lane >> 3) & 1) * 8;

    const int nch = K >> 5;

    auto tileb = [&](int s, int t) -> __nv_bfloat16* {
        return (__nv_bfloat16*)(dsm + (size_t)(s * 4 + t) * TBG_);
    };
    auto ldchunk = [&](int c, int s) {
        const int k0 = c << 5;
        __nv_bfloat16* ah = tileb(s, 0);
        __nv_bfloat16* al = tileb(s, 1);
        __nv_bfloat16* bh = tileb(s, 2);
        __nv_bfloat16* bl = tileb(s, 3);
        cpa16(sptr(ah + la_row0 * PAD_ + la_seg0), Ahi + (size_t)(bm + la_row0) * lda + k0 + la_seg0);
        cpa16(sptr(ah + la_row1 * PAD_ + la_seg1), Ahi + (size_t)(bm + la_row1) * lda + k0 + la_seg1);
        cpa16(sptr(al + la_row0 * PAD_ + la_seg0), Alo + (size_t)(bm + la_row0) * lda + k0 + la_seg0);
        cpa16(sptr(al + la_row1 * PAD_ + la_seg1), Alo + (size_t)(bm + la_row1) * lda + k0 + la_seg1);
        cpa16(sptr(bh + la_row0 * PAD_ + la_seg0), Bhi + (size_t)(bn + la_row0) * ldb + k0 + la_seg0);
        cpa16(sptr(bh + la_row1 * PAD_ + la_seg1), Bhi + (size_t)(bn + la_row1) * ldb + k0 + la_seg1);
        cpa16(sptr(bl + la_row0 * PAD_ + la_seg0), Blo + (size_t)(bn + la_row0) * ldb + k0 + la_seg0);
        cpa16(sptr(bl + la_row1 * PAD_ + la_seg1), Blo + (size_t)(bn + la_row1) * ldb + k0 + la_seg1);
    };

    ldchunk(0, 0);
    cpa_commit();

    for (int c = 0; c < nch; c++) {
        const int s = c & 1;
        if (c + 1 < nch) ldchunk(c + 1, (c + 1) & 1);
        cpa_commit();
        cpa_wait1();
        __syncthreads();

        __nv_bfloat16* sAh = tileb(s, 0);
        __nv_bfloat16* sAl = tileb(s, 1);
        __nv_bfloat16* sBh = tileb(s, 2);
        __nv_bfloat16* sBl = tileb(s, 3);

        #pragma unroll
        for (int ks = 0; ks < 2; ks++) {
            const int kc = ks * 16;
            uint32_t ah[2][4], al[2][4];
            #pragma unroll
            for (int mf = 0; mf < 2; mf++) {
                ldsm4(sptr(sAh + (wm * 32 + mf * 16 + a_row) * PAD_ + kc + a_col8),
                      ah[mf][0], ah[mf][1], ah[mf][2], ah[mf][3]);
                ldsm4(sptr(sAl + (wm * 32 + mf * 16 + a_row) * PAD_ + kc + a_col8),
                      al[mf][0], al[mf][1], al[mf][2], al[mf][3]);
            }
            #pragma unroll
            for (int nf2 = 0; nf2 < 4; nf2++) {
                const int brow = wn * 64 + nf2 * 16 + b_rowoff;
                uint32_t bh[4], bl[4];
                ldsm4(sptr(sBh + brow * PAD_ + kc + b_col8), bh[0], bh[1], bh[2], bh[3]);
                ldsm4(sptr(sBl + brow * PAD_ + kc + b_col8), bl[0], bl[1], bl[2], bl[3]);
                #pragma unroll
                for (int mf = 0; mf < 2; mf++) {
                    #pragma unroll
                    for (int f = 0; f < 2; f++) {
                        float* d = acc[mf][nf2 * 2 + f];
                        mma16816(d, ah[mf], bh + 2 * f);
                        mma16816(d, ah[mf], bl + 2 * f);
                        mma16816(d, al[mf], bh + 2 * f);
                    }
                }
            }
        }
        __syncthreads();
    }

    const int g = lane >> 2, t2 = (lane & 3) * 2;
    #pragma unroll
    for (int mf = 0; mf < 2; mf++) {
        #pragma unroll
        for (int nf = 0; nf < 8; nf++) {
            const int row = bm + wm * 32 + mf * 16 + g;
            const int col = bn + wn * 64 + nf * 8 + t2;
            float* d = acc[mf][nf];
            if (!splitOut) {
                *(float2*)(C + (size_t)row * ldc + col) = make_float2(d[0] * scale, d[1] * scale);
                *(float2*)(C + (size_t)(row + 8) * ldc + col) = make_float2(d[2] * scale, d[3] * scale);
            } else {
                uint32_t hp, lp;
                split_pack(d[0] * scale, d[1] * scale, hp, lp);
                *(uint32_t*)(Chi + (size_t)row * ldc + col) = hp;
                *(uint32_t*)(Clo + (size_t)row * ldc + col) = lp;
                split_pack(d[2] * scale, d[3] * scale, hp, lp);
                *(uint32_t*)(Chi + (size_t)(row + 8) * ldc + col) = hp;
                *(uint32_t*)(Clo + (size_t)(row + 8) * ldc + col) = lp;
            }
        }
    }
}

// ---------------------------------------------------------------------------
// Attention pass 1: Z[k] = sum_q exp(<k,q>/32).  Writes rZ = 1/Z.
// K tile persistent; Q tiles double-buffered via cp.async (2 stages).
// smem: K(2 tiles) + Q(2 stages x 2 tiles) = 6 tiles + sZ.
// ---------------------------------------------------------------------------
#define TP_ 72
#define TB_ (128 * TP_ * 2)

__global__ void __launch_bounds__(256) attn_stats(
    const __nv_bfloat16* __restrict__ Khi, const __nv_bfloat16* __restrict__ Klo,
    const __nv_bfloat16* __restrict__ Qhi, const __nv_bfloat16* __restrict__ Qlo,
    float* __restrict__ rZ) {
    extern __shared__ char smem[];
    __nv_bfloat16* sKh = (__nv_bfloat16*)(smem);
    __nv_bfloat16* sKl = (__nv_bfloat16*)(smem + TB_);
    float* sZ = (float*)(smem + 6 * TB_);

    const int hh = blockIdx.y;
    const int b = hh >> 4, h = hh & 15;
    const size_t off = (size_t)b * S_ * L_ + (size_t)h * DH_;
    const int kt = blockIdx.x * 128;

    const int tid = threadIdx.x;
    const int wid = tid >> 5, lane = tid & 31;
    const int wm = wid >> 1, wn = wid & 1;
    const int a_row = (lane & 15);
    const int a_col8 = (lane >> 4) * 8;
    const int b_rowoff = (lane & 7) + ((lane >> 4) << 3);
    const int b_col8 = ((lane >> 3) & 1) * 8;
    const int g = lane >> 2;

    auto qh = [&](int s) { return (__nv_bfloat16*)(smem + 2 * TB_ + (size_t)s * 2 * TB_); };
    auto ql = [&](int s) { return (__nv_bfloat16*)(smem + 3 * TB_ + (size_t)s * 2 * TB_); };
    auto ld_q = [&](int c, int s) {
        const int qt = c * 128;
        __nv_bfloat16* qhp = qh(s);
        __nv_bfloat16* qlp = ql(s);
        #pragma unroll
        for (int i = 0; i < 4; i++) {
            int idx = tid + i * 256;
            int row = idx >> 3;
            int seg = (idx & 7) * 8;
            cpa16(sptr(qhp + row * TP_ + seg), Qhi + off + (size_t)(qt + row) * L_ + seg);
            cpa16(sptr(qlp + row * TP_ + seg), Qlo + off + (size_t)(qt + row) * L_ + seg);
        }
    };

    // K tile direct load (consumed after first sync)
    #pragma unroll
    for (int i = 0; i < 4; i++) {
        int idx = tid + i * 256;
        int row = idx >> 3;
        int seg = (idx & 7) * 8;
        *(uint4*)&sKh[row * TP_ + seg] = *(const uint4*)(Khi + off + (size_t)(kt + row) * L_ + seg);
        *(uint4*)&sKl[row * TP_ + seg] = *(const uint4*)(Klo + off + (size_t)(kt + row) * L_ + seg);
    }

    ld_q(0, 0);
    cpa_commit();

    float zp[2][2] = {};
    for (int c = 0; c < 16; c++) {
        const int s = c & 1;
        if (c + 1 < 16) ld_q(c + 1, s ^ 1);
        cpa_commit();
        cpa_wait1();
        __syncthreads();
        __nv_bfloat16* sQh = qh(s);
        __nv_bfloat16* sQl = ql(s);

        float acc[2][8][4];
        #pragma unroll
        for (int i = 0; i < 2; i++)
            #pragma unroll
            for (int j = 0; j < 8; j++)
                #pragma unroll
                for (int r = 0; r < 4; r++) acc[i][j][r] = 0.0f;

        #pragma unroll
        for (int ks = 0; ks < 4; ks++) {
            const int kc = ks * 16;
            uint32_t ah[2][4], al[2][4];
            #pragma unroll
            for (int mf = 0; mf < 2; mf++) {
                ldsm4(sptr(&sKh[(wm * 32 + mf * 16 + a_row) * TP_ + kc + a_col8]),
                      ah[mf][0], ah[mf][1], ah[mf][2], ah[mf][3]);
                ldsm4(sptr(&sKl[(wm * 32 + mf * 16 + a_row) * TP_ + kc + a_col8]),
                      al[mf][0], al[mf][1], al[mf][2], al[mf][3]);
            }
            #pragma unroll
            for (int nf2 = 0; nf2 < 4; nf2++) {
                const int brow = wn * 64 + nf2 * 16 + b_rowoff;
                uint32_t bh[4], bl[4];
                ldsm4(sptr(&sQh[brow * TP_ + kc + b_col8]), bh[0], bh[1], bh[2], bh[3]);
                ldsm4(sptr(&sQl[brow * TP_ + kc + b_col8]), bl[0], bl[1], bl[2], bl[3]);
                #pragma unroll
                for (int mf = 0; mf < 2; mf++) {
                    #pragma unroll
                    for (int f = 0; f < 2; f++) {
                        float* d = acc[mf][nf2 * 2 + f];
                        mma16816(d, ah[mf], bh + 2 * f);
                        mma16816(d, ah[mf], bl + 2 * f);
                        mma16816(d, al[mf], bh + 2 * f);
                    }
                }
            }
        }

        #pragma unroll
        for (int mf = 0; mf < 2; mf++)
            #pragma unroll
            for (int nf = 0; nf < 8; nf++) {
                float* d = acc[mf][nf];
                zp[mf][0] += fexp32(d[0]) + fexp32(d[1]);
                zp[mf][1] += fexp32(d[2]) + fexp32(d[3]);
            }
        __syncthreads();
    }

    #pragma unroll
    for (int mf = 0; mf < 2; mf++)
        #pragma unroll
        for (int r = 0; r < 2; r++) {
            zp[mf][r] += __shfl_xor_sync(0xffffffffu, zp[mf][r], 1);
            zp[mf][r] += __shfl_xor_sync(0xffffffffu, zp[mf][r], 2);
        }

    if (tid < 128) sZ[tid] = 0.0f;
    __syncthreads();
    if ((lane & 3) == 0) {
        #pragma unroll
        for (int mf = 0; mf < 2; mf++) {
            int r0 = wm * 32 + mf * 16 + g;
            atomicAdd(&sZ[r0], zp[mf][0]);
            atomicAdd(&sZ[r0 + 8], zp[mf][1]);
        }
    }
    __syncthreads();
    if (tid < 128)
        rZ[(size_t)hh * S_ + kt + tid] = 1.0f / sZ[tid];
}

// ---------------------------------------------------------------------------
// Attention pass 2: out[q,d] = sum_k (exp(<k,q>/32) * rZ[k]) * V[k,d].
// Q persistent; K/V tiles + rz double-buffered via cp.async (2 stages).
// smem: Q(2) + KV(2 stages x 4 tiles) = 10 tiles + rz[2][128].
// ---------------------------------------------------------------------------
__global__ void __launch_bounds__(256) attn_av(
    const __nv_bfloat16* __restrict__ Qhi, const __nv_bfloat16* __restrict__ Qlo,
    const __nv_bfloat16* __restrict__ Khi, const __nv_bfloat16* __restrict__ Klo,
    const __nv_bfloat16* __restrict__ Vhi, const __nv_bfloat16* __restrict__ Vlo,
    const float* __restrict__ rZ,
    __nv_bfloat16* __restrict__ Ohi, __nv_bfloat16* __restrict__ Olo) {
    extern __shared__ char smem[];
    __nv_bfloat16* sQh = (__nv_bfloat16*)(smem);
    __nv_bfloat16* sQl = (__nv_bfloat16*)(smem + TB_);

    const int hh = blockIdx.y;
    const int b = hh >> 4, h = hh & 15;
    const size_t off = (size_t)b * S_ * L_ + (size_t)h * DH_;
    const int qt = blockIdx.x * 128;

    const int tid = threadIdx.x;
    const int wid = tid >> 5, lane = tid & 31;
    const int g = lane >> 2, t2 = (lane & 3) * 2;
    const int a_row = (lane & 15);
    const int a_col8 = (lane >> 4) * 8;
    const int b_rowoff = (lane & 7) + ((lane >> 4) << 3);
    const int b_col8 = ((lane >> 3) & 1) * 8;
    const int v_k = (lane & 7) + (((lane >> 3) & 1) << 3);
    const int v_d = (lane >> 4) * 8;

    auto kh = [&](int s) { return (__nv_bfloat16*)(smem + 2 * TB_ + (size_t)s * 4 * TB_); };
    auto kl = [&](int s) { return (__nv_bfloat16*)(smem + 3 * TB_ + (size_t)s * 4 * TB_); };
    auto vh = [&](int s) { return (__nv_bfloat16*)(smem + 4 * TB_ + (size_t)s * 4 * TB_); };
    auto vl = [&](int s) { return (__nv_bfloat16*)(smem + 5 * TB_ + (size_t)s * 4 * TB_); };
    float* srz = (float*)(smem + 10 * TB_);          // [2][128]

    auto ld_kv = [&](int c, int s) {
        const int kt = c * 128;
        __nv_bfloat16* khp = kh(s);
        __nv_bfloat16* klp = kl(s);
        __nv_bfloat16* vhp = vh(s);
        __nv_bfloat16* vlp = vl(s);
        #pragma unroll
        for (int i = 0; i < 4; i++) {
            int idx = tid + i * 256;
            int row = idx >> 3;
            int seg = (idx & 7) * 8;
            cpa16(sptr(khp + row * TP_ + seg), Khi + off + (size_t)(kt + row) * L_ + seg);
            cpa16(sptr(klp + row * TP_ + seg), Klo + off + (size_t)(kt + row) * L_ + seg);
            cpa16(sptr(vhp + row * TP_ + seg), Vhi + off + (size_t)(kt + row) * L_ + seg);
            cpa16(sptr(vlp + row * TP_ + seg), Vlo + off + (size_t)(kt + row) * L_ + seg);
        }
        if (tid < 32)
            cpa16(sptr(srz + s * 128 + tid * 4), rZ + (size_t)hh * S_ + kt + tid * 4);
    };

    // Q tile direct load (consumed after first sync)
    #pragma unroll
    for (int i = 0; i < 4; i++) {
        int idx = tid + i * 256;
        int row = idx >> 3;
        int seg = (idx & 7) * 8;
        *(uint4*)&sQh[row * TP_ + seg] = *(const uint4*)(Qhi + off + (size_t)(qt + row) * L_ + seg);
        *(uint4*)&sQl[row * TP_ + seg] = *(const uint4*)(Qlo + off + (size_t)(qt + row) * L_ + seg);
    }

    ld_kv(0, 0);
    cpa_commit();

    float avacc[8][4];
    #pragma unroll
    for (int j = 0; j < 8; j++)
        #pragma unroll
        for (int r = 0; r < 4; r++) avacc[j][r] = 0.0f;

    const int wq = wid * 16;

    for (int c = 0; c < 16; c++) {
        const int s = c & 1;
        if (c + 1 < 16) ld_kv(c + 1, s ^ 1);
        cpa_commit();
        cpa_wait1();
        __syncthreads();
        __nv_bfloat16* sKh = kh(s);
        __nv_bfloat16* sKl = kl(s);
        __nv_bfloat16* sVh = vh(s);
        __nv_bfloat16* sVl = vl(s);
        const float* rz = srz + s * 128;

        #pragma unroll
        for (int khalf = 0; khalf < 2; khalf++) {
            float sacc[8][4];
            #pragma unroll
            for (int j = 0; j < 8; j++)
                #pragma unroll
                for (int r = 0; r < 4; r++) sacc[j][r] = 0.0f;

            #pragma unroll
            for (int ks = 0; ks < 4; ks++) {
                const int kc = ks * 16;
                uint32_t ah[4], al[4];
                ldsm4(sptr(&sQh[(wq + a_row) * TP_ + kc + a_col8]), ah[0], ah[1], ah[2], ah[3]);
                ldsm4(sptr(&sQl[(wq + a_row) * TP_ + kc + a_col8]), al[0], al[1], al[2], al[3]);
                #pragma unroll
                for (int nf2 = 0; nf2 < 4; nf2++) {
                    const int brow = khalf * 64 + nf2 * 16 + b_rowoff;
                    uint32_t bh[4], bl[4];
                    ldsm4(sptr(&sKh[brow * TP_ + kc + b_col8]), bh[0], bh[1], bh[2], bh[3]);
                    ldsm4(sptr(&sKl[brow * TP_ + kc + b_col8]), bl[0], bl[1], bl[2], bl[3]);
                    #pragma unroll
                    for (int f = 0; f < 2; f++) {
                        float* d = sacc[nf2 * 2 + f];
                        mma16816(d, ah, bh + 2 * f);
                        mma16816(d, ah, bl + 2 * f);
                        mma16816(d, al, bh + 2 * f);
                    }
                }
            }

            uint32_t pah[4][4], pal[4][4];
            #pragma unroll
            for (int j = 0; j < 4; j++) {
                #pragma unroll
                for (int e = 0; e < 2; e++) {
                    float* d = sacc[2 * j + e];
                    const int col = khalf * 64 + j * 16 + e * 8 + t2;
                    float r0 = rz[col], r1 = rz[col + 1];
                    float p0 = fexp32(d[0]) * r0;
                    float p1 = fexp32(d[1]) * r1;
                    float p2 = fexp32(d[2]) * r0;
                    float p3 = fexp32(d[3]) * r1;
                    split_pack(p0, p1, pah[j][2 * e + 0], pal[j][2 * e + 0]);
                    split_pack(p2, p3, pah[j][2 * e + 1], pal[j][2 * e + 1]);
                }
            }

            #pragma unroll
            for (int j = 0; j < 4; j++) {
                const int kbase = khalf * 64 + j * 16;
                #pragma unroll
                for (int nb = 0; nb < 4; nb++) {
                    uint32_t bvh[4], bvl[4];
                    ldsm4t(sptr(&sVh[(kbase + v_k) * TP_ + nb * 16 + v_d]),
                           bvh[0], bvh[1], bvh[2], bvh[3]);
                    ldsm4t(sptr(&sVl[(kbase + v_k) * TP_ + nb * 16 + v_d]),
                           bvl[0], bvl[1], bvl[2], bvl[3]);
                    #pragma unroll
                    for (int f = 0; f < 2; f++) {
                        float* d = avacc[nb * 2 + f];
                        mma16816(d, pah[j], bvh + 2 * f);
                        mma16816(d, pah[j], bvl + 2 * f);
                        mma16816(d, pal[j], bvh + 2 * f);
                    }
                }
            }
        }
        __syncthreads();
    }

    #pragma unroll
    for (int nf = 0; nf < 8; nf++) {
        const int row = qt + wq + g;
        const int col = nf * 8 + t2;
        float* d = avacc[nf];
        uint32_t hp, lp;
        split_pack(d[0], d[1], hp, lp);
        *(uint32_t*)(Ohi + off + (size_t)row * L_ + col) = hp;
        *(uint32_t*)(Olo + off + (size_t)row * L_ + col) = lp;
        split_pack(d[2], d[3], hp, lp);
        *(uint32_t*)(Ohi + off + (size_t)(row + 8) * L_ + col) = hp;
        *(uint32_t*)(Olo + off + (size_t)(row + 8) * L_ + col) = lp;
    }
}

// ---------------------------------------------------------------------------
// fp32 -> bf16 hi/lo split (element-wise)
// ---------------------------------------------------------------------------
__global__ void __launch_bounds__(256) split_kernel(const float* __restrict__ A,
                                                    __nv_bfloat16* __restrict__ Hi,
                                                    __nv_bfloat16* __restrict__ Lo) {
    size_t i = ((size_t)blockIdx.x * 256 + threadIdx.x) * 4;
    float4 a = *(const float4*)(A + i);
    __nv_bfloat16 h0, l0, h1, l1, h2, l2, h3, l3;
    split1(a.x, h0, l0); split1(a.y, h1, l1);
    split1(a.z, h2, l2); split1(a.w, h3, l3);
    __nv_bfloat162* hp = (__nv_bfloat162*)(Hi + i);
    __nv_bfloat162* lp = (__nv_bfloat162*)(Lo + i);
    hp[0] = __nv_bfloat162(h0, h1); hp[1] = __nv_bfloat162(h2, h3);
    lp[0] = __nv_bfloat162(l0, l1); lp[1] = __nv_bfloat162(l2, l3);
}

// W[K,N] -> Wt hi/lo [N,K]
__global__ void __launch_bounds__(256) transpose_split(const float* __restrict__ W,
                                                       __nv_bfloat16* __restrict__ Th,
                                                       __nv_bfloat16* __restrict__ Tl,
                                                       int K, int N) {
    __shared__ float t[32][33];
    const int k0 = blockIdx.y * 32, n0 = blockIdx.x * 32;
    const int tx = threadIdx.x & 31, ty = threadIdx.x >> 5;
    #pragma unroll
    for (int j = 0; j < 4; j++) {
        int row = ty + j * 8;
        t[row][tx] = W[(size_t)(k0 + row) * N + n0 + tx];
    }
    __syncthreads();
    #pragma unroll
    for (int j = 0; j < 4; j++) {
        int row = ty + j * 8;
        float v = t[tx][row];
        __nv_bfloat16 h, l; split1(v, h, l);
        size_t o = (size_t)(n0 + row) * K + k0 + tx;
        Th[o] = h; Tl[o] = l;
    }
}

// ---------------------------------------------------------------------------
// Row L2 normalize -> bf16 hi/lo split
// ---------------------------------------------------------------------------
__global__ void __launch_bounds__(256) l2norm_split(const float* __restrict__ Z,
                                                    __nv_bfloat16* __restrict__ Hi,
                                                    __nv_bfloat16* __restrict__ Lo) {
    __shared__ float shs[8];
    const size_t row = blockIdx.x;
    const float* p = Z + row * (size_t)D_;
    const int tid = threadIdx.x;
    const int lane = tid & 31, wid = tid >> 5;
    float4 v = *(const float4*)(p + tid * 4);
    float ss = v.x * v.x + v.y * v.y + v.z * v.z + v.w * v.w;
    #pragma unroll
    for (int o = 16; o; o >>= 1) ss += __shfl_xor_sync(0xffffffffu, ss, o);
    if (lane == 0) shs[wid] = ss;
    __syncthreads();
    ss = shs[0];
    #pragma unroll
    for (int i = 1; i < 8; i++) ss += shs[i];
    const float sc = 1.0f / fmaxf(sqrtf(ss), 1e-12f);
    float y0 = v.x * sc, y1 = v.y * sc, y2 = v.z * sc, y3 = v.w * sc;
    __nv_bfloat16 h0, l0, h1, l1, h2, l2, h3, l3;
    split1(y0, h0, l0); split1(y1, h1, l1);
    split1(y2, h2, l2); split1(y3, h3, l3);
    size_t o = row * (size_t)D_ + tid * 4;
    __nv_bfloat162* hp = (__nv_bfloat162*)(Hi + o);
    __nv_bfloat162* lp = (__nv_bfloat162*)(Lo + o);
    hp[0] = __nv_bfloat162(h0, h1); hp[1] = __nv_bfloat162(h2, h3);
    lp[0] = __nv_bfloat162(l0, l1); lp[1] = __nv_bfloat162(l2, l3);
}

// ---------------------------------------------------------------------------
// Row L2 normalize + exact GELU, writes to output
// ---------------------------------------------------------------------------
__global__ void __launch_bounds__(256) l2norm_gelu(const float* __restrict__ Z,
                                                   float* __restrict__ O) {
    __shared__ float shs[8];
    const size_t row = blockIdx.x;
    const float* p = Z + row * (size_t)D_;
    float* q = O + row * (size_t)D_;
    const int tid = threadIdx.x;
    const int lane = tid & 31, wid = tid >> 5;
    float4 v = *(const float4*)(p + tid * 4);
    float ss = v.x * v.x + v.y * v.y + v.z * v.z + v.w * v.w;
    #pragma unroll
    for (int o = 16; o; o >>= 1) ss += __shfl_xor_sync(0xffffffffu, ss, o);
    if (lane == 0) shs[wid] = ss;
    __syncthreads();
    ss = shs[0];
    #pragma unroll
    for (int i = 1; i < 8; i++) ss += shs[i];
    const float sc = 1.0f / fmaxf(sqrtf(ss), 1e-12f);
    float y0 = v.x * sc, y1 = v.y * sc, y2 = v.z * sc, y3 = v.w * sc;
    const float inv_sqrt2 = 0.70710678118654752f;
    float4 g;
    g.x = 0.5f * y0 * (1.0f + erff(y0 * inv_sqrt2));
    g.y = 0.5f * y1 * (1.0f + erff(y1 * inv_sqrt2));
    g.z = 0.5f * y2 * (1.0f + erff(y2 * inv_sqrt2));
    g.w = 0.5f * y3 * (1.0f + erff(y3 * inv_sqrt2));
    *(float4*)(q + tid * 4) = g;
}

// ---------------------------------------------------------------------------
// Launch
// ---------------------------------------------------------------------------
extern "C" void kernel_launch(void* const* d_in, const int* in_sizes, int n_in,
                              void* d_out, int out_size) {
    (void)in_sizes; (void)n_in; (void)out_size;
    const float* x   = (const float*)d_in[0];
    const float* Wq  = (const float*)d_in[1];
    const float* Wk  = (const float*)d_in[2];
    const float* Wv  = (const float*)d_in[3];
    const float* Wo  = (const float*)d_in[4];
    const float* Wff = (const float*)d_in[5];

    float *z1, *z2, *rz;
    cudaGetSymbolAddress((void**)&z1, g_z1);
    cudaGetSymbolAddress((void**)&z2, g_z2);
    cudaGetSymbolAddress((void**)&rz, g_rz);

    __nv_bfloat16 *xhi, *xlo, *qhi, *qlo, *khi, *klo, *vhi, *vlo,
                  *aohi, *aolo, *z1hi, *z1lo, *wth, *wtl;
    cudaGetSymbolAddress((void**)&xhi,  g_xhi);
    cudaGetSymbolAddress((void**)&xlo,  g_xlo);
    cudaGetSymbolAddress((void**)&qhi,  g_qhi);
    cudaGetSymbolAddress((void**)&qlo,  g_qlo);
    cudaGetSymbolAddress((void**)&khi,  g_khi);
    cudaGetSymbolAddress((void**)&klo,  g_klo);
    cudaGetSymbolAddress((void**)&vhi,  g_vhi);
    cudaGetSymbolAddress((void**)&vlo,  g_vlo);
    cudaGetSymbolAddress((void**)&aohi, g_aohi);
    cudaGetSymbolAddress((void**)&aolo, g_aolo);
    cudaGetSymbolAddress((void**)&z1hi, g_z1hi);
    cudaGetSymbolAddress((void**)&z1lo, g_z1lo);
    cudaGetSymbolAddress((void**)&wth,  g_wt_hi);
    cudaGetSymbolAddress((void**)&wtl,  g_wt_lo);
    const size_t WSTR = (size_t)D_ * L_;

    const int SMEM1 = 6 * TB_ + 512;
    const int SMEM2 = 10 * TB_ + 1024;
    cudaFuncSetAttribute(hgemm_nt,   cudaFuncAttributeMaxDynamicSharedMemorySize, GSMEM_);
    cudaFuncSetAttribute(attn_stats, cudaFuncAttributeMaxDynamicSharedMemorySize, SMEM1);
    cudaFuncSetAttribute(attn_av,    cudaFuncAttributeMaxDynamicSharedMemorySize, SMEM2);

    const dim3 blk(256);
    const dim3 gT(L_ / 32, D_ / 32);

    split_kernel<<<(M4_ * D_) / 1024, blk>>>(x, xhi, xlo);
    transpose_split<<<gT, blk>>>(Wq,  wth + 0 * WSTR, wtl + 0 * WSTR, D_, L_);
    transpose_split<<<gT, blk>>>(Wk,  wth + 1 * WSTR, wtl + 1 * WSTR, D_, L_);
    transpose_split<<<gT, blk>>>(Wv,  wth + 2 * WSTR, wtl + 2 * WSTR, D_, L_);
    transpose_split<<<gT, blk>>>(Wo,  wth + 3 * WSTR, wtl + 3 * WSTR, L_, D_);
    transpose_split<<<gT, blk>>>(Wff, wth + 4 * WSTR, wtl + 4 * WSTR, D_, D_);

    const dim3 gG(L_ / 128, M4_ / 128, 1);

    // QKV projections, emitting bf16 hi/lo directly
    hgemm_nt<<<gG, blk, GSMEM_>>>(xhi, xlo, wth + 0 * WSTR, wtl + 0 * WSTR, z1, qhi, qlo,
                                  M4_, L_, D_, D_, D_, L_, 1.0f, 1);
    hgemm_nt<<<gG, blk, GSMEM_>>>(xhi, xlo, wth + 1 * WSTR, wtl + 1 * WSTR, z1, khi, klo,
                                  M4_, L_, D_, D_, D_, L_, 1.0f, 1);
    hgemm_nt<<<gG, blk, GSMEM_>>>(xhi, xlo, wth + 2 * WSTR, wtl + 2 * WSTR, z1, vhi, vlo,
                                  M4_, L_, D_, D_, D_, L_, 1.0f, 1);

    // fused attention (two-pass, no materialized scores; cp.async pipelined)
    attn_stats<<<dim3(16, 32), blk, SMEM1>>>(khi, klo, qhi, qlo, rz);
    attn_av<<<dim3(16, 32), blk, SMEM2>>>(qhi, qlo, khi, klo, vhi, vlo, rz, aohi, aolo);

    // output projection
    hgemm_nt<<<gG, blk, GSMEM_>>>(aohi, aolo, wth + 3 * WSTR, wtl + 3 * WSTR, z1,
                                  (__nv_bfloat16*)0, (__nv_bfloat16*)0,
                                  M4_, D_, L_, L_, L_, D_, 1.0f, 0);

    // FFN
    l2norm_split<<<M4_, blk>>>(z1, z1hi, z1lo);
    hgemm_nt<<<gG, blk, GSMEM_>>>(z1hi, z1lo, wth + 4 * WSTR, wtl + 4 * WSTR, z2,
                                  (__nv_bfloat16*)0, (__nv_bfloat16*)0,
                                  M4_, D_, D_, D_, D_, D_, 1.0f, 0);
    l2norm_gelu<<<M4_, blk>>>(z2, (float*)d_out);
}

// round 16
// speedup vs baseline: 2.8691x; 1.1956x over previous
#include <cuda_runtime.h>
#include <cuda_bf16.h>
#include <cuda_fp16.h>
#include <math.h>
#include <stdint.h>

// Problem dims (fixed by the dataset)
#define B_  2
#define S_  2048
#define D_  1024
#define L_  1024
#define H_  16
#define DH_ 64
#define BH_ (B_ * H_)          // 32
#define M4_ (B_ * S_)          // 4096

// ---------------------------------------------------------------------------
// Scratch
// ---------------------------------------------------------------------------
__device__ float g_z1[(size_t)M4_ * D_];
__device__ float g_z2[(size_t)M4_ * D_];
__device__ float g_rz[(size_t)BH_ * S_];            // 1/Z per (head, k)

__device__ unsigned short g_xhi[(size_t)M4_ * D_];
__device__ unsigned short g_xlo[(size_t)M4_ * D_];
__device__ unsigned short g_q16[(size_t)M4_ * L_];  // q as fp16
__device__ unsigned short g_k16[(size_t)M4_ * L_];  // k as fp16
__device__ unsigned short g_vhi[(size_t)M4_ * L_];
__device__ unsigned short g_vlo[(size_t)M4_ * L_];
__device__ unsigned short g_aohi[(size_t)M4_ * L_];
__device__ unsigned short g_aolo[(size_t)M4_ * L_];
__device__ unsigned short g_z1hi[(size_t)M4_ * D_];
__device__ unsigned short g_z1lo[(size_t)M4_ * D_];
__device__ unsigned short g_wt_hi[5][(size_t)D_ * L_];
__device__ unsigned short g_wt_lo[5][(size_t)D_ * L_];

// ---------------------------------------------------------------------------
// helpers
// ---------------------------------------------------------------------------
__device__ __forceinline__ uint32_t sptr(const void* p) {
    return (uint32_t)__cvta_generic_to_shared(p);
}
__device__ __forceinline__ void cpa16(uint32_t saddr, const void* g) {
    asm volatile("cp.async.cg.shared.global [%0], [%1], 16;" :: "r"(saddr), "l"(g));
}
__device__ __forceinline__ void cpa_commit() {
    asm volatile("cp.async.commit_group;" ::: "memory");
}
__device__ __forceinline__ void cpa_wait1() {
    asm volatile("cp.async.wait_group 1;" ::: "memory");
}
__device__ __forceinline__ void ldsm4(uint32_t a, uint32_t& r0, uint32_t& r1,
                                      uint32_t& r2, uint32_t& r3) {
    asm volatile("ldmatrix.sync.aligned.m8n8.x4.shared.b16 {%0,%1,%2,%3}, [%4];"
                 : "=r"(r0), "=r"(r1), "=r"(r2), "=r"(r3) : "r"(a));
}
__device__ __forceinline__ void ldsm4t(uint32_t a, uint32_t& r0, uint32_t& r1,
                                       uint32_t& r2, uint32_t& r3) {
    asm volatile("ldmatrix.sync.aligned.m8n8.x4.trans.shared.b16 {%0,%1,%2,%3}, [%4];"
                 : "=r"(r0), "=r"(r1), "=r"(r2), "=r"(r3) : "r"(a));
}
// bf16 MMA
__device__ __forceinline__ void mma16816(float* d, const uint32_t* a, const uint32_t* b) {
    asm volatile(
        "mma.sync.aligned.m16n8k16.row.col.f32.bf16.bf16.f32 "
        "{%0,%1,%2,%3}, {%4,%5,%6,%7}, {%8,%9}, {%0,%1,%2,%3};"
        : "+f"(d[0]), "+f"(d[1]), "+f"(d[2]), "+f"(d[3])
        : "r"(a[0]), "r"(a[1]), "r"(a[2]), "r"(a[3]), "r"(b[0]), "r"(b[1]));
}
// fp16 MMA (same fragment layout)
__device__ __forceinline__ void mma16816h(float* d, const uint32_t* a, const uint32_t* b) {
    asm volatile(
        "mma.sync.aligned.m16n8k16.row.col.f32.f16.f16.f32 "
        "{%0,%1,%2,%3}, {%4,%5,%6,%7}, {%8,%9}, {%0,%1,%2,%3};"
        : "+f"(d[0]), "+f"(d[1]), "+f"(d[2]), "+f"(d[3])
        : "r"(a[0]), "r"(a[1]), "r"(a[2]), "r"(a[3]), "r"(b[0]), "r"(b[1]));
}
__device__ __forceinline__ void split1(float a, __nv_bfloat16& h, __nv_bfloat16& l) {
    h = __float2bfloat16(a);
    l = __float2bfloat16(a - __bfloat162float(h));
}
__device__ __forceinline__ void split_pack(float x, float y, uint32_t& hi, uint32_t& lo) {
    __nv_bfloat16 hx, lx, hy, ly;
    split1(x, hx, lx); split1(y, hy, ly);
    __nv_bfloat162 Hp(hx, hy), Lp(lx, ly);
    hi = *(uint32_t*)&Hp; lo = *(uint32_t*)&Lp;
}
// exp(s/32) via MUFU
#define EXPC_ (1.4426950408889634f / 32.0f)
__device__ __forceinline__ float fexp32(float s) {
    float y;
    asm("ex2.approx.f32 %0, %1;" : "=f"(y) : "f"(s * EXPC_));
    return y;
}

// ---------------------------------------------------------------------------
// Warp-MMA NT GEMM, bf16x3, 2-stage cp.async double buffer.
// splitOut: 0 -> fp32 C; 1 -> bf16 hi/lo (Chi,Clo); 2 -> single fp16 (Chi).
// CTA 128x128, K-chunk 32, 256 threads = 8 warps (4M x 2N).
// ---------------------------------------------------------------------------
#define PAD_ 40
#define TBG_ (128 * PAD_ * 2)
#define GSMEM_ (8 * TBG_)

__global__ void __launch_bounds__(256) hgemm_nt(
    const __nv_bfloat16* __restrict__ Ahi, const __nv_bfloat16* __restrict__ Alo,
    const __nv_bfloat16* __restrict__ Bhi, const __nv_bfloat16* __restrict__ Blo,
    float* __restrict__ C, __nv_bfloat16* __restrict__ Chi, __nv_bfloat16* __restrict__ Clo,
    int M, int N, int K, int lda, int ldb, int ldc, float scale, int splitOut) {
    extern __shared__ char dsm[];

    const int tid = threadIdx.x;
    const int wid = tid >> 5, lane = tid & 31;
    const int wm = wid >> 1, wn = wid & 1;
    const int bm = blockIdx.y * 128, bn = blockIdx.x * 128;

    const int la_row0 = tid >> 2, la_seg0 = (tid & 3) * 8;
    const int la_row1 = (tid + 256) >> 2, la_seg1 = ((tid + 256) & 3) * 8;

    float acc[2][8][4];
    #pragma unroll
    for (int i = 0; i < 2; i++)
        #pragma unroll
        for (int j = 0; j < 8; j++)
            #pragma unroll
            for (int r = 0; r < 4; r++) acc[i][j][r] = 0.0f;

    const int a_row = (lane & 15);
    const int a_col8 = (lane >> 4) * 8;
    const int b_rowoff = (lane & 7) + ((lane >> 4) << 3);
    const int b_col8 = ((lane >> 3) & 1) * 8;

    const int nch = K >> 5;

    auto tileb = [&](int s, int t) -> __nv_bfloat16* {
        return (__nv_bfloat16*)(dsm + (size_t)(s * 4 + t) * TBG_);
    };
    auto ldchunk = [&](int c, int s) {
        const int k0 = c << 5;
        __nv_bfloat16* ah = tileb(s, 0);
        __nv_bfloat16* al = tileb(s, 1);
        __nv_bfloat16* bh = tileb(s, 2);
        __nv_bfloat16* bl = tileb(s, 3);
        cpa16(sptr(ah + la_row0 * PAD_ + la_seg0), Ahi + (size_t)(bm + la_row0) * lda + k0 + la_seg0);
        cpa16(sptr(ah + la_row1 * PAD_ + la_seg1), Ahi + (size_t)(bm + la_row1) * lda + k0 + la_seg1);
        cpa16(sptr(al + la_row0 * PAD_ + la_seg0), Alo + (size_t)(bm + la_row0) * lda + k0 + la_seg0);
        cpa16(sptr(al + la_row1 * PAD_ + la_seg1), Alo + (size_t)(bm + la_row1) * lda + k0 + la_seg1);
        cpa16(sptr(bh + la_row0 * PAD_ + la_seg0), Bhi + (size_t)(bn + la_row0) * ldb + k0 + la_seg0);
        cpa16(sptr(bh + la_row1 * PAD_ + la_seg1), Bhi + (size_t)(bn + la_row1) * ldb + k0 + la_seg1);
        cpa16(sptr(bl + la_row0 * PAD_ + la_seg0), Blo + (size_t)(bn + la_row0) * ldb + k0 + la_seg0);
        cpa16(sptr(bl + la_row1 * PAD_ + la_seg1), Blo + (size_t)(bn + la_row1) * ldb + k0 + la_seg1);
    };

    ldchunk(0, 0);
    cpa_commit();

    for (int c = 0; c < nch; c++) {
        const int s = c & 1;
        if (c + 1 < nch) ldchunk(c + 1, (c + 1) & 1);
        cpa_commit();
        cpa_wait1();
        __syncthreads();

        __nv_bfloat16* sAh = tileb(s, 0);
        __nv_bfloat16* sAl = tileb(s, 1);
        __nv_bfloat16* sBh = tileb(s, 2);
        __nv_bfloat16* sBl = tileb(s, 3);

        #pragma unroll
        for (int ks = 0; ks < 2; ks++) {
            const int kc = ks * 16;
            uint32_t ah[2][4], al[2][4];
            #pragma unroll
            for (int mf = 0; mf < 2; mf++) {
                ldsm4(sptr(sAh + (wm * 32 + mf * 16 + a_row) * PAD_ + kc + a_col8),
                      ah[mf][0], ah[mf][1], ah[mf][2], ah[mf][3]);
                ldsm4(sptr(sAl + (wm * 32 + mf * 16 + a_row) * PAD_ + kc + a_col8),
                      al[mf][0], al[mf][1], al[mf][2], al[mf][3]);
            }
            #pragma unroll
            for (int nf2 = 0; nf2 < 4; nf2++) {
                const int brow = wn * 64 + nf2 * 16 + b_rowoff;
                uint32_t bh[4], bl[4];
                ldsm4(sptr(sBh + brow * PAD_ + kc + b_col8), bh[0], bh[1], bh[2], bh[3]);
                ldsm4(sptr(sBl + brow * PAD_ + kc + b_col8), bl[0], bl[1], bl[2], bl[3]);
                #pragma unroll
                for (int mf = 0; mf < 2; mf++) {
                    #pragma unroll
                    for (int f = 0; f < 2; f++) {
                        float* d = acc[mf][nf2 * 2 + f];
                        mma16816(d, ah[mf], bh + 2 * f);
                        mma16816(d, ah[mf], bl + 2 * f);
                        mma16816(d, al[mf], bh + 2 * f);
                    }
                }
            }
        }
        __syncthreads();
    }

    const int g = lane >> 2, t2 = (lane & 3) * 2;
    #pragma unroll
    for (int mf = 0; mf < 2; mf++) {
        #pragma unroll
        for (int nf = 0; nf < 8; nf++) {
            const int row = bm + wm * 32 + mf * 16 + g;
            const int col = bn + wn * 64 + nf * 8 + t2;
            float* d = acc[mf][nf];
            if (splitOut == 0) {
                *(float2*)(C + (size_t)row * ldc + col) = make_float2(d[0] * scale, d[1] * scale);
                *(float2*)(C + (size_t)(row + 8) * ldc + col) = make_float2(d[2] * scale, d[3] * scale);
            } else if (splitOut == 1) {
                uint32_t hp, lp;
                split_pack(d[0] * scale, d[1] * scale, hp, lp);
                *(uint32_t*)(Chi + (size_t)row * ldc + col) = hp;
                *(uint32_t*)(Clo + (size_t)row * ldc + col) = lp;
                split_pack(d[2] * scale, d[3] * scale, hp, lp);
                *(uint32_t*)(Chi + (size_t)(row + 8) * ldc + col) = hp;
                *(uint32_t*)(Clo + (size_t)(row + 8) * ldc + col) = lp;
            } else {
                __half2 o0 = __floats2half2_rn(d[0] * scale, d[1] * scale);
                __half2 o1 = __floats2half2_rn(d[2] * scale, d[3] * scale);
                *(uint32_t*)(Chi + (size_t)row * ldc + col) = *(uint32_t*)&o0;
                *(uint32_t*)(Chi + (size_t)(row + 8) * ldc + col) = *(uint32_t*)&o1;
            }
        }
    }
}

// ---------------------------------------------------------------------------
// Attention pass 1: Z[k] = sum_q exp(<k,q>/32).  fp16 q/k, SINGLE fp16 MMA.
// K tile persistent; Q tiles double-buffered via cp.async (2 stages).
// smem: K(1) + Q(2 stages) = 3 tiles + sZ  (~56 KB)
// ---------------------------------------------------------------------------
#define TP_ 72
#define TB_ (128 * TP_ * 2)

__global__ void __launch_bounds__(256) attn_stats(
    const __half* __restrict__ Kq, const __half* __restrict__ Qq,
    float* __restrict__ rZ) {
    extern __shared__ char smem[];
    __half* sK = (__half*)(smem);
    float* sZ = (float*)(smem + 3 * TB_);

    const int hh = blockIdx.y;
    const int b = hh >> 4, h = hh & 15;
    const size_t off = (size_t)b * S_ * L_ + (size_t)h * DH_;
    const int kt = blockIdx.x * 128;

    const int tid = threadIdx.x;
    const int wid = tid >> 5, lane = tid & 31;
    const int wm = wid >> 1, wn = wid & 1;
    const int a_row = (lane & 15);
    const int a_col8 = (lane >> 4) * 8;
    const int b_rowoff = (lane & 7) + ((lane >> 4) << 3);
    const int b_col8 = ((lane >> 3) & 1) * 8;
    const int g = lane >> 2;

    auto qtile = [&](int s) { return (__half*)(smem + TB_ + (size_t)s * TB_); };
    auto ld_q = [&](int c, int s) {
        const int qt = c * 128;
        __half* qp = qtile(s);
        #pragma unroll
        for (int i = 0; i < 4; i++) {
            int idx = tid + i * 256;
            int row = idx >> 3;
            int seg = (idx & 7) * 8;
            cpa16(sptr(qp + row * TP_ + seg), Qq + off + (size_t)(qt + row) * L_ + seg);
        }
    };

    // K tile direct load
    #pragma unroll
    for (int i = 0; i < 4; i++) {
        int idx = tid + i * 256;
        int row = idx >> 3;
        int seg = (idx & 7) * 8;
        *(uint4*)&sK[row * TP_ + seg] = *(const uint4*)(Kq + off + (size_t)(kt + row) * L_ + seg);
    }

    ld_q(0, 0);
    cpa_commit();

    float zp[2][2] = {};
    for (int c = 0; c < 16; c++) {
        const int s = c & 1;
        if (c + 1 < 16) ld_q(c + 1, s ^ 1);
        cpa_commit();
        cpa_wait1();
        __syncthreads();
        __half* sQ = qtile(s);

        float acc[2][8][4];
        #pragma unroll
        for (int i = 0; i < 2; i++)
            #pragma unroll
            for (int j = 0; j < 8; j++)
                #pragma unroll
                for (int r = 0; r < 4; r++) acc[i][j][r] = 0.0f;

        #pragma unroll
        for (int ks = 0; ks < 4; ks++) {
            const int kc = ks * 16;
            uint32_t ah[2][4];
            #pragma unroll
            for (int mf = 0; mf < 2; mf++)
                ldsm4(sptr(&sK[(wm * 32 + mf * 16 + a_row) * TP_ + kc + a_col8]),
                      ah[mf][0], ah[mf][1], ah[mf][2], ah[mf][3]);
            #pragma unroll
            for (int nf2 = 0; nf2 < 4; nf2++) {
                const int brow = wn * 64 + nf2 * 16 + b_rowoff;
                uint32_t bh[4];
                ldsm4(sptr(&sQ[brow * TP_ + kc + b_col8]), bh[0], bh[1], bh[2], bh[3]);
                #pragma unroll
                for (int mf = 0; mf < 2; mf++) {
                    #pragma unroll
                    for (int f = 0; f < 2; f++)
                        mma16816h(acc[mf][nf2 * 2 + f], ah[mf], bh + 2 * f);
                }
            }
        }

        #pragma unroll
        for (int mf = 0; mf < 2; mf++)
            #pragma unroll
            for (int nf = 0; nf < 8; nf++) {
                float* d = acc[mf][nf];
                zp[mf][0] += fexp32(d[0]) + fexp32(d[1]);
                zp[mf][1] += fexp32(d[2]) + fexp32(d[3]);
            }
        __syncthreads();
    }

    #pragma unroll
    for (int mf = 0; mf < 2; mf++)
        #pragma unroll
        for (int r = 0; r < 2; r++) {
            zp[mf][r] += __shfl_xor_sync(0xffffffffu, zp[mf][r], 1);
            zp[mf][r] += __shfl_xor_sync(0xffffffffu, zp[mf][r], 2);
        }

    if (tid < 128) sZ[tid] = 0.0f;
    __syncthreads();
    if ((lane & 3) == 0) {
        #pragma unroll
        for (int mf = 0; mf < 2; mf++) {
            int r0 = wm * 32 + mf * 16 + g;
            atomicAdd(&sZ[r0], zp[mf][0]);
            atomicAdd(&sZ[r0 + 8], zp[mf][1]);
        }
    }
    __syncthreads();
    if (tid < 128)
        rZ[(size_t)hh * S_ + kt + tid] = 1.0f / sZ[tid];
}

// ---------------------------------------------------------------------------
// Attention pass 2: out[q,d] = sum_k (exp(<k,q>/32) * rZ[k]) * V[k,d].
// QK via single fp16 MMA; PV via bf16x3.  K/V + rz double-buffered.
// smem: Q(1) + stages 2 x (K + Vh + Vl) = 7 tiles + rz  (~130 KB)
// ---------------------------------------------------------------------------
__global__ void __launch_bounds__(256) attn_av(
    const __half* __restrict__ Qq, const __half* __restrict__ Kq,
    const __nv_bfloat16* __restrict__ Vhi, const __nv_bfloat16* __restrict__ Vlo,
    const float* __restrict__ rZ,
    __nv_bfloat16* __restrict__ Ohi, __nv_bfloat16* __restrict__ Olo) {
    extern __shared__ char smem[];
    __half* sQ = (__half*)(smem);

    const int hh = blockIdx.y;
    const int b = hh >> 4, h = hh & 15;
    const size_t off = (size_t)b * S_ * L_ + (size_t)h * DH_;
    const int qt = blockIdx.x * 128;

    const int tid = threadIdx.x;
    const int wid = tid >> 5, lane = tid & 31;
    const int g = lane >> 2, t2 = (lane & 3) * 2;
    const int a_row = (lane & 15);
    const int a_col8 = (lane >> 4) * 8;
    const int b_rowoff = (lane & 7) + ((lane >> 4) << 3);
    const int b_col8 = ((lane >> 3) & 1) * 8;
    const int v_k = (lane & 7) + (((lane >> 3) & 1) << 3);
    const int v_d = (lane >> 4) * 8;

    auto kq  = [&](int s) { return (__half*)(smem + TB_ + (size_t)s * 3 * TB_); };
    auto vh  = [&](int s) { return (__nv_bfloat16*)(smem + 2 * TB_ + (size_t)s * 3 * TB_); };
    auto vl  = [&](int s) { return (__nv_bfloat16*)(smem + 3 * TB_ + (size_t)s * 3 * TB_); };
    float* srz = (float*)(smem + 7 * TB_);            // [2][128]

    auto ld_kv = [&](int c, int s) {
        const int kt = c * 128;
        __half* kp = kq(s);
        __nv_bfloat16* vhp = vh(s);
        __nv_bfloat16* vlp = vl(s);
        #pragma unroll
        for (int i = 0; i < 4; i++) {
            int idx = tid + i * 256;
            int row = idx >> 3;
            int seg = (idx & 7) * 8;
            cpa16(sptr(kp + row * TP_ + seg), Kq + off + (size_t)(kt + row) * L_ + seg);
            cpa16(sptr(vhp + row * TP_ + seg), Vhi + off + (size_t)(kt + row) * L_ + seg);
            cpa16(sptr(vlp + row * TP_ + seg), Vlo + off + (size_t)(kt + row) * L_ + seg);
        }
        if (tid < 32)
            cpa16(sptr(srz + s * 128 + tid * 4), rZ + (size_t)hh * S_ + kt + tid * 4);
    };

    // Q tile direct load
    #pragma unroll
    for (int i = 0; i < 4; i++) {
        int idx = tid + i * 256;
        int row = idx >> 3;
        int seg = (idx & 7) * 8;
        *(uint4*)&sQ[row * TP_ + seg] = *(const uint4*)(Qq + off + (size_t)(qt + row) * L_ + seg);
    }

    ld_kv(0, 0);
    cpa_commit();

    float avacc[8][4];
    #pragma unroll
    for (int j = 0; j < 8; j++)
        #pragma unroll
        for (int r = 0; r < 4; r++) avacc[j][r] = 0.0f;

    const int wq = wid * 16;

    for (int c = 0; c < 16; c++) {
        const int s = c & 1;
        if (c + 1 < 16) ld_kv(c + 1, s ^ 1);
        cpa_commit();
        cpa_wait1();
        __syncthreads();
        __half* sK = kq(s);
        __nv_bfloat16* sVh = vh(s);
        __nv_bfloat16* sVl = vl(s);
        const float* rz = srz + s * 128;

        #pragma unroll
        for (int khalf = 0; khalf < 2; khalf++) {
            float sacc[8][4];
            #pragma unroll
            for (int j = 0; j < 8; j++)
                #pragma unroll
                for (int r = 0; r < 4; r++) sacc[j][r] = 0.0f;

            #pragma unroll
            for (int ks = 0; ks < 4; ks++) {
                const int kc = ks * 16;
                uint32_t ah[4];
                ldsm4(sptr(&sQ[(wq + a_row) * TP_ + kc + a_col8]), ah[0], ah[1], ah[2], ah[3]);
                #pragma unroll
                for (int nf2 = 0; nf2 < 4; nf2++) {
                    const int brow = khalf * 64 + nf2 * 16 + b_rowoff;
                    uint32_t bh[4];
                    ldsm4(sptr(&sK[brow * TP_ + kc + b_col8]), bh[0], bh[1], bh[2], bh[3]);
                    #pragma unroll
                    for (int f = 0; f < 2; f++)
                        mma16816h(sacc[nf2 * 2 + f], ah, bh + 2 * f);
                }
            }

            uint32_t pah[4][4], pal[4][4];
            #pragma unroll
            for (int j = 0; j < 4; j++) {
                #pragma unroll
                for (int e = 0; e < 2; e++) {
                    float* d = sacc[2 * j + e];
                    const int col = khalf * 64 + j * 16 + e * 8 + t2;
                    float r0 = rz[col], r1 = rz[col + 1];
                    float p0 = fexp32(d[0]) * r0;
                    float p1 = fexp32(d[1]) * r1;
                    float p2 = fexp32(d[2]) * r0;
                    float p3 = fexp32(d[3]) * r1;
                    split_pack(p0, p1, pah[j][2 * e + 0], pal[j][2 * e + 0]);
                    split_pack(p2, p3, pah[j][2 * e + 1], pal[j][2 * e + 1]);
                }
            }

            #pragma unroll
            for (int j = 0; j < 4; j++) {
                const int kbase = khalf * 64 + j * 16;
                #pragma unroll
                for (int nb = 0; nb < 4; nb++) {
                    uint32_t bvh[4], bvl[4];
                    ldsm4t(sptr(&sVh[(kbase + v_k) * TP_ + nb * 16 + v_d]),
                           bvh[0], bvh[1], bvh[2], bvh[3]);
                    ldsm4t(sptr(&sVl[(kbase + v_k) * TP_ + nb * 16 + v_d]),
                           bvl[0], bvl[1], bvl[2], bvl[3]);
                    #pragma unroll
                    for (int f = 0; f < 2; f++) {
                        float* d = avacc[nb * 2 + f];
                        mma16816(d, pah[j], bvh + 2 * f);
                        mma16816(d, pah[j], bvl + 2 * f);
                        mma16816(d, pal[j], bvh + 2 * f);
                    }
                }
            }
        }
        __syncthreads();
    }

    #pragma unroll
    for (int nf = 0; nf < 8; nf++) {
        const int row = qt + wq + g;
        const int col = nf * 8 + t2;
        float* d = avacc[nf];
        uint32_t hp, lp;
        split_pack(d[0], d[1], hp, lp);
        *(uint32_t*)(Ohi + off + (size_t)row * L_ + col) = hp;
        *(uint32_t*)(Olo + off + (size_t)row * L_ + col) = lp;
        split_pack(d[2], d[3], hp, lp);
        *(uint32_t*)(Ohi + off + (size_t)(row + 8) * L_ + col) = hp;
        *(uint32_t*)(Olo + off + (size_t)(row + 8) * L_ + col) = lp;
    }
}

// ---------------------------------------------------------------------------
// fp32 -> bf16 hi/lo split (element-wise)
// ---------------------------------------------------------------------------
__global__ void __launch_bounds__(256) split_kernel(const float* __restrict__ A,
                                                    __nv_bfloat16* __restrict__ Hi,
                                                    __nv_bfloat16* __restrict__ Lo) {
    size_t i = ((size_t)blockIdx.x * 256 + threadIdx.x) * 4;
    float4 a = *(const float4*)(A + i);
    __nv_bfloat16 h0, l0, h1, l1, h2, l2, h3, l3;
    split1(a.x, h0, l0); split1(a.y, h1, l1);
    split1(a.z, h2, l2); split1(a.w, h3, l3);
    __nv_bfloat162* hp = (__nv_bfloat162*)(Hi + i);
    __nv_bfloat162* lp = (__nv_bfloat162*)(Lo + i);
    hp[0] = __nv_bfloat162(h0, h1); hp[1] = __nv_bfloat162(h2, h3);
    lp[0] = __nv_bfloat162(l0, l1); lp[1] = __nv_bfloat162(l2, l3);
}

// W[K,N] -> Wt hi/lo [N,K]
__global__ void __launch_bounds__(256) transpose_split(const float* __restrict__ W,
                                                       __nv_bfloat16* __restrict__ Th,
                                                       __nv_bfloat16* __restrict__ Tl,
                                                       int K, int N) {
    __shared__ float t[32][33];
    const int k0 = blockIdx.y * 32, n0 = blockIdx.x * 32;
    const int tx = threadIdx.x & 31, ty = threadIdx.x >> 5;
    #pragma unroll
    for (int j = 0; j < 4; j++) {
        int row = ty + j * 8;
        t[row][tx] = W[(size_t)(k0 + row) * N + n0 + tx];
    }
    __syncthreads();
    #pragma unroll
    for (int j = 0; j < 4; j++) {
        int row = ty + j * 8;
        float v = t[tx][row];
        __nv_bfloat16 h, l; split1(v, h, l);
        size_t o = (size_t)(n0 + row) * K + k0 + tx;
        Th[o] = h; Tl[o] = l;
    }
}

// ---------------------------------------------------------------------------
// Row L2 normalize -> bf16 hi/lo split
// ---------------------------------------------------------------------------
__global__ void __launch_bounds__(256) l2norm_split(const float* __restrict__ Z,
                                                    __nv_bfloat16* __restrict__ Hi,
                                                    __nv_bfloat16* __restrict__ Lo) {
    __shared__ float shs[8];
    const size_t row = blockIdx.x;
    const float* p = Z + row * (size_t)D_;
    const int tid = threadIdx.x;
    const int lane = tid & 31, wid = tid >> 5;
    float4 v = *(const float4*)(p + tid * 4);
    float ss = v.x * v.x + v.y * v.y + v.z * v.z + v.w * v.w;
    #pragma unroll
    for (int o = 16; o; o >>= 1) ss += __shfl_xor_sync(0xffffffffu, ss, o);
    if (lane == 0) shs[wid] = ss;
    __syncthreads();
    ss = shs[0];
    #pragma unroll
    for (int i = 1; i < 8; i++) ss += shs[i];
    const float sc = 1.0f / fmaxf(sqrtf(ss), 1e-12f);
    float y0 = v.x * sc, y1 = v.y * sc, y2 = v.z * sc, y3 = v.w * sc;
    __nv_bfloat16 h0, l0, h1, l1, h2, l2, h3, l3;
    split1(y0, h0, l0); split1(y1, h1, l1);
    split1(y2, h2, l2); split1(y3, h3, l3);
    size_t o = row * (size_t)D_ + tid * 4;
    __nv_bfloat162* hp = (__nv_bfloat162*)(Hi + o);
    __nv_bfloat162* lp = (__nv_bfloat162*)(Lo + o);
    hp[0] = __nv_bfloat162(h0, h1); hp[1] = __nv_bfloat162(h2, h3);
    lp[0] = __nv_bfloat162(l0, l1); lp[1] = __nv_bfloat162(l2, l3);
}

// ---------------------------------------------------------------------------
// Row L2 normalize + exact GELU, writes to output
// ---------------------------------------------------------------------------
__global__ void __launch_bounds__(256) l2norm_gelu(const float* __restrict__ Z,
                                                   float* __restrict__ O) {
    __shared__ float shs[8];
    const size_t row = blockIdx.x;
    const float* p = Z + row * (size_t)D_;
    float* q = O + row * (size_t)D_;
    const int tid = threadIdx.x;
    const int lane = tid & 31, wid = tid >> 5;
    float4 v = *(const float4*)(p + tid * 4);
    float ss = v.x * v.x + v.y * v.y + v.z * v.z + v.w * v.w;
    #pragma unroll
    for (int o = 16; o; o >>= 1) ss += __shfl_xor_sync(0xffffffffu, ss, o);
    if (lane == 0) shs[wid] = ss;
    __syncthreads();
    ss = shs[0];
    #pragma unroll
    for (int i = 1; i < 8; i++) ss += shs[i];
    const float sc = 1.0f / fmaxf(sqrtf(ss), 1e-12f);
    float y0 = v.x * sc, y1 = v.y * sc, y2 = v.z * sc, y3 = v.w * sc;
    const float inv_sqrt2 = 0.70710678118654752f;
    float4 g;
    g.x = 0.5f * y0 * (1.0f + erff(y0 * inv_sqrt2));
    g.y = 0.5f * y1 * (1.0f + erff(y1 * inv_sqrt2));
    g.z = 0.5f * y2 * (1.0f + erff(y2 * inv_sqrt2));
    g.w = 0.5f * y3 * (1.0f + erff(y3 * inv_sqrt2));
    *(float4*)(q + tid * 4) = g;
}

// ---------------------------------------------------------------------------
// Launch
// ---------------------------------------------------------------------------
extern "C" void kernel_launch(void* const* d_in, const int* in_sizes, int n_in,
                              void* d_out, int out_size) {
    (void)in_sizes; (void)n_in; (void)out_size;
    const float* x   = (const float*)d_in[0];
    const float* Wq  = (const float*)d_in[1];
    const float* Wk  = (const float*)d_in[2];
    const float* Wv  = (const float*)d_in[3];
    const float* Wo  = (const float*)d_in[4];
    const float* Wff = (const float*)d_in[5];

    float *z1, *z2, *rz;
    cudaGetSymbolAddress((void**)&z1, g_z1);
    cudaGetSymbolAddress((void**)&z2, g_z2);
    cudaGetSymbolAddress((void**)&rz, g_rz);

    __nv_bfloat16 *xhi, *xlo, *vhi, *vlo, *aohi, *aolo, *z1hi, *z1lo, *wth, *wtl;
    __half *q16, *k16;
    cudaGetSymbolAddress((void**)&xhi,  g_xhi);
    cudaGetSymbolAddress((void**)&xlo,  g_xlo);
    cudaGetSymbolAddress((void**)&q16,  g_q16);
    cudaGetSymbolAddress((void**)&k16,  g_k16);
    cudaGetSymbolAddress((void**)&vhi,  g_vhi);
    cudaGetSymbolAddress((void**)&vlo,  g_vlo);
    cudaGetSymbolAddress((void**)&aohi, g_aohi);
    cudaGetSymbolAddress((void**)&aolo, g_aolo);
    cudaGetSymbolAddress((void**)&z1hi, g_z1hi);
    cudaGetSymbolAddress((void**)&z1lo, g_z1lo);
    cudaGetSymbolAddress((void**)&wth,  g_wt_hi);
    cudaGetSymbolAddress((void**)&wtl,  g_wt_lo);
    const size_t WSTR = (size_t)D_ * L_;

    const int SMEM1 = 3 * TB_ + 512;
    const int SMEM2 = 7 * TB_ + 1024;
    cudaFuncSetAttribute(hgemm_nt,   cudaFuncAttributeMaxDynamicSharedMemorySize, GSMEM_);
    cudaFuncSetAttribute(attn_stats, cudaFuncAttributeMaxDynamicSharedMemorySize, SMEM1);
    cudaFuncSetAttribute(attn_av,    cudaFuncAttributeMaxDynamicSharedMemorySize, SMEM2);

    const dim3 blk(256);
    const dim3 gT(L_ / 32, D_ / 32);

    split_kernel<<<(M4_ * D_) / 1024, blk>>>(x, xhi, xlo);
    transpose_split<<<gT, blk>>>(Wq,  wth + 0 * WSTR, wtl + 0 * WSTR, D_, L_);
    transpose_split<<<gT, blk>>>(Wk,  wth + 1 * WSTR, wtl + 1 * WSTR, D_, L_);
    transpose_split<<<gT, blk>>>(Wv,  wth + 2 * WSTR, wtl + 2 * WSTR, D_, L_);
    transpose_split<<<gT, blk>>>(Wo,  wth + 3 * WSTR, wtl + 3 * WSTR, L_, D_);
    transpose_split<<<gT, blk>>>(Wff, wth + 4 * WSTR, wtl + 4 * WSTR, D_, D_);

    const dim3 gG(L_ / 128, M4_ / 128, 1);

    // QKV projections: q,k -> single fp16 (mode 2); v -> bf16 hi/lo (mode 1)
    hgemm_nt<<<gG, blk, GSMEM_>>>(xhi, xlo, wth + 0 * WSTR, wtl + 0 * WSTR, z1,
                                  (__nv_bfloat16*)q16, (__nv_bfloat16*)0,
                                  M4_, L_, D_, D_, D_, L_, 1.0f, 2);
    hgemm_nt<<<gG, blk, GSMEM_>>>(xhi, xlo, wth + 1 * WSTR, wtl + 1 * WSTR, z1,
                                  (__nv_bfloat16*)k16, (__nv_bfloat16*)0,
                                  M4_, L_, D_, D_, D_, L_, 1.0f, 2);
    hgemm_nt<<<gG, blk, GSMEM_>>>(xhi, xlo, wth + 2 * WSTR, wtl + 2 * WSTR, z1, vhi, vlo,
                                  M4_, L_, D_, D_, D_, L_, 1.0f, 1);

    // fused attention (two-pass; fp16 QK single-MMA, bf16x3 PV)
    attn_stats<<<dim3(16, 32), blk, SMEM1>>>(k16, q16, rz);
    attn_av<<<dim3(16, 32), blk, SMEM2>>>(q16, k16, vhi, vlo, rz, aohi, aolo);

    // output projection
    hgemm_nt<<<gG, blk, GSMEM_>>>(aohi, aolo, wth + 3 * WSTR, wtl + 3 * WSTR, z1,
                                  (__nv_bfloat16*)0, (__nv_bfloat16*)0,
                                  M4_, D_, L_, L_, L_, D_, 1.0f, 0);

    // FFN
    l2norm_split<<<M4_, blk>>>(z1, z1hi, z1lo);
    hgemm_nt<<<gG, blk, GSMEM_>>>(z1hi, z1lo, wth + 4 * WSTR, wtl + 4 * WSTR, z2,
                                  (__nv_bfloat16*)0, (__nv_bfloat16*)0,
                                  M4_, D_, D_, D_, D_, D_, 1.0f, 0);
    l2norm_gelu<<<M4_, blk>>>(z2, (float*)d_out);
}

// round 17
// speedup vs baseline: 4.3574x; 1.5187x over previous
#include <cuda_runtime.h>
#include <cuda_bf16.h>
#include <cuda_fp16.h>
#include <math.h>
#include <stdint.h>

// Problem dims (fixed by the dataset)
#define B_  2
#define S_  2048
#define D_  1024
#define L_  1024
#define H_  16
#define DH_ 64
#define BH_ (B_ * H_)          // 32
#define M4_ (B_ * S_)          // 4096

// ---------------------------------------------------------------------------
// Scratch
// ---------------------------------------------------------------------------
__device__ float g_z1[(size_t)M4_ * D_];
__device__ float g_z2[(size_t)M4_ * D_];
__device__ float g_rz[(size_t)BH_ * S_];            // 1/Z per (head, k)

__device__ unsigned short g_x16[(size_t)M4_ * D_];  // x as fp16
__device__ unsigned short g_q16[(size_t)M4_ * L_];
__device__ unsigned short g_k16[(size_t)M4_ * L_];
__device__ unsigned short g_v16[(size_t)M4_ * L_];
__device__ unsigned short g_aohi[(size_t)M4_ * L_];
__device__ unsigned short g_aolo[(size_t)M4_ * L_];
__device__ unsigned short g_z1hi[(size_t)M4_ * D_];
__device__ unsigned short g_z1lo[(size_t)M4_ * D_];
__device__ unsigned short g_wt16[3][(size_t)D_ * L_];    // Wq,Wk,Wv transposed fp16
__device__ unsigned short g_wt_hi[2][(size_t)D_ * L_];   // Wo,Wff transposed bf16 hi
__device__ unsigned short g_wt_lo[2][(size_t)D_ * L_];   // Wo,Wff transposed bf16 lo

// ---------------------------------------------------------------------------
// helpers
// ---------------------------------------------------------------------------
__device__ __forceinline__ uint32_t sptr(const void* p) {
    return (uint32_t)__cvta_generic_to_shared(p);
}
__device__ __forceinline__ void cpa16(uint32_t saddr, const void* g) {
    asm volatile("cp.async.cg.shared.global [%0], [%1], 16;" :: "r"(saddr), "l"(g));
}
__device__ __forceinline__ void cpa_commit() {
    asm volatile("cp.async.commit_group;" ::: "memory");
}
__device__ __forceinline__ void cpa_wait1() {
    asm volatile("cp.async.wait_group 1;" ::: "memory");
}
__device__ __forceinline__ void ldsm4(uint32_t a, uint32_t& r0, uint32_t& r1,
                                      uint32_t& r2, uint32_t& r3) {
    asm volatile("ldmatrix.sync.aligned.m8n8.x4.shared.b16 {%0,%1,%2,%3}, [%4];"
                 : "=r"(r0), "=r"(r1), "=r"(r2), "=r"(r3) : "r"(a));
}
__device__ __forceinline__ void ldsm4t(uint32_t a, uint32_t& r0, uint32_t& r1,
                                       uint32_t& r2, uint32_t& r3) {
    asm volatile("ldmatrix.sync.aligned.m8n8.x4.trans.shared.b16 {%0,%1,%2,%3}, [%4];"
                 : "=r"(r0), "=r"(r1), "=r"(r2), "=r"(r3) : "r"(a));
}
// bf16 MMA
__device__ __forceinline__ void mma16816(float* d, const uint32_t* a, const uint32_t* b) {
    asm volatile(
        "mma.sync.aligned.m16n8k16.row.col.f32.bf16.bf16.f32 "
        "{%0,%1,%2,%3}, {%4,%5,%6,%7}, {%8,%9}, {%0,%1,%2,%3};"
        : "+f"(d[0]), "+f"(d[1]), "+f"(d[2]), "+f"(d[3])
        : "r"(a[0]), "r"(a[1]), "r"(a[2]), "r"(a[3]), "r"(b[0]), "r"(b[1]));
}
// fp16 MMA (same fragment layout)
__device__ __forceinline__ void mma16816h(float* d, const uint32_t* a, const uint32_t* b) {
    asm volatile(
        "mma.sync.aligned.m16n8k16.row.col.f32.f16.f16.f32 "
        "{%0,%1,%2,%3}, {%4,%5,%6,%7}, {%8,%9}, {%0,%1,%2,%3};"
        : "+f"(d[0]), "+f"(d[1]), "+f"(d[2]), "+f"(d[3])
        : "r"(a[0]), "r"(a[1]), "r"(a[2]), "r"(a[3]), "r"(b[0]), "r"(b[1]));
}
__device__ __forceinline__ void split1(float a, __nv_bfloat16& h, __nv_bfloat16& l) {
    h = __float2bfloat16(a);
    l = __float2bfloat16(a - __bfloat162float(h));
}
__device__ __forceinline__ void split_pack(float x, float y, uint32_t& hi, uint32_t& lo) {
    __nv_bfloat16 hx, lx, hy, ly;
    split1(x, hx, lx); split1(y, hy, ly);
    __nv_bfloat162 Hp(hx, hy), Lp(lx, ly);
    hi = *(uint32_t*)&Hp; lo = *(uint32_t*)&Lp;
}
// exp(s/32) via MUFU
#define EXPC_ (1.4426950408889634f / 32.0f)
__device__ __forceinline__ float fexp32(float s) {
    float y;
    asm("ex2.approx.f32 %0, %1;" : "=f"(y) : "f"(s * EXPC_));
    return y;
}

#define PAD_ 40
#define TBG_ (128 * PAD_ * 2)

// ---------------------------------------------------------------------------
// Pure-fp16 NT GEMM, single MMA, 2-stage cp.async.  C fp16.
// CTA 128x128, K-chunk 32, 256 threads = 8 warps (4M x 2N).
// smem: 2 stages x 2 tiles = 40 KB
// ---------------------------------------------------------------------------
#define GSMEM16_ (4 * TBG_)

__global__ void __launch_bounds__(256) hgemm_f16(
    const __half* __restrict__ A, const __half* __restrict__ Bt,
    __half* __restrict__ C, int M, int N, int K, int lda, int ldb, int ldc) {
    extern __shared__ char dsm[];

    const int tid = threadIdx.x;
    const int wid = tid >> 5, lane = tid & 31;
    const int wm = wid >> 1, wn = wid & 1;
    const int bm = blockIdx.y * 128, bn = blockIdx.x * 128;

    const int la_row0 = tid >> 2, la_seg0 = (tid & 3) * 8;
    const int la_row1 = (tid + 256) >> 2, la_seg1 = ((tid + 256) & 3) * 8;

    float acc[2][8][4];
    #pragma unroll
    for (int i = 0; i < 2; i++)
        #pragma unroll
        for (int j = 0; j < 8; j++)
            #pragma unroll
            for (int r = 0; r < 4; r++) acc[i][j][r] = 0.0f;

    const int a_row = (lane & 15);
    const int a_col8 = (lane >> 4) * 8;
    const int b_rowoff = (lane & 7) + ((lane >> 4) << 3);
    const int b_col8 = ((lane >> 3) & 1) * 8;

    const int nch = K >> 5;

    auto tileb = [&](int s, int t) -> __half* {
        return (__half*)(dsm + (size_t)(s * 2 + t) * TBG_);
    };
    auto ldchunk = [&](int c, int s) {
        const int k0 = c << 5;
        __half* a = tileb(s, 0);
        __half* b = tileb(s, 1);
        cpa16(sptr(a + la_row0 * PAD_ + la_seg0), A + (size_t)(bm + la_row0) * lda + k0 + la_seg0);
        cpa16(sptr(a + la_row1 * PAD_ + la_seg1), A + (size_t)(bm + la_row1) * lda + k0 + la_seg1);
        cpa16(sptr(b + la_row0 * PAD_ + la_seg0), Bt + (size_t)(bn + la_row0) * ldb + k0 + la_seg0);
        cpa16(sptr(b + la_row1 * PAD_ + la_seg1), Bt + (size_t)(bn + la_row1) * ldb + k0 + la_seg1);
    };

    ldchunk(0, 0);
    cpa_commit();

    for (int c = 0; c < nch; c++) {
        const int s = c & 1;
        if (c + 1 < nch) ldchunk(c + 1, (c + 1) & 1);
        cpa_commit();
        cpa_wait1();
        __syncthreads();

        __half* sA = tileb(s, 0);
        __half* sB = tileb(s, 1);

        #pragma unroll
        for (int ks = 0; ks < 2; ks++) {
            const int kc = ks * 16;
            uint32_t ah[2][4];
            #pragma unroll
            for (int mf = 0; mf < 2; mf++)
                ldsm4(sptr(sA + (wm * 32 + mf * 16 + a_row) * PAD_ + kc + a_col8),
                      ah[mf][0], ah[mf][1], ah[mf][2], ah[mf][3]);
            #pragma unroll
            for (int nf2 = 0; nf2 < 4; nf2++) {
                const int brow = wn * 64 + nf2 * 16 + b_rowoff;
                uint32_t bh[4];
                ldsm4(sptr(sB + brow * PAD_ + kc + b_col8), bh[0], bh[1], bh[2], bh[3]);
                #pragma unroll
                for (int mf = 0; mf < 2; mf++)
                    #pragma unroll
                    for (int f = 0; f < 2; f++)
                        mma16816h(acc[mf][nf2 * 2 + f], ah[mf], bh + 2 * f);
            }
        }
        __syncthreads();
    }

    const int g = lane >> 2, t2 = (lane & 3) * 2;
    #pragma unroll
    for (int mf = 0; mf < 2; mf++) {
        #pragma unroll
        for (int nf = 0; nf < 8; nf++) {
            const int row = bm + wm * 32 + mf * 16 + g;
            const int col = bn + wn * 64 + nf * 8 + t2;
            float* d = acc[mf][nf];
            __half2 o0 = __floats2half2_rn(d[0], d[1]);
            __half2 o1 = __floats2half2_rn(d[2], d[3]);
            *(uint32_t*)(C + (size_t)row * ldc + col) = *(uint32_t*)&o0;
            *(uint32_t*)(C + (size_t)(row + 8) * ldc + col) = *(uint32_t*)&o1;
        }
    }
}

// ---------------------------------------------------------------------------
// Warp-MMA NT GEMM, bf16x3, 2-stage cp.async (Wo / Wff path).
// splitOut: 0 -> fp32 C; 1 -> bf16 hi/lo (Chi,Clo).
// ---------------------------------------------------------------------------
#define GSMEM_ (8 * TBG_)

__global__ void __launch_bounds__(256) hgemm_nt(
    const __nv_bfloat16* __restrict__ Ahi, const __nv_bfloat16* __restrict__ Alo,
    const __nv_bfloat16* __restrict__ Bhi, const __nv_bfloat16* __restrict__ Blo,
    float* __restrict__ C, __nv_bfloat16* __restrict__ Chi, __nv_bfloat16* __restrict__ Clo,
    int M, int N, int K, int lda, int ldb, int ldc, float scale, int splitOut) {
    extern __shared__ char dsm[];

    const int tid = threadIdx.x;
    const int wid = tid >> 5, lane = tid & 31;
    const int wm = wid >> 1, wn = wid & 1;
    const int bm = blockIdx.y * 128, bn = blockIdx.x * 128;

    const int la_row0 = tid >> 2, la_seg0 = (tid & 3) * 8;
    const int la_row1 = (tid + 256) >> 2, la_seg1 = ((tid + 256) & 3) * 8;

    float acc[2][8][4];
    #pragma unroll
    for (int i = 0; i < 2; i++)
        #pragma unroll
        for (int j = 0; j < 8; j++)
            #pragma unroll
            for (int r = 0; r < 4; r++) acc[i][j][r] = 0.0f;

    const int a_row = (lane & 15);
    const int a_col8 = (lane >> 4) * 8;
    const int b_rowoff = (lane & 7) + ((lane >> 4) << 3);
    const int b_col8 = ((lane >> 3) & 1) * 8;

    const int nch = K >> 5;

    auto tileb = [&](int s, int t) -> __nv_bfloat16* {
        return (__nv_bfloat16*)(dsm + (size_t)(s * 4 + t) * TBG_);
    };
    auto ldchunk = [&](int c, int s) {
        const int k0 = c << 5;
        __nv_bfloat16* ah = tileb(s, 0);
        __nv_bfloat16* al = tileb(s, 1);
        __nv_bfloat16* bh = tileb(s, 2);
        __nv_bfloat16* bl = tileb(s, 3);
        cpa16(sptr(ah + la_row0 * PAD_ + la_seg0), Ahi + (size_t)(bm + la_row0) * lda + k0 + la_seg0);
        cpa16(sptr(ah + la_row1 * PAD_ + la_seg1), Ahi + (size_t)(bm + la_row1) * lda + k0 + la_seg1);
        cpa16(sptr(al + la_row0 * PAD_ + la_seg0), Alo + (size_t)(bm + la_row0) * lda + k0 + la_seg0);
        cpa16(sptr(al + la_row1 * PAD_ + la_seg1), Alo + (size_t)(bm + la_row1) * lda + k0 + la_seg1);
        cpa16(sptr(bh + la_row0 * PAD_ + la_seg0), Bhi + (size_t)(bn + la_row0) * ldb + k0 + la_seg0);
        cpa16(sptr(bh + la_row1 * PAD_ + la_seg1), Bhi + (size_t)(bn + la_row1) * ldb + k0 + la_seg1);
        cpa16(sptr(bl + la_row0 * PAD_ + la_seg0), Blo + (size_t)(bn + la_row0) * ldb + k0 + la_seg0);
        cpa16(sptr(bl + la_row1 * PAD_ + la_seg1), Blo + (size_t)(bn + la_row1) * ldb + k0 + la_seg1);
    };

    ldchunk(0, 0);
    cpa_commit();

    for (int c = 0; c < nch; c++) {
        const int s = c & 1;
        if (c + 1 < nch) ldchunk(c + 1, (c + 1) & 1);
        cpa_commit();
        cpa_wait1();
        __syncthreads();

        __nv_bfloat16* sAh = tileb(s, 0);
        __nv_bfloat16* sAl = tileb(s, 1);
        __nv_bfloat16* sBh = tileb(s, 2);
        __nv_bfloat16* sBl = tileb(s, 3);

        #pragma unroll
        for (int ks = 0; ks < 2; ks++) {
            const int kc = ks * 16;
            uint32_t ah[2][4], al[2][4];
            #pragma unroll
            for (int mf = 0; mf < 2; mf++) {
                ldsm4(sptr(sAh + (wm * 32 + mf * 16 + a_row) * PAD_ + kc + a_col8),
                      ah[mf][0], ah[mf][1], ah[mf][2], ah[mf][3]);
                ldsm4(sptr(sAl + (wm * 32 + mf * 16 + a_row) * PAD_ + kc + a_col8),
                      al[mf][0], al[mf][1], al[mf][2], al[mf][3]);
            }
            #pragma unroll
            for (int nf2 = 0; nf2 < 4; nf2++) {
                const int brow = wn * 64 + nf2 * 16 + b_rowoff;
                uint32_t bh[4], bl[4];
                ldsm4(sptr(sBh + brow * PAD_ + kc + b_col8), bh[0], bh[1], bh[2], bh[3]);
                ldsm4(sptr(sBl + brow * PAD_ + kc + b_col8), bl[0], bl[1], bl[2], bl[3]);
                #pragma unroll
                for (int mf = 0; mf < 2; mf++) {
                    #pragma unroll
                    for (int f = 0; f < 2; f++) {
                        float* d = acc[mf][nf2 * 2 + f];
                        mma16816(d, ah[mf], bh + 2 * f);
                        mma16816(d, ah[mf], bl + 2 * f);
                        mma16816(d, al[mf], bh + 2 * f);
                    }
                }
            }
        }
        __syncthreads();
    }

    const int g = lane >> 2, t2 = (lane & 3) * 2;
    #pragma unroll
    for (int mf = 0; mf < 2; mf++) {
        #pragma unroll
        for (int nf = 0; nf < 8; nf++) {
            const int row = bm + wm * 32 + mf * 16 + g;
            const int col = bn + wn * 64 + nf * 8 + t2;
            float* d = acc[mf][nf];
            if (splitOut == 0) {
                *(float2*)(C + (size_t)row * ldc + col) = make_float2(d[0] * scale, d[1] * scale);
                *(float2*)(C + (size_t)(row + 8) * ldc + col) = make_float2(d[2] * scale, d[3] * scale);
            } else {
                uint32_t hp, lp;
                split_pack(d[0] * scale, d[1] * scale, hp, lp);
                *(uint32_t*)(Chi + (size_t)row * ldc + col) = hp;
                *(uint32_t*)(Clo + (size_t)row * ldc + col) = lp;
                split_pack(d[2] * scale, d[3] * scale, hp, lp);
                *(uint32_t*)(Chi + (size_t)(row + 8) * ldc + col) = hp;
                *(uint32_t*)(Clo + (size_t)(row + 8) * ldc + col) = lp;
            }
        }
    }
}

// ---------------------------------------------------------------------------
// Attention pass 1: Z[k] = sum_q exp(<k,q>/32).  fp16 q/k, single fp16 MMA.
// ---------------------------------------------------------------------------
#define TP_ 72
#define TB_ (128 * TP_ * 2)

__global__ void __launch_bounds__(256) attn_stats(
    const __half* __restrict__ Kq, const __half* __restrict__ Qq,
    float* __restrict__ rZ) {
    extern __shared__ char smem[];
    __half* sK = (__half*)(smem);
    float* sZ = (float*)(smem + 3 * TB_);

    const int hh = blockIdx.y;
    const int b = hh >> 4, h = hh & 15;
    const size_t off = (size_t)b * S_ * L_ + (size_t)h * DH_;
    const int kt = blockIdx.x * 128;

    const int tid = threadIdx.x;
    const int wid = tid >> 5, lane = tid & 31;
    const int wm = wid >> 1, wn = wid & 1;
    const int a_row = (lane & 15);
    const int a_col8 = (lane >> 4) * 8;
    const int b_rowoff = (lane & 7) + ((lane >> 4) << 3);
    const int b_col8 = ((lane >> 3) & 1) * 8;
    const int g = lane >> 2;

    auto qtile = [&](int s) { return (__half*)(smem + TB_ + (size_t)s * TB_); };
    auto ld_q = [&](int c, int s) {
        const int qt = c * 128;
        __half* qp = qtile(s);
        #pragma unroll
        for (int i = 0; i < 4; i++) {
            int idx = tid + i * 256;
            int row = idx >> 3;
            int seg = (idx & 7) * 8;
            cpa16(sptr(qp + row * TP_ + seg), Qq + off + (size_t)(qt + row) * L_ + seg);
        }
    };

    #pragma unroll
    for (int i = 0; i < 4; i++) {
        int idx = tid + i * 256;
        int row = idx >> 3;
        int seg = (idx & 7) * 8;
        *(uint4*)&sK[row * TP_ + seg] = *(const uint4*)(Kq + off + (size_t)(kt + row) * L_ + seg);
    }

    ld_q(0, 0);
    cpa_commit();

    float zp[2][2] = {};
    for (int c = 0; c < 16; c++) {
        const int s = c & 1;
        if (c + 1 < 16) ld_q(c + 1, s ^ 1);
        cpa_commit();
        cpa_wait1();
        __syncthreads();
        __half* sQ = qtile(s);

        float acc[2][8][4];
        #pragma unroll
        for (int i = 0; i < 2; i++)
            #pragma unroll
            for (int j = 0; j < 8; j++)
                #pragma unroll
                for (int r = 0; r < 4; r++) acc[i][j][r] = 0.0f;

        #pragma unroll
        for (int ks = 0; ks < 4; ks++) {
            const int kc = ks * 16;
            uint32_t ah[2][4];
            #pragma unroll
            for (int mf = 0; mf < 2; mf++)
                ldsm4(sptr(&sK[(wm * 32 + mf * 16 + a_row) * TP_ + kc + a_col8]),
                      ah[mf][0], ah[mf][1], ah[mf][2], ah[mf][3]);
            #pragma unroll
            for (int nf2 = 0; nf2 < 4; nf2++) {
                const int brow = wn * 64 + nf2 * 16 + b_rowoff;
                uint32_t bh[4];
                ldsm4(sptr(&sQ[brow * TP_ + kc + b_col8]), bh[0], bh[1], bh[2], bh[3]);
                #pragma unroll
                for (int mf = 0; mf < 2; mf++)
                    #pragma unroll
                    for (int f = 0; f < 2; f++)
                        mma16816h(acc[mf][nf2 * 2 + f], ah[mf], bh + 2 * f);
            }
        }

        #pragma unroll
        for (int mf = 0; mf < 2; mf++)
            #pragma unroll
            for (int nf = 0; nf < 8; nf++) {
                float* d = acc[mf][nf];
                zp[mf][0] += fexp32(d[0]) + fexp32(d[1]);
                zp[mf][1] += fexp32(d[2]) + fexp32(d[3]);
            }
        __syncthreads();
    }

    #pragma unroll
    for (int mf = 0; mf < 2; mf++)
        #pragma unroll
        for (int r = 0; r < 2; r++) {
            zp[mf][r] += __shfl_xor_sync(0xffffffffu, zp[mf][r], 1);
            zp[mf][r] += __shfl_xor_sync(0xffffffffu, zp[mf][r], 2);
        }

    if (tid < 128) sZ[tid] = 0.0f;
    __syncthreads();
    if ((lane & 3) == 0) {
        #pragma unroll
        for (int mf = 0; mf < 2; mf++) {
            int r0 = wm * 32 + mf * 16 + g;
            atomicAdd(&sZ[r0], zp[mf][0]);
            atomicAdd(&sZ[r0 + 8], zp[mf][1]);
        }
    }
    __syncthreads();
    if (tid < 128)
        rZ[(size_t)hh * S_ + kt + tid] = 1.0f / sZ[tid];
}

// ---------------------------------------------------------------------------
// Attention pass 2: out[q,d] = sum_k (exp(<k,q>/32) * rZ[k]) * V[k,d].
// QK single fp16 MMA; PV single fp16 MMA (P,V fp16).  K/V + rz double-buffered.
// smem: Q(1) + 2 stages x (K + V) = 5 tiles + rz  (~93 KB)
// ---------------------------------------------------------------------------
__global__ void __launch_bounds__(256) attn_av(
    const __half* __restrict__ Qq, const __half* __restrict__ Kq,
    const __half* __restrict__ Vq, const float* __restrict__ rZ,
    __nv_bfloat16* __restrict__ Ohi, __nv_bfloat16* __restrict__ Olo) {
    extern __shared__ char smem[];
    __half* sQ = (__half*)(smem);

    const int hh = blockIdx.y;
    const int b = hh >> 4, h = hh & 15;
    const size_t off = (size_t)b * S_ * L_ + (size_t)h * DH_;
    const int qt = blockIdx.x * 128;

    const int tid = threadIdx.x;
    const int wid = tid >> 5, lane = tid & 31;
    const int g = lane >> 2, t2 = (lane & 3) * 2;
    const int a_row = (lane & 15);
    const int a_col8 = (lane >> 4) * 8;
    const int b_rowoff = (lane & 7) + ((lane >> 4) << 3);
    const int b_col8 = ((lane >> 3) & 1) * 8;
    const int v_k = (lane & 7) + (((lane >> 3) & 1) << 3);
    const int v_d = (lane >> 4) * 8;

    auto kq = [&](int s) { return (__half*)(smem + TB_ + (size_t)s * 2 * TB_); };
    auto vq = [&](int s) { return (__half*)(smem + 2 * TB_ + (size_t)s * 2 * TB_); };
    float* srz = (float*)(smem + 5 * TB_);            // [2][128]

    auto ld_kv = [&](int c, int s) {
        const int kt = c * 128;
        __half* kp = kq(s);
        __half* vp = vq(s);
        #pragma unroll
        for (int i = 0; i < 4; i++) {
            int idx = tid + i * 256;
            int row = idx >> 3;
            int seg = (idx & 7) * 8;
            cpa16(sptr(kp + row * TP_ + seg), Kq + off + (size_t)(kt + row) * L_ + seg);
            cpa16(sptr(vp + row * TP_ + seg), Vq + off + (size_t)(kt + row) * L_ + seg);
        }
        if (tid < 32)
            cpa16(sptr(srz + s * 128 + tid * 4), rZ + (size_t)hh * S_ + kt + tid * 4);
    };

    #pragma unroll
    for (int i = 0; i < 4; i++) {
        int idx = tid + i * 256;
        int row = idx >> 3;
        int seg = (idx & 7) * 8;
        *(uint4*)&sQ[row * TP_ + seg] = *(const uint4*)(Qq + off + (size_t)(qt + row) * L_ + seg);
    }

    ld_kv(0, 0);
    cpa_commit();

    float avacc[8][4];
    #pragma unroll
    for (int j = 0; j < 8; j++)
        #pragma unroll
        for (int r = 0; r < 4; r++) avacc[j][r] = 0.0f;

    const int wq = wid * 16;

    for (int c = 0; c < 16; c++) {
        const int s = c & 1;
        if (c + 1 < 16) ld_kv(c + 1, s ^ 1);
        cpa_commit();
        cpa_wait1();
        __syncthreads();
        __half* sK = kq(s);
        __half* sV = vq(s);
        const float* rz = srz + s * 128;

        #pragma unroll
        for (int khalf = 0; khalf < 2; khalf++) {
            float sacc[8][4];
            #pragma unroll
            for (int j = 0; j < 8; j++)
                #pragma unroll
                for (int r = 0; r < 4; r++) sacc[j][r] = 0.0f;

            #pragma unroll
            for (int ks = 0; ks < 4; ks++) {
                const int kc = ks * 16;
                uint32_t ah[4];
                ldsm4(sptr(&sQ[(wq + a_row) * TP_ + kc + a_col8]), ah[0], ah[1], ah[2], ah[3]);
                #pragma unroll
                for (int nf2 = 0; nf2 < 4; nf2++) {
                    const int brow = khalf * 64 + nf2 * 16 + b_rowoff;
                    uint32_t bh[4];
                    ldsm4(sptr(&sK[brow * TP_ + kc + b_col8]), bh[0], bh[1], bh[2], bh[3]);
                    #pragma unroll
                    for (int f = 0; f < 2; f++)
                        mma16816h(sacc[nf2 * 2 + f], ah, bh + 2 * f);
                }
            }

            // p = exp(s/32) * rZ[k] as fp16 A-fragments
            uint32_t pa[4][4];
            #pragma unroll
            for (int j = 0; j < 4; j++) {
                #pragma unroll
                for (int e = 0; e < 2; e++) {
                    float* d = sacc[2 * j + e];
                    const int col = khalf * 64 + j * 16 + e * 8 + t2;
                    float r0 = rz[col], r1 = rz[col + 1];
                    __half2 p01 = __floats2half2_rn(fexp32(d[0]) * r0, fexp32(d[1]) * r1);
                    __half2 p23 = __floats2half2_rn(fexp32(d[2]) * r0, fexp32(d[3]) * r1);
                    pa[j][2 * e + 0] = *(uint32_t*)&p01;
                    pa[j][2 * e + 1] = *(uint32_t*)&p23;
                }
            }

            #pragma unroll
            for (int j = 0; j < 4; j++) {
                const int kbase = khalf * 64 + j * 16;
                #pragma unroll
                for (int nb = 0; nb < 4; nb++) {
                    uint32_t bv[4];
                    ldsm4t(sptr(&sV[(kbase + v_k) * TP_ + nb * 16 + v_d]),
                           bv[0], bv[1], bv[2], bv[3]);
                    #pragma unroll
                    for (int f = 0; f < 2; f++)
                        mma16816h(avacc[nb * 2 + f], pa[j], bv + 2 * f);
                }
            }
        }
        __syncthreads();
    }

    #pragma unroll
    for (int nf = 0; nf < 8; nf++) {
        const int row = qt + wq + g;
        const int col = nf * 8 + t2;
        float* d = avacc[nf];
        uint32_t hp, lp;
        split_pack(d[0], d[1], hp, lp);
        *(uint32_t*)(Ohi + off + (size_t)row * L_ + col) = hp;
        *(uint32_t*)(Olo + off + (size_t)row * L_ + col) = lp;
        split_pack(d[2], d[3], hp, lp);
        *(uint32_t*)(Ohi + off + (size_t)(row + 8) * L_ + col) = hp;
        *(uint32_t*)(Olo + off + (size_t)(row + 8) * L_ + col) = lp;
    }
}

// ---------------------------------------------------------------------------
// fp32 -> fp16 convert (element-wise)
// ---------------------------------------------------------------------------
__global__ void __launch_bounds__(256) f32tof16(const float* __restrict__ A,
                                                __half* __restrict__ O) {
    size_t i = ((size_t)blockIdx.x * 256 + threadIdx.x) * 4;
    float4 a = *(const float4*)(A + i);
    __half2 o0 = __floats2half2_rn(a.x, a.y);
    __half2 o1 = __floats2half2_rn(a.z, a.w);
    *(uint32_t*)(O + i) = *(uint32_t*)&o0;
    *(uint32_t*)(O + i + 2) = *(uint32_t*)&o1;
}

// W[K,N] -> Wt fp16 [N,K]
__global__ void __launch_bounds__(256) transpose_f16(const float* __restrict__ W,
                                                     __half* __restrict__ T,
                                                     int K, int N) {
    __shared__ float t[32][33];
    const int k0 = blockIdx.y * 32, n0 = blockIdx.x * 32;
    const int tx = threadIdx.x & 31, ty = threadIdx.x >> 5;
    #pragma unroll
    for (int j = 0; j < 4; j++) {
        int row = ty + j * 8;
        t[row][tx] = W[(size_t)(k0 + row) * N + n0 + tx];
    }
    __syncthreads();
    #pragma unroll
    for (int j = 0; j < 4; j++) {
        int row = ty + j * 8;
        T[(size_t)(n0 + row) * K + k0 + tx] = __float2half_rn(t[tx][row]);
    }
}

// W[K,N] -> Wt bf16 hi/lo [N,K]
__global__ void __launch_bounds__(256) transpose_split(const float* __restrict__ W,
                                                       __nv_bfloat16* __restrict__ Th,
                                                       __nv_bfloat16* __restrict__ Tl,
                                                       int K, int N) {
    __shared__ float t[32][33];
    const int k0 = blockIdx.y * 32, n0 = blockIdx.x * 32;
    const int tx = threadIdx.x & 31, ty = threadIdx.x >> 5;
    #pragma unroll
    for (int j = 0; j < 4; j++) {
        int row = ty + j * 8;
        t[row][tx] = W[(size_t)(k0 + row) * N + n0 + tx];
    }
    __syncthreads();
    #pragma unroll
    for (int j = 0; j < 4; j++) {
        int row = ty + j * 8;
        float v = t[tx][row];
        __nv_bfloat16 h, l; split1(v, h, l);
        size_t o = (size_t)(n0 + row) * K + k0 + tx;
        Th[o] = h; Tl[o] = l;
    }
}

// ---------------------------------------------------------------------------
// Row L2 normalize -> bf16 hi/lo split
// ---------------------------------------------------------------------------
__global__ void __launch_bounds__(256) l2norm_split(const float* __restrict__ Z,
                                                    __nv_bfloat16* __restrict__ Hi,
                                                    __nv_bfloat16* __restrict__ Lo) {
    __shared__ float shs[8];
    const size_t row = blockIdx.x;
    const float* p = Z + row * (size_t)D_;
    const int tid = threadIdx.x;
    const int lane = tid & 31, wid = tid >> 5;
    float4 v = *(const float4*)(p + tid * 4);
    float ss = v.x * v.x + v.y * v.y + v.z * v.z + v.w * v.w;
    #pragma unroll
    for (int o = 16; o; o >>= 1) ss += __shfl_xor_sync(0xffffffffu, ss, o);
    if (lane == 0) shs[wid] = ss;
    __syncthreads();
    ss = shs[0];
    #pragma unroll
    for (int i = 1; i < 8; i++) ss += shs[i];
    const float sc = 1.0f / fmaxf(sqrtf(ss), 1e-12f);
    float y0 = v.x * sc, y1 = v.y * sc, y2 = v.z * sc, y3 = v.w * sc;
    __nv_bfloat16 h0, l0, h1, l1, h2, l2, h3, l3;
    split1(y0, h0, l0); split1(y1, h1, l1);
    split1(y2, h2, l2); split1(y3, h3, l3);
    size_t o = row * (size_t)D_ + tid * 4;
    __nv_bfloat162* hp = (__nv_bfloat162*)(Hi + o);
    __nv_bfloat162* lp = (__nv_bfloat162*)(Lo + o);
    hp[0] = __nv_bfloat162(h0, h1); hp[1] = __nv_bfloat162(h2, h3);
    lp[0] = __nv_bfloat162(l0, l1); lp[1] = __nv_bfloat162(l2, l3);
}

// ---------------------------------------------------------------------------
// Row L2 normalize + exact GELU, writes to output
// ---------------------------------------------------------------------------
__global__ void __launch_bounds__(256) l2norm_gelu(const float* __restrict__ Z,
                                                   float* __restrict__ O) {
    __shared__ float shs[8];
    const size_t row = blockIdx.x;
    const float* p = Z + row * (size_t)D_;
    float* q = O + row * (size_t)D_;
    const int tid = threadIdx.x;
    const int lane = tid & 31, wid = tid >> 5;
    float4 v = *(const float4*)(p + tid * 4);
    float ss = v.x * v.x + v.y * v.y + v.z * v.z + v.w * v.w;
    #pragma unroll
    for (int o = 16; o; o >>= 1) ss += __shfl_xor_sync(0xffffffffu, ss, o);
    if (lane == 0) shs[wid] = ss;
    __syncthreads();
    ss = shs[0];
    #pragma unroll
    for (int i = 1; i < 8; i++) ss += shs[i];
    const float sc = 1.0f / fmaxf(sqrtf(ss), 1e-12f);
    float y0 = v.x * sc, y1 = v.y * sc, y2 = v.z * sc, y3 = v.w * sc;
    const float inv_sqrt2 = 0.70710678118654752f;
    float4 g;
    g.x = 0.5f * y0 * (1.0f + erff(y0 * inv_sqrt2));
    g.y = 0.5f * y1 * (1.0f + erff(y1 * inv_sqrt2));
    g.z = 0.5f * y2 * (1.0f + erff(y2 * inv_sqrt2));
    g.w = 0.5f * y3 * (1.0f + erff(y3 * inv_sqrt2));
    *(float4*)(q + tid * 4) = g;
}

// ---------------------------------------------------------------------------
// Launch
// ---------------------------------------------------------------------------
extern "C" void kernel_launch(void* const* d_in, const int* in_sizes, int n_in,
                              void* d_out, int out_size) {
    (void)in_sizes; (void)n_in; (void)out_size;
    const float* x   = (const float*)d_in[0];
    const float* Wq  = (const float*)d_in[1];
    const float* Wk  = (const float*)d_in[2];
    const float* Wv  = (const float*)d_in[3];
    const float* Wo  = (const float*)d_in[4];
    const float* Wff = (const float*)d_in[5];

    float *z1, *z2, *rz;
    cudaGetSymbolAddress((void**)&z1, g_z1);
    cudaGetSymbolAddress((void**)&z2, g_z2);
    cudaGetSymbolAddress((void**)&rz, g_rz);

    __half *x16, *q16, *k16, *v16, *wt16;
    __nv_bfloat16 *aohi, *aolo, *z1hi, *z1lo, *wth, *wtl;
    cudaGetSymbolAddress((void**)&x16,  g_x16);
    cudaGetSymbolAddress((void**)&q16,  g_q16);
    cudaGetSymbolAddress((void**)&k16,  g_k16);
    cudaGetSymbolAddress((void**)&v16,  g_v16);
    cudaGetSymbolAddress((void**)&wt16, g_wt16);
    cudaGetSymbolAddress((void**)&aohi, g_aohi);
    cudaGetSymbolAddress((void**)&aolo, g_aolo);
    cudaGetSymbolAddress((void**)&z1hi, g_z1hi);
    cudaGetSymbolAddress((void**)&z1lo, g_z1lo);
    cudaGetSymbolAddress((void**)&wth,  g_wt_hi);
    cudaGetSymbolAddress((void**)&wtl,  g_wt_lo);
    const size_t WSTR = (size_t)D_ * L_;

    const int SMEM1 = 3 * TB_ + 512;
    const int SMEM2 = 5 * TB_ + 1024;
    cudaFuncSetAttribute(hgemm_nt,   cudaFuncAttributeMaxDynamicSharedMemorySize, GSMEM_);
    cudaFuncSetAttribute(hgemm_f16,  cudaFuncAttributeMaxDynamicSharedMemorySize, GSMEM16_);
    cudaFuncSetAttribute(attn_stats, cudaFuncAttributeMaxDynamicSharedMemorySize, SMEM1);
    cudaFuncSetAttribute(attn_av,    cudaFuncAttributeMaxDynamicSharedMemorySize, SMEM2);

    const dim3 blk(256);
    const dim3 gT(L_ / 32, D_ / 32);

    f32tof16<<<(M4_ * D_) / 1024, blk>>>(x, x16);
    transpose_f16<<<gT, blk>>>(Wq,  wt16 + 0 * WSTR, D_, L_);
    transpose_f16<<<gT, blk>>>(Wk,  wt16 + 1 * WSTR, D_, L_);
    transpose_f16<<<gT, blk>>>(Wv,  wt16 + 2 * WSTR, D_, L_);
    transpose_split<<<gT, blk>>>(Wo,  wth + 0 * WSTR, wtl + 0 * WSTR, L_, D_);
    transpose_split<<<gT, blk>>>(Wff, wth + 1 * WSTR, wtl + 1 * WSTR, D_, D_);

    const dim3 gG(L_ / 128, M4_ / 128, 1);

    // QKV projections: pure fp16
    hgemm_f16<<<gG, blk, GSMEM16_>>>(x16, wt16 + 0 * WSTR, q16, M4_, L_, D_, D_, D_, L_);
    hgemm_f16<<<gG, blk, GSMEM16_>>>(x16, wt16 + 1 * WSTR, k16, M4_, L_, D_, D_, D_, L_);
    hgemm_f16<<<gG, blk, GSMEM16_>>>(x16, wt16 + 2 * WSTR, v16, M4_, L_, D_, D_, D_, L_);

    // fused attention (two-pass; all-fp16 MMA)
    attn_stats<<<dim3(16, 32), blk, SMEM1>>>(k16, q16, rz);
    attn_av<<<dim3(16, 32), blk, SMEM2>>>(q16, k16, v16, rz, aohi, aolo);

    // output projection (bf16x3 keeps downstream precision)
    hgemm_nt<<<gG, blk, GSMEM_>>>(aohi, aolo, wth + 0 * WSTR, wtl + 0 * WSTR, z1,
                                  (__nv_bfloat16*)0, (__nv_bfloat16*)0,
                                  M4_, D_, L_, L_, L_, D_, 1.0f, 0);

    // FFN (bf16x3)
    l2norm_split<<<M4_, blk>>>(z1, z1hi, z1lo);
    hgemm_nt<<<gG, blk, GSMEM_>>>(z1hi, z1lo, wth + 1 * WSTR, wtl + 1 * WSTR, z2,
                                  (__nv_bfloat16*)0, (__nv_bfloat16*)0,
                                  M4_, D_, D_, D_, D_, D_, 1.0f, 0);
    l2norm_gelu<<<M4_, blk>>>(z2, (float*)d_out);
}